// round 1
// baseline (speedup 1.0000x reference)
#include <cuda_runtime.h>
#include <cuda_bf16.h>
#include <math.h>

// Problem constants
#define BB 512
#define AA 4
#define EE 10
#define HH 256
#define TT 10
#define MP_ROWS (BB*AA*EE)   // 20480
#define MA_ROWS (BB*AA)      // 2048
#define G3H (3*HH)           // 768

// ---------------- scratch (static device allocations) ----------------
__device__ float g_giC[MP_ROWS * G3H];     // precomputed x_p @ Wih_p^T + b_ih_p (gate-major cols)
__device__ float g_goalC[MA_ROWS * G3H];   // goal part of gi_a + b_ih_a
__device__ float g_mp[2][MP_ROWS * HH];    // physical memory ping-pong
__device__ float g_ma[2][MA_ROWS * HH];    // action memory ping-pong
__device__ float g_proc[MP_ROWS * HH];
__device__ float g_feat[MA_ROWS * HH];
__device__ float g_t1[MA_ROWS * HH];
__device__ float g_t2[MA_ROWS * HH];

// ---------------- helpers ----------------
__device__ __forceinline__ float sigmoidf_(float x) { return 1.0f / (1.0f + __expf(-x)); }
__device__ __forceinline__ float eluf_(float x) { return x > 0.0f ? x : expm1f(x); }

// ---------------- prep kernels (time-invariant inputs) ----------------
// giC[r, col] = b_ih_p[col] + obs[r,0:2]·Wih[col,0:2] + phys[b,e,0:3]·Wih[col,2:5]
__global__ void prep_gip_kernel(const float* __restrict__ obs,
                                const float* __restrict__ phys,
                                const float* __restrict__ Wih,
                                const float* __restrict__ bih,
                                float* __restrict__ giC)
{
    int idx = blockIdx.x * blockDim.x + threadIdx.x;
    if (idx >= MP_ROWS * G3H) return;
    int r = idx / G3H, col = idx - r * G3H;
    int b = r / (AA*EE);
    int e = r % EE;
    const float* w = Wih + col * 5;
    const float* ob = obs + r * 2;
    const float* ph = phys + (b * EE + e) * 3;
    float s = bih[col];
    s += ob[0]*w[0] + ob[1]*w[1];
    s += ph[0]*w[2] + ph[1]*w[3] + ph[2]*w[4];
    giC[idx] = s;
}

// goalC[m, col] = b_ih_a[col] + goals[m,0:3]·Wih_a[col,256:259]
__global__ void prep_goal_kernel(const float* __restrict__ goals,
                                 const float* __restrict__ Wih,   // [768,259]
                                 const float* __restrict__ bih,
                                 float* __restrict__ goalC)
{
    int idx = blockIdx.x * blockDim.x + threadIdx.x;
    if (idx >= MA_ROWS * G3H) return;
    int m = idx / G3H, col = idx - m * G3H;
    const float* w = Wih + col * 259 + HH;
    const float* gl = goals + m * 3;
    goalC[idx] = bih[col] + gl[0]*w[0] + gl[1]*w[1] + gl[2]*w[2];
}

// ---------------- physical GRU: fused 3-gate GEMM + GRU update ----------------
// h_out[m, n] = GRU(giC[m,*], h_in[m,*] @ Whh^T + bhh)
// Tile: BM=64 x BN=64 (n in [0,256)), BK=16; 256 threads, 4x4 micro-tile x 3 gates.
#define GP_BM 64
#define GP_BN 64
#define GP_BK 16
__global__ __launch_bounds__(256) void gru_p_kernel(const float* __restrict__ Whh,  // [768,256]
                                                    const float* __restrict__ bhh,
                                                    const float* __restrict__ giC,
                                                    const float* __restrict__ h_in,
                                                    float* __restrict__ h_out)
{
    const int m0 = blockIdx.x * GP_BM;
    const int n0 = blockIdx.y * GP_BN;
    __shared__ float As[GP_BM][GP_BK + 1];
    __shared__ float Bs[3][GP_BK][GP_BN + 1];

    float acc[3][4][4];
#pragma unroll
    for (int g = 0; g < 3; g++)
#pragma unroll
        for (int i = 0; i < 4; i++)
#pragma unroll
            for (int j = 0; j < 4; j++) acc[g][i][j] = 0.0f;

    const int tid = threadIdx.x;
    const int tr = tid >> 4;          // 0..15
    const int tc = tid & 15;          // 0..15
    const int lk = tid & 15;          // k lane for loads
    const int lm = tid >> 4;          // row lane for loads

    for (int k0 = 0; k0 < HH; k0 += GP_BK) {
#pragma unroll
        for (int i = 0; i < 4; i++) {
            int m = lm + 16 * i;
            As[m][lk] = h_in[(m0 + m) * HH + k0 + lk];
        }
#pragma unroll
        for (int g = 0; g < 3; g++)
#pragma unroll
            for (int i = 0; i < 4; i++) {
                int n = lm + 16 * i;
                Bs[g][lk][n] = Whh[(g * HH + n0 + n) * HH + k0 + lk];
            }
        __syncthreads();
#pragma unroll
        for (int k = 0; k < GP_BK; k++) {
            float a[4], b[3][4];
#pragma unroll
            for (int i = 0; i < 4; i++) a[i] = As[tr * 4 + i][k];
#pragma unroll
            for (int g = 0; g < 3; g++)
#pragma unroll
                for (int j = 0; j < 4; j++) b[g][j] = Bs[g][k][tc * 4 + j];
#pragma unroll
            for (int g = 0; g < 3; g++)
#pragma unroll
                for (int i = 0; i < 4; i++)
#pragma unroll
                    for (int j = 0; j < 4; j++) acc[g][i][j] += a[i] * b[g][j];
        }
        __syncthreads();
    }

#pragma unroll
    for (int i = 0; i < 4; i++) {
        int m = m0 + tr * 4 + i;
#pragma unroll
        for (int j = 0; j < 4; j++) {
            int n = n0 + tc * 4 + j;
            float hr = acc[0][i][j] + bhh[n];
            float hz = acc[1][i][j] + bhh[HH + n];
            float hn = acc[2][i][j] + bhh[2 * HH + n];
            const float* gi = giC + m * G3H;
            float r = sigmoidf_(gi[n] + hr);
            float z = sigmoidf_(gi[HH + n] + hz);
            float nn = tanhf(gi[2 * HH + n] + r * hn);
            float hold = h_in[m * HH + n];
            h_out[m * HH + n] = (1.0f - z) * nn + z * hold;
        }
    }
}

// ---------------- generic GEMM + ELU: C[M,256] = elu(A[M,256] @ W[256,256]^T + b) ----------------
__global__ __launch_bounds__(256) void gemm_elu_kernel(const float* __restrict__ A,
                                                       const float* __restrict__ W,
                                                       const float* __restrict__ bias,
                                                       float* __restrict__ C)
{
    const int m0 = blockIdx.x * 64;
    const int n0 = blockIdx.y * 64;
    __shared__ float As[64][17];
    __shared__ float Bs[16][65];

    float acc[4][4];
#pragma unroll
    for (int i = 0; i < 4; i++)
#pragma unroll
        for (int j = 0; j < 4; j++) acc[i][j] = 0.0f;

    const int tid = threadIdx.x;
    const int tr = tid >> 4, tc = tid & 15;
    const int lk = tid & 15, lm = tid >> 4;

    for (int k0 = 0; k0 < HH; k0 += 16) {
#pragma unroll
        for (int i = 0; i < 4; i++) {
            int m = lm + 16 * i;
            As[m][lk] = A[(m0 + m) * HH + k0 + lk];
        }
#pragma unroll
        for (int i = 0; i < 4; i++) {
            int n = lm + 16 * i;
            Bs[lk][n] = W[(n0 + n) * HH + k0 + lk];
        }
        __syncthreads();
#pragma unroll
        for (int k = 0; k < 16; k++) {
            float a[4], b[4];
#pragma unroll
            for (int i = 0; i < 4; i++) a[i] = As[tr * 4 + i][k];
#pragma unroll
            for (int j = 0; j < 4; j++) b[j] = Bs[k][tc * 4 + j];
#pragma unroll
            for (int i = 0; i < 4; i++)
#pragma unroll
                for (int j = 0; j < 4; j++) acc[i][j] += a[i] * b[j];
        }
        __syncthreads();
    }

#pragma unroll
    for (int i = 0; i < 4; i++) {
        int m = m0 + tr * 4 + i;
#pragma unroll
        for (int j = 0; j < 4; j++) {
            int n = n0 + tc * 4 + j;
            C[m * HH + n] = eluf_(acc[i][j] + bias[n]);
        }
    }
}

// ---------------- entity max-pool: feat[m, j] = max_e proc[m*10+e, j] ----------------
__global__ void pool_kernel(const float* __restrict__ proc, float* __restrict__ feat)
{
    int m = blockIdx.x;
    int j = threadIdx.x;
    const float* p = proc + (size_t)m * EE * HH + j;
    float v = p[0];
#pragma unroll
    for (int e = 1; e < EE; e++) v = fmaxf(v, p[e * HH]);
    feat[m * HH + j] = v;
}

// ---------------- action GRU: fused dual-operand 4-accumulator GEMM + GRU ----------------
// BM=32 x BN=64, BK=16; 256 threads, 2x4 micro-tile x 4 accum groups.
__global__ __launch_bounds__(256) void gru_a_kernel(const float* __restrict__ feat,
                                                    const float* __restrict__ ma_in,
                                                    const float* __restrict__ Wih,   // [768,259]
                                                    const float* __restrict__ Whh,   // [768,256]
                                                    const float* __restrict__ bhh,
                                                    const float* __restrict__ goalC,
                                                    float* __restrict__ ma_out)
{
    const int m0 = blockIdx.x * 32;
    const int n0 = blockIdx.y * 64;
    __shared__ float Af[32][17];   // feat tile
    __shared__ float Am[32][17];   // ma tile
    __shared__ float Bs[6][16][65];

    // acc groups: 0: r-sum (feat*Wih_r + ma*Whh_r), 1: z-sum, 2: gi_n (feat*Wih_n), 3: gh_n (ma*Whh_n)
    float acc[4][2][4];
#pragma unroll
    for (int s = 0; s < 4; s++)
#pragma unroll
        for (int i = 0; i < 2; i++)
#pragma unroll
            for (int j = 0; j < 4; j++) acc[s][i][j] = 0.0f;

    const int tid = threadIdx.x;
    const int tr = tid >> 4, tc = tid & 15;   // rows tr*2+{0,1}, cols tc*4+{0..3}
    const int lk = tid & 15, lm = tid >> 4;

    for (int k0 = 0; k0 < HH; k0 += 16) {
#pragma unroll
        for (int i = 0; i < 2; i++) {
            int m = lm + 16 * i;
            Af[m][lk] = feat[(m0 + m) * HH + k0 + lk];
            Am[m][lk] = ma_in[(m0 + m) * HH + k0 + lk];
        }
#pragma unroll
        for (int g = 0; g < 3; g++)
#pragma unroll
            for (int i = 0; i < 4; i++) {
                int n = lm + 16 * i;
                Bs[g][lk][n]     = Wih[(g * HH + n0 + n) * 259 + k0 + lk];
                Bs[g + 3][lk][n] = Whh[(g * HH + n0 + n) * HH + k0 + lk];
            }
        __syncthreads();
#pragma unroll
        for (int k = 0; k < 16; k++) {
            float af[2], am[2], b[6][4];
#pragma unroll
            for (int i = 0; i < 2; i++) { af[i] = Af[tr * 2 + i][k]; am[i] = Am[tr * 2 + i][k]; }
#pragma unroll
            for (int g = 0; g < 6; g++)
#pragma unroll
                for (int j = 0; j < 4; j++) b[g][j] = Bs[g][k][tc * 4 + j];
#pragma unroll
            for (int i = 0; i < 2; i++)
#pragma unroll
                for (int j = 0; j < 4; j++) {
                    acc[0][i][j] += af[i] * b[0][j] + am[i] * b[3][j];
                    acc[1][i][j] += af[i] * b[1][j] + am[i] * b[4][j];
                    acc[2][i][j] += af[i] * b[2][j];
                    acc[3][i][j] += am[i] * b[5][j];
                }
        }
        __syncthreads();
    }

#pragma unroll
    for (int i = 0; i < 2; i++) {
        int m = m0 + tr * 2 + i;
#pragma unroll
        for (int j = 0; j < 4; j++) {
            int n = n0 + tc * 4 + j;
            const float* gc = goalC + m * G3H;
            float r = sigmoidf_(gc[n] + acc[0][i][j] + bhh[n]);
            float z = sigmoidf_(gc[HH + n] + acc[1][i][j] + bhh[HH + n]);
            float nn = tanhf(gc[2 * HH + n] + acc[2][i][j] + r * (acc[3][i][j] + bhh[2 * HH + n]));
            float hold = ma_in[m * HH + n];
            ma_out[m * HH + n] = (1.0f - z) * nn + z * hold;
        }
    }
}

// ---------------- head: out[t, m, v] = tanh(t2[m,:] · Wm2[v,:] + b[v]) * 0.05 ----------------
__global__ void head_kernel(const float* __restrict__ t2,
                            const float* __restrict__ Wm2,   // [2,256]
                            const float* __restrict__ bm2,
                            float* __restrict__ out, int tstep)
{
    int warp = (blockIdx.x * blockDim.x + threadIdx.x) >> 5;
    int lane = threadIdx.x & 31;
    if (warp >= MA_ROWS) return;
    float s0 = 0.0f, s1 = 0.0f;
    for (int k = lane; k < HH; k += 32) {
        float x = t2[warp * HH + k];
        s0 += x * Wm2[k];
        s1 += x * Wm2[HH + k];
    }
#pragma unroll
    for (int off = 16; off; off >>= 1) {
        s0 += __shfl_xor_sync(0xffffffffu, s0, off);
        s1 += __shfl_xor_sync(0xffffffffu, s1, off);
    }
    if (lane == 0) {
        out[((size_t)tstep * MA_ROWS + warp) * 2 + 0] = tanhf(s0 + bm2[0]) * 0.05f;
        out[((size_t)tstep * MA_ROWS + warp) * 2 + 1] = tanhf(s1 + bm2[1]) * 0.05f;
    }
}

// ---------------- host launcher ----------------
extern "C" void kernel_launch(void* const* d_in, const int* in_sizes, int n_in,
                              void* d_out, int out_size)
{
    const float* obs    = (const float*)d_in[0];
    const float* phys   = (const float*)d_in[1];
    const float* goals  = (const float*)d_in[2];
    const float* mem_p  = (const float*)d_in[3];
    const float* mem_a  = (const float*)d_in[4];
    const float* Wih_p  = (const float*)d_in[5];
    const float* Whh_p  = (const float*)d_in[6];
    const float* bih_p  = (const float*)d_in[7];
    const float* bhh_p  = (const float*)d_in[8];
    const float* Wfc_p  = (const float*)d_in[9];
    const float* bfc_p  = (const float*)d_in[10];
    const float* Wih_a  = (const float*)d_in[11];
    const float* Whh_a  = (const float*)d_in[12];
    const float* bih_a  = (const float*)d_in[13];
    const float* bhh_a  = (const float*)d_in[14];
    const float* Wfc_a  = (const float*)d_in[15];
    const float* bfc_a  = (const float*)d_in[16];
    const float* Wm1    = (const float*)d_in[17];
    const float* bm1    = (const float*)d_in[18];
    const float* Wm2    = (const float*)d_in[19];
    const float* bm2    = (const float*)d_in[20];
    float* out = (float*)d_out;

    void *p;
    cudaGetSymbolAddress(&p, g_giC);   float* giC   = (float*)p;
    cudaGetSymbolAddress(&p, g_goalC); float* goalC = (float*)p;
    cudaGetSymbolAddress(&p, g_mp);    float* mpB   = (float*)p;
    cudaGetSymbolAddress(&p, g_ma);    float* maB   = (float*)p;
    cudaGetSymbolAddress(&p, g_proc);  float* proc  = (float*)p;
    cudaGetSymbolAddress(&p, g_feat);  float* feat  = (float*)p;
    cudaGetSymbolAddress(&p, g_t1);    float* t1    = (float*)p;
    cudaGetSymbolAddress(&p, g_t2);    float* t2    = (float*)p;

    float* mp[2] = { mpB, mpB + (size_t)MP_ROWS * HH };
    float* ma[2] = { maB, maB + (size_t)MA_ROWS * HH };

    cudaStream_t s = 0;

    // initial state + time-invariant precomputes
    cudaMemcpyAsync(mp[0], mem_p, (size_t)MP_ROWS * HH * sizeof(float), cudaMemcpyDeviceToDevice, s);
    cudaMemcpyAsync(ma[0], mem_a, (size_t)MA_ROWS * HH * sizeof(float), cudaMemcpyDeviceToDevice, s);
    {
        int n1 = MP_ROWS * G3H;
        prep_gip_kernel<<<(n1 + 255) / 256, 256, 0, s>>>(obs, phys, Wih_p, bih_p, giC);
        int n2 = MA_ROWS * G3H;
        prep_goal_kernel<<<(n2 + 255) / 256, 256, 0, s>>>(goals, Wih_a, bih_a, goalC);
    }

    int cur = 0;
    for (int t = 0; t < TT; t++) {
        int nxt = cur ^ 1;
        gru_p_kernel<<<dim3(MP_ROWS / 64, 4), 256, 0, s>>>(Whh_p, bhh_p, giC, mp[cur], mp[nxt]);
        gemm_elu_kernel<<<dim3(MP_ROWS / 64, 4), 256, 0, s>>>(mp[nxt], Wfc_p, bfc_p, proc);
        pool_kernel<<<MA_ROWS, HH, 0, s>>>(proc, feat);
        gru_a_kernel<<<dim3(MA_ROWS / 32, 4), 256, 0, s>>>(feat, ma[cur], Wih_a, Whh_a, bhh_a, goalC, ma[nxt]);
        gemm_elu_kernel<<<dim3(MA_ROWS / 64, 4), 256, 0, s>>>(ma[nxt], Wfc_a, bfc_a, t1);
        gemm_elu_kernel<<<dim3(MA_ROWS / 64, 4), 256, 0, s>>>(t1, Wm1, bm1, t2);
        head_kernel<<<(MA_ROWS * 32) / 256, 256, 0, s>>>(t2, Wm2, bm2, out, t);
        cur = nxt;
    }
}

// round 2
// speedup vs baseline: 2.2042x; 2.2042x over previous
#include <cuda_runtime.h>
#include <cuda_bf16.h>
#include <mma.h>
#include <math.h>

using namespace nvcuda;

// Problem constants
#define BB 512
#define AA 4
#define EE 10
#define HH 256
#define TT 10
#define MP_ROWS (BB*AA*EE)   // 20480
#define MA_ROWS (BB*AA)      // 2048
#define G3H (3*HH)           // 768

// ---------------- scratch (static device allocations) ----------------
__device__ float g_giC[MP_ROWS * G3H];        // x_p @ Wih_p^T + b_ih_p
__device__ float g_goalC[MA_ROWS * G3H];      // goal part of gi_a + b_ih_a
__device__ float g_h[MP_ROWS * HH];           // physical memory (in-place update)
__device__ __nv_bfloat16 g_h_hi[MP_ROWS * HH];
__device__ __nv_bfloat16 g_h_lo[MP_ROWS * HH];
__device__ float g_ma[MA_ROWS * HH];          // action memory fp32
__device__ __nv_bfloat16 g_xcat_hi[MA_ROWS * 512];  // [feat | ma] bf16 hi
__device__ __nv_bfloat16 g_xcat_lo[MA_ROWS * 512];
__device__ float g_gates_p[MP_ROWS * G3H];
__device__ float g_gates_a[MA_ROWS * 1024];
__device__ float g_proc[MP_ROWS * HH];
__device__ float g_t1[MA_ROWS * HH];
__device__ __nv_bfloat16 g_t1_hi[MA_ROWS * HH];
__device__ __nv_bfloat16 g_t1_lo[MA_ROWS * HH];
__device__ float g_t2[MA_ROWS * HH];
// weights (bf16 hi/lo splits, prepared once)
__device__ __nv_bfloat16 g_Whhp_hi[G3H * HH], g_Whhp_lo[G3H * HH];
__device__ __nv_bfloat16 g_Wfcp_hi[HH * HH],  g_Wfcp_lo[HH * HH];
__device__ __nv_bfloat16 g_Wcat_hi[1024 * 512], g_Wcat_lo[1024 * 512];
__device__ __nv_bfloat16 g_Wfca_hi[HH * HH],  g_Wfca_lo[HH * HH];
__device__ __nv_bfloat16 g_Wm1_hi[HH * HH],   g_Wm1_lo[HH * HH];

// ---------------- helpers ----------------
__device__ __forceinline__ float sigmoidf_(float x) { return 1.0f / (1.0f + __expf(-x)); }
__device__ __forceinline__ float eluf_(float x) { return x > 0.0f ? x : expm1f(x); }
__device__ __forceinline__ void split_bf16(float x, __nv_bfloat16& hi, __nv_bfloat16& lo) {
    hi = __float2bfloat16_rn(x);
    lo = __float2bfloat16_rn(x - __bfloat162float(hi));
}

// ---------------- prep kernels ----------------
__global__ void prep_gip_kernel(const float* __restrict__ obs,
                                const float* __restrict__ phys,
                                const float* __restrict__ Wih,
                                const float* __restrict__ bih,
                                float* __restrict__ giC)
{
    int idx = blockIdx.x * blockDim.x + threadIdx.x;
    if (idx >= MP_ROWS * G3H) return;
    int r = idx / G3H, col = idx - r * G3H;
    int b = r / (AA*EE);
    int e = r % EE;
    const float* w = Wih + col * 5;
    const float* ob = obs + r * 2;
    const float* ph = phys + (b * EE + e) * 3;
    float s = bih[col];
    s += ob[0]*w[0] + ob[1]*w[1];
    s += ph[0]*w[2] + ph[1]*w[3] + ph[2]*w[4];
    giC[idx] = s;
}

__global__ void prep_goal_kernel(const float* __restrict__ goals,
                                 const float* __restrict__ Wih,   // [768,259]
                                 const float* __restrict__ bih,
                                 float* __restrict__ goalC)
{
    int idx = blockIdx.x * blockDim.x + threadIdx.x;
    if (idx >= MA_ROWS * G3H) return;
    int m = idx / G3H, col = idx - m * G3H;
    const float* w = Wih + col * 259 + HH;
    const float* gl = goals + m * 3;
    goalC[idx] = bih[col] + gl[0]*w[0] + gl[1]*w[1] + gl[2]*w[2];
}

__global__ void split_kernel(const float* __restrict__ src,
                             __nv_bfloat16* __restrict__ hi,
                             __nv_bfloat16* __restrict__ lo, int n)
{
    int i = blockIdx.x * blockDim.x + threadIdx.x;
    if (i >= n) return;
    split_bf16(src[i], hi[i], lo[i]);
}

__global__ void split_strided_kernel(const float* __restrict__ src,
                                     __nv_bfloat16* __restrict__ hi,
                                     __nv_bfloat16* __restrict__ lo,
                                     int rows, int cols, int ldo)
{
    int i = blockIdx.x * blockDim.x + threadIdx.x;
    if (i >= rows * cols) return;
    int r = i / cols, c = i - r * cols;
    split_bf16(src[i], hi[r * ldo + c], lo[r * ldo + c]);
}

// Wcat [1024, 512]: rows g*256+n.
//  g=0 (r): [Wih_r | Whh_r], g=1 (z): [Wih_z | Whh_z], g=2: [Wih_n | 0], g=3: [0 | Whh_n]
__global__ void build_wcat_kernel(const float* __restrict__ Wih,  // [768,259]
                                  const float* __restrict__ Whh,  // [768,256]
                                  __nv_bfloat16* __restrict__ hi,
                                  __nv_bfloat16* __restrict__ lo)
{
    int idx = blockIdx.x * blockDim.x + threadIdx.x;
    if (idx >= 1024 * 512) return;
    int row = idx >> 9, col = idx & 511;
    int g = row >> 8, n = row & 255;
    float v = 0.0f;
    if (g < 2) {
        v = (col < 256) ? Wih[(g * 256 + n) * 259 + col] : Whh[(g * 256 + n) * 256 + (col - 256)];
    } else if (g == 2) {
        if (col < 256) v = Wih[(512 + n) * 259 + col];
    } else {
        if (col >= 256) v = Whh[(512 + n) * 256 + (col - 256)];
    }
    split_bf16(v, hi[idx], lo[idx]);
}

// ---------------- 3-pass bf16-split tensor-core GEMM ----------------
// C[M,N] = A[M,K] @ B[N,K]^T, A/B given as bf16 hi/lo pairs, fp32 accumulate.
// Block tile 128x64, BK=32, 8 warps (32x32 warp tiles).
// EPI 0: plain fp32 store. EPI 1: bias + ELU, fp32 store, optional bf16 hi/lo store.
template<int EPI>
__global__ __launch_bounds__(256) void gemm_bf16x3(
    const __nv_bfloat16* __restrict__ Ahi, const __nv_bfloat16* __restrict__ Alo, int lda,
    const __nv_bfloat16* __restrict__ Bhi, const __nv_bfloat16* __restrict__ Blo,
    const float* __restrict__ bias,
    float* __restrict__ C, __nv_bfloat16* __restrict__ Chi, __nv_bfloat16* __restrict__ Clo,
    int N, int K)
{
    __shared__ __align__(16) char smem_raw[36864];
    __nv_bfloat16* sAh = (__nv_bfloat16*)smem_raw;       // 128 x 48
    __nv_bfloat16* sAl = sAh + 128 * 48;
    __nv_bfloat16* sBh = sAl + 128 * 48;                 // 64 x 48
    __nv_bfloat16* sBl = sBh + 64 * 48;

    const int m0 = blockIdx.x * 128;
    const int n0 = blockIdx.y * 64;
    const int tid = threadIdx.x;
    const int wid = tid >> 5;
    const int wm = wid >> 1, wn = wid & 1;

    wmma::fragment<wmma::accumulator, 16, 16, 16, float> acc[2][2];
#pragma unroll
    for (int i = 0; i < 2; i++)
#pragma unroll
        for (int j = 0; j < 2; j++) wmma::fill_fragment(acc[i][j], 0.0f);

    for (int k0 = 0; k0 < K; k0 += 32) {
        // load A tile: 128x32 -> 512 float4 (8 bf16) chunks, 2 per thread
#pragma unroll
        for (int r = 0; r < 2; r++) {
            int c = tid + r * 256;
            int m = c >> 2, kk = (c & 3) * 8;
            *(float4*)&sAh[m * 48 + kk] = *(const float4*)&Ahi[(size_t)(m0 + m) * lda + k0 + kk];
            *(float4*)&sAl[m * 48 + kk] = *(const float4*)&Alo[(size_t)(m0 + m) * lda + k0 + kk];
        }
        // load B tile: 64x32 -> 256 chunks, 1 per thread
        {
            int n = tid >> 2, kk = (tid & 3) * 8;
            *(float4*)&sBh[n * 48 + kk] = *(const float4*)&Bhi[(size_t)(n0 + n) * K + k0 + kk];
            *(float4*)&sBl[n * 48 + kk] = *(const float4*)&Blo[(size_t)(n0 + n) * K + k0 + kk];
        }
        __syncthreads();
#pragma unroll
        for (int kc = 0; kc < 32; kc += 16) {
            wmma::fragment<wmma::matrix_a, 16, 16, 16, __nv_bfloat16, wmma::row_major> ah[2], al[2];
            wmma::fragment<wmma::matrix_b, 16, 16, 16, __nv_bfloat16, wmma::col_major> bh[2], bl[2];
#pragma unroll
            for (int i = 0; i < 2; i++) {
                wmma::load_matrix_sync(ah[i], sAh + (wm * 32 + i * 16) * 48 + kc, 48);
                wmma::load_matrix_sync(al[i], sAl + (wm * 32 + i * 16) * 48 + kc, 48);
            }
#pragma unroll
            for (int j = 0; j < 2; j++) {
                wmma::load_matrix_sync(bh[j], sBh + (wn * 32 + j * 16) * 48 + kc, 48);
                wmma::load_matrix_sync(bl[j], sBl + (wn * 32 + j * 16) * 48 + kc, 48);
            }
#pragma unroll
            for (int i = 0; i < 2; i++)
#pragma unroll
                for (int j = 0; j < 2; j++) {
                    wmma::mma_sync(acc[i][j], ah[i], bh[j], acc[i][j]);
                    wmma::mma_sync(acc[i][j], ah[i], bl[j], acc[i][j]);
                    wmma::mma_sync(acc[i][j], al[i], bh[j], acc[i][j]);
                }
        }
        __syncthreads();
    }

    if (EPI == 0) {
#pragma unroll
        for (int i = 0; i < 2; i++)
#pragma unroll
            for (int j = 0; j < 2; j++)
                wmma::store_matrix_sync(&C[(size_t)(m0 + wm * 32 + i * 16) * N + n0 + wn * 32 + j * 16],
                                        acc[i][j], N, wmma::mem_row_major);
    } else {
        float* sC = (float*)smem_raw;   // 128 x 64
#pragma unroll
        for (int i = 0; i < 2; i++)
#pragma unroll
            for (int j = 0; j < 2; j++)
                wmma::store_matrix_sync(&sC[(wm * 32 + i * 16) * 64 + wn * 32 + j * 16],
                                        acc[i][j], 64, wmma::mem_row_major);
        __syncthreads();
        int rowg = tid >> 4;        // 0..15 (8 rows each)
        int cg = tid & 15;          // col group, 4 cols each
        int n = n0 + cg * 4;
        float4 bv = *(const float4*)&bias[n];
#pragma unroll
        for (int r = 0; r < 8; r++) {
            int m = rowg * 8 + r;
            float4 v = *(float4*)&sC[m * 64 + cg * 4];
            v.x = eluf_(v.x + bv.x);
            v.y = eluf_(v.y + bv.y);
            v.z = eluf_(v.z + bv.z);
            v.w = eluf_(v.w + bv.w);
            size_t off = (size_t)(m0 + m) * N + n;
            *(float4*)&C[off] = v;
            if (Chi) {
                __nv_bfloat16 h4[4], l4[4];
                split_bf16(v.x, h4[0], l4[0]);
                split_bf16(v.y, h4[1], l4[1]);
                split_bf16(v.z, h4[2], l4[2]);
                split_bf16(v.w, h4[3], l4[3]);
                *(float2*)&Chi[off] = *(float2*)h4;
                *(float2*)&Clo[off] = *(float2*)l4;
            }
        }
    }
}

// ---------------- elementwise GRU updates ----------------
__global__ void gru_p_update_kernel(const float* __restrict__ gates,
                                    const float* __restrict__ giC,
                                    const float* __restrict__ bhh,
                                    float* __restrict__ h,
                                    __nv_bfloat16* __restrict__ h_hi,
                                    __nv_bfloat16* __restrict__ h_lo)
{
    int idx = blockIdx.x * blockDim.x + threadIdx.x;
    if (idx >= MP_ROWS * 64) return;
    int m = idx >> 6, n = (idx & 63) * 4;
    const float* gr = gates + (size_t)m * G3H;
    const float* gc = giC + (size_t)m * G3H;
    float4 hr = *(const float4*)&gr[n];
    float4 hz = *(const float4*)&gr[256 + n];
    float4 hn = *(const float4*)&gr[512 + n];
    float4 ir = *(const float4*)&gc[n];
    float4 iz = *(const float4*)&gc[256 + n];
    float4 in_ = *(const float4*)&gc[512 + n];
    float4 br = *(const float4*)&bhh[n];
    float4 bz = *(const float4*)&bhh[256 + n];
    float4 bn = *(const float4*)&bhh[512 + n];
    size_t ho = (size_t)m * HH + n;
    float4 hv = *(const float4*)&h[ho];
    float4 o;
    {
        float r = sigmoidf_(ir.x + hr.x + br.x);
        float z = sigmoidf_(iz.x + hz.x + bz.x);
        float nn = tanhf(in_.x + r * (hn.x + bn.x));
        o.x = (1.0f - z) * nn + z * hv.x;
    }
    {
        float r = sigmoidf_(ir.y + hr.y + br.y);
        float z = sigmoidf_(iz.y + hz.y + bz.y);
        float nn = tanhf(in_.y + r * (hn.y + bn.y));
        o.y = (1.0f - z) * nn + z * hv.y;
    }
    {
        float r = sigmoidf_(ir.z + hr.z + br.z);
        float z = sigmoidf_(iz.z + hz.z + bz.z);
        float nn = tanhf(in_.z + r * (hn.z + bn.z));
        o.z = (1.0f - z) * nn + z * hv.z;
    }
    {
        float r = sigmoidf_(ir.w + hr.w + br.w);
        float z = sigmoidf_(iz.w + hz.w + bz.w);
        float nn = tanhf(in_.w + r * (hn.w + bn.w));
        o.w = (1.0f - z) * nn + z * hv.w;
    }
    *(float4*)&h[ho] = o;
    __nv_bfloat16 h4[4], l4[4];
    split_bf16(o.x, h4[0], l4[0]);
    split_bf16(o.y, h4[1], l4[1]);
    split_bf16(o.z, h4[2], l4[2]);
    split_bf16(o.w, h4[3], l4[3]);
    *(float2*)&h_hi[ho] = *(float2*)h4;
    *(float2*)&h_lo[ho] = *(float2*)l4;
}

__global__ void gru_a_update_kernel(const float* __restrict__ gates,   // [M,1024]
                                    const float* __restrict__ goalC,   // [M,768]
                                    const float* __restrict__ bhh,
                                    float* __restrict__ ma,
                                    __nv_bfloat16* __restrict__ xcat_hi,
                                    __nv_bfloat16* __restrict__ xcat_lo)
{
    int idx = blockIdx.x * blockDim.x + threadIdx.x;
    if (idx >= MA_ROWS * 64) return;
    int m = idx >> 6, n = (idx & 63) * 4;
    const float* gr = gates + (size_t)m * 1024;
    const float* gc = goalC + (size_t)m * G3H;
    float4 sr = *(const float4*)&gr[n];
    float4 sz = *(const float4*)&gr[256 + n];
    float4 sni = *(const float4*)&gr[512 + n];
    float4 snh = *(const float4*)&gr[768 + n];
    float4 cr = *(const float4*)&gc[n];
    float4 cz = *(const float4*)&gc[256 + n];
    float4 cn = *(const float4*)&gc[512 + n];
    float4 br = *(const float4*)&bhh[n];
    float4 bz = *(const float4*)&bhh[256 + n];
    float4 bn = *(const float4*)&bhh[512 + n];
    size_t mo = (size_t)m * HH + n;
    float4 hv = *(const float4*)&ma[mo];
    float4 o;
    {
        float r = sigmoidf_(cr.x + sr.x + br.x);
        float z = sigmoidf_(cz.x + sz.x + bz.x);
        float nn = tanhf(cn.x + sni.x + r * (snh.x + bn.x));
        o.x = (1.0f - z) * nn + z * hv.x;
    }
    {
        float r = sigmoidf_(cr.y + sr.y + br.y);
        float z = sigmoidf_(cz.y + sz.y + bz.y);
        float nn = tanhf(cn.y + sni.y + r * (snh.y + bn.y));
        o.y = (1.0f - z) * nn + z * hv.y;
    }
    {
        float r = sigmoidf_(cr.z + sr.z + br.z);
        float z = sigmoidf_(cz.z + sz.z + bz.z);
        float nn = tanhf(cn.z + sni.z + r * (snh.z + bn.z));
        o.z = (1.0f - z) * nn + z * hv.z;
    }
    {
        float r = sigmoidf_(cr.w + sr.w + br.w);
        float z = sigmoidf_(cz.w + sz.w + bz.w);
        float nn = tanhf(cn.w + sni.w + r * (snh.w + bn.w));
        o.w = (1.0f - z) * nn + z * hv.w;
    }
    *(float4*)&ma[mo] = o;
    __nv_bfloat16 h4[4], l4[4];
    split_bf16(o.x, h4[0], l4[0]);
    split_bf16(o.y, h4[1], l4[1]);
    split_bf16(o.z, h4[2], l4[2]);
    split_bf16(o.w, h4[3], l4[3]);
    size_t xo = (size_t)m * 512 + 256 + n;
    *(float2*)&xcat_hi[xo] = *(float2*)h4;
    *(float2*)&xcat_lo[xo] = *(float2*)l4;
}

// ---------------- entity max-pool -> feat bf16 hi/lo into xcat cols [0,256) ----------------
__global__ void pool_kernel(const float* __restrict__ proc,
                            __nv_bfloat16* __restrict__ xcat_hi,
                            __nv_bfloat16* __restrict__ xcat_lo)
{
    int idx = blockIdx.x * blockDim.x + threadIdx.x;
    if (idx >= MA_ROWS * 64) return;
    int m = idx >> 6, n = (idx & 63) * 4;
    const float* p = proc + (size_t)m * EE * HH + n;
    float4 v = *(const float4*)p;
#pragma unroll
    for (int e = 1; e < EE; e++) {
        float4 w = *(const float4*)(p + e * HH);
        v.x = fmaxf(v.x, w.x); v.y = fmaxf(v.y, w.y);
        v.z = fmaxf(v.z, w.z); v.w = fmaxf(v.w, w.w);
    }
    __nv_bfloat16 h4[4], l4[4];
    split_bf16(v.x, h4[0], l4[0]);
    split_bf16(v.y, h4[1], l4[1]);
    split_bf16(v.z, h4[2], l4[2]);
    split_bf16(v.w, h4[3], l4[3]);
    size_t xo = (size_t)m * 512 + n;
    *(float2*)&xcat_hi[xo] = *(float2*)h4;
    *(float2*)&xcat_lo[xo] = *(float2*)l4;
}

// ---------------- head ----------------
__global__ void head_kernel(const float* __restrict__ t2,
                            const float* __restrict__ Wm2,   // [2,256]
                            const float* __restrict__ bm2,
                            float* __restrict__ out, int tstep)
{
    int warp = (blockIdx.x * blockDim.x + threadIdx.x) >> 5;
    int lane = threadIdx.x & 31;
    if (warp >= MA_ROWS) return;
    float s0 = 0.0f, s1 = 0.0f;
    for (int k = lane; k < HH; k += 32) {
        float x = t2[warp * HH + k];
        s0 += x * Wm2[k];
        s1 += x * Wm2[HH + k];
    }
#pragma unroll
    for (int off = 16; off; off >>= 1) {
        s0 += __shfl_xor_sync(0xffffffffu, s0, off);
        s1 += __shfl_xor_sync(0xffffffffu, s1, off);
    }
    if (lane == 0) {
        out[((size_t)tstep * MA_ROWS + warp) * 2 + 0] = tanhf(s0 + bm2[0]) * 0.05f;
        out[((size_t)tstep * MA_ROWS + warp) * 2 + 1] = tanhf(s1 + bm2[1]) * 0.05f;
    }
}

// ---------------- host launcher ----------------
extern "C" void kernel_launch(void* const* d_in, const int* in_sizes, int n_in,
                              void* d_out, int out_size)
{
    const float* obs    = (const float*)d_in[0];
    const float* phys   = (const float*)d_in[1];
    const float* goals  = (const float*)d_in[2];
    const float* mem_p  = (const float*)d_in[3];
    const float* mem_a  = (const float*)d_in[4];
    const float* Wih_p  = (const float*)d_in[5];
    const float* Whh_p  = (const float*)d_in[6];
    const float* bih_p  = (const float*)d_in[7];
    const float* bhh_p  = (const float*)d_in[8];
    const float* Wfc_p  = (const float*)d_in[9];
    const float* bfc_p  = (const float*)d_in[10];
    const float* Wih_a  = (const float*)d_in[11];
    const float* Whh_a  = (const float*)d_in[12];
    const float* bih_a  = (const float*)d_in[13];
    const float* bhh_a  = (const float*)d_in[14];
    const float* Wfc_a  = (const float*)d_in[15];
    const float* bfc_a  = (const float*)d_in[16];
    const float* Wm1    = (const float*)d_in[17];
    const float* bm1    = (const float*)d_in[18];
    const float* Wm2    = (const float*)d_in[19];
    const float* bm2    = (const float*)d_in[20];
    float* out = (float*)d_out;

    void* p;
    cudaGetSymbolAddress(&p, g_giC);     float* giC    = (float*)p;
    cudaGetSymbolAddress(&p, g_goalC);   float* goalC  = (float*)p;
    cudaGetSymbolAddress(&p, g_h);       float* h      = (float*)p;
    cudaGetSymbolAddress(&p, g_h_hi);    __nv_bfloat16* h_hi = (__nv_bfloat16*)p;
    cudaGetSymbolAddress(&p, g_h_lo);    __nv_bfloat16* h_lo = (__nv_bfloat16*)p;
    cudaGetSymbolAddress(&p, g_ma);      float* ma     = (float*)p;
    cudaGetSymbolAddress(&p, g_xcat_hi); __nv_bfloat16* xcat_hi = (__nv_bfloat16*)p;
    cudaGetSymbolAddress(&p, g_xcat_lo); __nv_bfloat16* xcat_lo = (__nv_bfloat16*)p;
    cudaGetSymbolAddress(&p, g_gates_p); float* gates_p = (float*)p;
    cudaGetSymbolAddress(&p, g_gates_a); float* gates_a = (float*)p;
    cudaGetSymbolAddress(&p, g_proc);    float* proc   = (float*)p;
    cudaGetSymbolAddress(&p, g_t1);      float* t1     = (float*)p;
    cudaGetSymbolAddress(&p, g_t1_hi);   __nv_bfloat16* t1_hi = (__nv_bfloat16*)p;
    cudaGetSymbolAddress(&p, g_t1_lo);   __nv_bfloat16* t1_lo = (__nv_bfloat16*)p;
    cudaGetSymbolAddress(&p, g_t2);      float* t2     = (float*)p;
    cudaGetSymbolAddress(&p, g_Whhp_hi); __nv_bfloat16* Whhp_hi = (__nv_bfloat16*)p;
    cudaGetSymbolAddress(&p, g_Whhp_lo); __nv_bfloat16* Whhp_lo = (__nv_bfloat16*)p;
    cudaGetSymbolAddress(&p, g_Wfcp_hi); __nv_bfloat16* Wfcp_hi = (__nv_bfloat16*)p;
    cudaGetSymbolAddress(&p, g_Wfcp_lo); __nv_bfloat16* Wfcp_lo = (__nv_bfloat16*)p;
    cudaGetSymbolAddress(&p, g_Wcat_hi); __nv_bfloat16* Wcat_hi = (__nv_bfloat16*)p;
    cudaGetSymbolAddress(&p, g_Wcat_lo); __nv_bfloat16* Wcat_lo = (__nv_bfloat16*)p;
    cudaGetSymbolAddress(&p, g_Wfca_hi); __nv_bfloat16* Wfca_hi = (__nv_bfloat16*)p;
    cudaGetSymbolAddress(&p, g_Wfca_lo); __nv_bfloat16* Wfca_lo = (__nv_bfloat16*)p;
    cudaGetSymbolAddress(&p, g_Wm1_hi);  __nv_bfloat16* Wm1_hi = (__nv_bfloat16*)p;
    cudaGetSymbolAddress(&p, g_Wm1_lo);  __nv_bfloat16* Wm1_lo = (__nv_bfloat16*)p;

    cudaStream_t s = 0;

    // ---- prep: initial state + weight splits + time-invariant GEMM parts ----
    cudaMemcpyAsync(h,  mem_p, (size_t)MP_ROWS * HH * sizeof(float), cudaMemcpyDeviceToDevice, s);
    cudaMemcpyAsync(ma, mem_a, (size_t)MA_ROWS * HH * sizeof(float), cudaMemcpyDeviceToDevice, s);
    split_kernel<<<(MP_ROWS * HH + 255) / 256, 256, 0, s>>>(mem_p, h_hi, h_lo, MP_ROWS * HH);
    split_strided_kernel<<<(MA_ROWS * HH + 255) / 256, 256, 0, s>>>(mem_a, xcat_hi + 256, xcat_lo + 256, MA_ROWS, HH, 512);
    split_kernel<<<(G3H * HH + 255) / 256, 256, 0, s>>>(Whh_p, Whhp_hi, Whhp_lo, G3H * HH);
    split_kernel<<<(HH * HH + 255) / 256, 256, 0, s>>>(Wfc_p, Wfcp_hi, Wfcp_lo, HH * HH);
    split_kernel<<<(HH * HH + 255) / 256, 256, 0, s>>>(Wfc_a, Wfca_hi, Wfca_lo, HH * HH);
    split_kernel<<<(HH * HH + 255) / 256, 256, 0, s>>>(Wm1, Wm1_hi, Wm1_lo, HH * HH);
    build_wcat_kernel<<<(1024 * 512 + 255) / 256, 256, 0, s>>>(Wih_a, Whh_a, Wcat_hi, Wcat_lo);
    prep_gip_kernel<<<(MP_ROWS * G3H + 255) / 256, 256, 0, s>>>(obs, phys, Wih_p, bih_p, giC);
    prep_goal_kernel<<<(MA_ROWS * G3H + 255) / 256, 256, 0, s>>>(goals, Wih_a, bih_a, goalC);

    // ---- recurrence ----
    for (int t = 0; t < TT; t++) {
        // physical GRU gates: [20480,768] = h @ Whh_p^T
        gemm_bf16x3<0><<<dim3(MP_ROWS / 128, G3H / 64), 256, 0, s>>>(
            h_hi, h_lo, HH, Whhp_hi, Whhp_lo, nullptr,
            gates_p, nullptr, nullptr, G3H, HH);
        gru_p_update_kernel<<<(MP_ROWS * 64 + 255) / 256, 256, 0, s>>>(gates_p, giC, bhh_p, h, h_hi, h_lo);
        // fc_p + ELU: proc = elu(h @ Wfc_p^T + b)
        gemm_bf16x3<1><<<dim3(MP_ROWS / 128, HH / 64), 256, 0, s>>>(
            h_hi, h_lo, HH, Wfcp_hi, Wfcp_lo, bfc_p,
            proc, nullptr, nullptr, HH, HH);
        pool_kernel<<<(MA_ROWS * 64 + 255) / 256, 256, 0, s>>>(proc, xcat_hi, xcat_lo);
        // action GRU gates: [2048,1024] = [feat|ma] @ Wcat^T
        gemm_bf16x3<0><<<dim3(MA_ROWS / 128, 1024 / 64), 256, 0, s>>>(
            xcat_hi, xcat_lo, 512, Wcat_hi, Wcat_lo, nullptr,
            gates_a, nullptr, nullptr, 1024, 512);
        gru_a_update_kernel<<<(MA_ROWS * 64 + 255) / 256, 256, 0, s>>>(gates_a, goalC, bhh_a, ma, xcat_hi, xcat_lo);
        // fc_a + ELU (input = new ma, at xcat cols [256,512))
        gemm_bf16x3<1><<<dim3(MA_ROWS / 128, HH / 64), 256, 0, s>>>(
            xcat_hi + 256, xcat_lo + 256, 512, Wfca_hi, Wfca_lo, bfc_a,
            t1, t1_hi, t1_lo, HH, HH);
        // m1 + ELU
        gemm_bf16x3<1><<<dim3(MA_ROWS / 128, HH / 64), 256, 0, s>>>(
            t1_hi, t1_lo, HH, Wm1_hi, Wm1_lo, bm1,
            t2, nullptr, nullptr, HH, HH);
        head_kernel<<<(MA_ROWS * 32 + 255) / 256, 256, 0, s>>>(t2, Wm2, bm2, out, t);
    }
}

// round 3
// speedup vs baseline: 2.3705x; 1.0754x over previous
#include <cuda_runtime.h>
#include <cuda_bf16.h>
#include <mma.h>
#include <math.h>

using namespace nvcuda;

#define BB 512
#define AA 4
#define EE 10
#define HH 256
#define TT 10
#define MP_ROWS (BB*AA*EE)   // 20480
#define MA_ROWS (BB*AA)      // 2048
#define G3H (3*HH)           // 768

// ---------------- scratch ----------------
__device__ __nv_bfloat16 g_h_hi[2][MP_ROWS * HH];
__device__ __nv_bfloat16 g_h_lo[2][MP_ROWS * HH];
__device__ __nv_bfloat16 g_xcat_hi[2][MA_ROWS * 512];   // [feat | ma]
__device__ __nv_bfloat16 g_xcat_lo[2][MA_ROWS * 512];
__device__ __nv_bfloat16 g_proc_hi[MP_ROWS * HH];
__device__ __nv_bfloat16 g_proc_lo[MP_ROWS * HH];
__device__ __nv_bfloat16 g_t1_hi[MA_ROWS * HH];
__device__ __nv_bfloat16 g_t1_lo[MA_ROWS * HH];
__device__ float g_t2[MA_ROWS * HH];
__device__ float g_xp8[MP_ROWS * 8];     // [ob0,ob1,ph0,ph1,ph2,0,0,0]
__device__ float g_xa4[MA_ROWS * 4];     // [g0,g1,g2,0]
__device__ float g_Wp8[G3H * 8];         // [w0..w4, bih, bhh, 0]
__device__ float g_Wa8[G3H * 8];         // [wg0,wg1,wg2, bih, bhh, 0,0,0]
__device__ __nv_bfloat16 g_Whhp_hi[G3H * HH], g_Whhp_lo[G3H * HH];
__device__ __nv_bfloat16 g_Wfcp_hi[HH * HH],  g_Wfcp_lo[HH * HH];
__device__ __nv_bfloat16 g_Wcat_hi[1024 * 512], g_Wcat_lo[1024 * 512];
__device__ __nv_bfloat16 g_Wfca_hi[HH * HH],  g_Wfca_lo[HH * HH];
__device__ __nv_bfloat16 g_Wm1_hi[HH * HH],   g_Wm1_lo[HH * HH];

// ---------------- helpers ----------------
__device__ __forceinline__ float sigmoidf_(float x) { return 1.0f / (1.0f + __expf(-x)); }
__device__ __forceinline__ float eluf_(float x) { return x > 0.0f ? x : expm1f(x); }
__device__ __forceinline__ void split_bf16(float x, __nv_bfloat16& hi, __nv_bfloat16& lo) {
    hi = __float2bfloat16_rn(x);
    lo = __float2bfloat16_rn(x - __bfloat162float(hi));
}
__device__ __forceinline__ void cp16(void* dst, const void* src) {
    unsigned d = (unsigned)__cvta_generic_to_shared(dst);
    asm volatile("cp.async.cg.shared.global [%0], [%1], 16;\n" :: "r"(d), "l"(src));
}
__device__ __forceinline__ void cp_commit() { asm volatile("cp.async.commit_group;\n" ::); }
template<int N> __device__ __forceinline__ void cp_wait() { asm volatile("cp.async.wait_group %0;\n" :: "n"(N)); }

// ---------------- prep kernels ----------------
__global__ void prep_xp_kernel(const float* __restrict__ obs, const float* __restrict__ phys,
                               float* __restrict__ xp8)
{
    int r = blockIdx.x * blockDim.x + threadIdx.x;
    if (r >= MP_ROWS) return;
    int b = r / (AA*EE);
    int e = r % EE;
    float* o = xp8 + r * 8;
    o[0] = obs[r*2+0]; o[1] = obs[r*2+1];
    const float* ph = phys + (b * EE + e) * 3;
    o[2] = ph[0]; o[3] = ph[1]; o[4] = ph[2];
    o[5] = 0.f; o[6] = 0.f; o[7] = 0.f;
}
__global__ void prep_wp8_kernel(const float* __restrict__ Wih, const float* __restrict__ bih,
                                const float* __restrict__ bhh, float* __restrict__ Wp8)
{
    int r = blockIdx.x * blockDim.x + threadIdx.x;
    if (r >= G3H) return;
    float* o = Wp8 + r * 8;
#pragma unroll
    for (int k = 0; k < 5; k++) o[k] = Wih[r*5+k];
    o[5] = bih[r]; o[6] = bhh[r]; o[7] = 0.f;
}
__global__ void prep_xa_kernel(const float* __restrict__ goals, float* __restrict__ xa4)
{
    int m = blockIdx.x * blockDim.x + threadIdx.x;
    if (m >= MA_ROWS) return;
    float* o = xa4 + m * 4;
    o[0] = goals[m*3+0]; o[1] = goals[m*3+1]; o[2] = goals[m*3+2]; o[3] = 0.f;
}
__global__ void prep_wa8_kernel(const float* __restrict__ Wih, const float* __restrict__ bih,
                                const float* __restrict__ bhh, float* __restrict__ Wa8)
{
    int r = blockIdx.x * blockDim.x + threadIdx.x;
    if (r >= G3H) return;
    float* o = Wa8 + r * 8;
    o[0] = Wih[r*259+256]; o[1] = Wih[r*259+257]; o[2] = Wih[r*259+258];
    o[3] = bih[r]; o[4] = bhh[r]; o[5] = 0.f; o[6] = 0.f; o[7] = 0.f;
}
__global__ void split_kernel(const float* __restrict__ src,
                             __nv_bfloat16* __restrict__ hi, __nv_bfloat16* __restrict__ lo, int n)
{
    int i = blockIdx.x * blockDim.x + threadIdx.x;
    if (i >= n) return;
    split_bf16(src[i], hi[i], lo[i]);
}
__global__ void split_strided_kernel(const float* __restrict__ src,
                                     __nv_bfloat16* __restrict__ hi, __nv_bfloat16* __restrict__ lo,
                                     int rows, int cols, int ldo)
{
    int i = blockIdx.x * blockDim.x + threadIdx.x;
    if (i >= rows * cols) return;
    int r = i / cols, c = i - r * cols;
    split_bf16(src[i], hi[r * ldo + c], lo[r * ldo + c]);
}
__global__ void build_wcat_kernel(const float* __restrict__ Wih,  // [768,259]
                                  const float* __restrict__ Whh,  // [768,256]
                                  __nv_bfloat16* __restrict__ hi, __nv_bfloat16* __restrict__ lo)
{
    int idx = blockIdx.x * blockDim.x + threadIdx.x;
    if (idx >= 1024 * 512) return;
    int row = idx >> 9, col = idx & 511;
    int g = row >> 8, n = row & 255;
    float v = 0.0f;
    if (g < 2) {
        v = (col < 256) ? Wih[(g * 256 + n) * 259 + col] : Whh[(g * 256 + n) * 256 + (col - 256)];
    } else if (g == 2) {
        if (col < 256) v = Wih[(512 + n) * 259 + col];
    } else {
        if (col >= 256) v = Whh[(512 + n) * 256 + (col - 256)];
    }
    split_bf16(v, hi[idx], lo[idx]);
}

// ---------------- fused GEMM kernel ----------------
// MODE 0: physical GRU  (NSEG=3, K=256)  out = GRU update -> Ohi/Olo
// MODE 1: action GRU    (NSEG=4, K=512)  out = GRU update -> Ohi/Olo
// MODE 2: ELU layer     (NSEG=1, K=256)  out = elu(acc+bias) -> Ohi/Olo and/or Ofp
// Block: 128(M) x 64(N per segment), BK=32, 256 threads, 8 warps (4x2 of 32x32).
template<int MODE>
__global__ __launch_bounds__(256) void fused_kernel(
    const __nv_bfloat16* __restrict__ Ahi, const __nv_bfloat16* __restrict__ Alo, int lda,
    const __nv_bfloat16* __restrict__ Bhi, const __nv_bfloat16* __restrict__ Blo,
    const float* __restrict__ xw,     // xp8 / xa4 / bias
    const float* __restrict__ swg,    // Wp8 / Wa8 / unused
    const __nv_bfloat16* __restrict__ oldHi, const __nv_bfloat16* __restrict__ oldLo, int oldLd,
    __nv_bfloat16* __restrict__ Ohi, __nv_bfloat16* __restrict__ Olo, int ldo,
    float* __restrict__ Ofp)
{
    constexpr int NSEG = (MODE == 0) ? 3 : ((MODE == 1) ? 4 : 1);
    constexpr int K = (MODE == 1) ? 512 : 256;
    constexpr int KT = K / 32;
    constexpr int AHS = 128 * 40;          // A half-stage elems
    constexpr int BHS = NSEG * 64 * 40;    // B half-stage elems

    extern __shared__ char smem_raw[];
    __nv_bfloat16* sm = (__nv_bfloat16*)smem_raw;
    // layout: Ahi[0],Ahi[1],Alo[0],Alo[1],Bhi[0],Bhi[1],Blo[0],Blo[1]
    __nv_bfloat16* sAh[2] = { sm,            sm + AHS };
    __nv_bfloat16* sAl[2] = { sm + 2*AHS,   sm + 3*AHS };
    __nv_bfloat16* sBh[2] = { sm + 4*AHS,            sm + 4*AHS + BHS };
    __nv_bfloat16* sBl[2] = { sm + 4*AHS + 2*BHS,    sm + 4*AHS + 3*BHS };

    const int m0 = blockIdx.x * 128;
    const int n0 = blockIdx.y * 64;
    const int tid = threadIdx.x;
    const int wid = tid >> 5;
    const int lane = tid & 31;
    const int wm = wid >> 1, wn = wid & 1;

    auto load_tile = [&](int s, int kt) {
        const int k0 = kt * 32;
        // A: 1024 16B chunks (hi+lo)
#pragma unroll
        for (int r = 0; r < 4; r++) {
            int c = tid + r * 256;
            int half = c >> 9;
            int c2 = c & 511;
            int row = c2 >> 2, kk = (c2 & 3) * 8;
            const __nv_bfloat16* src = (half ? Alo : Ahi) + (size_t)(m0 + row) * lda + k0 + kk;
            __nv_bfloat16* dst = (half ? sAl : sAh)[s] + row * 40 + kk;
            cp16(dst, src);
        }
        // B: NSEG*512 chunks
#pragma unroll
        for (int r = 0; r < NSEG * 2; r++) {
            int c = tid + r * 256;
            int half = (c >= NSEG * 256) ? 1 : 0;
            int c2 = c - half * NSEG * 256;
            int srow = c2 >> 2, kk = (c2 & 3) * 8;
            int seg = srow >> 6, nloc = srow & 63;
            const __nv_bfloat16* src = (half ? Blo : Bhi) + (size_t)(seg * 256 + n0 + nloc) * K + k0 + kk;
            __nv_bfloat16* dst = (half ? sBl : sBh)[s] + srow * 40 + kk;
            cp16(dst, src);
        }
    };

    wmma::fragment<wmma::accumulator, 16, 16, 16, float> acc[NSEG][2][2];
#pragma unroll
    for (int g = 0; g < NSEG; g++)
#pragma unroll
        for (int i = 0; i < 2; i++)
#pragma unroll
            for (int j = 0; j < 2; j++) wmma::fill_fragment(acc[g][i][j], 0.0f);

    load_tile(0, 0); cp_commit();
    load_tile(1, 1); cp_commit();

    for (int kt = 0; kt < KT; kt++) {
        if (kt == KT - 1) cp_wait<0>(); else cp_wait<1>();
        __syncthreads();
        const int s = kt & 1;
#pragma unroll
        for (int kc = 0; kc < 32; kc += 16) {
            wmma::fragment<wmma::matrix_a, 16, 16, 16, __nv_bfloat16, wmma::row_major> ah[2], al[2];
#pragma unroll
            for (int i = 0; i < 2; i++) {
                wmma::load_matrix_sync(ah[i], sAh[s] + (wm * 32 + i * 16) * 40 + kc, 40);
                wmma::load_matrix_sync(al[i], sAl[s] + (wm * 32 + i * 16) * 40 + kc, 40);
            }
#pragma unroll
            for (int g = 0; g < NSEG; g++) {
                wmma::fragment<wmma::matrix_b, 16, 16, 16, __nv_bfloat16, wmma::col_major> bh[2], bl[2];
#pragma unroll
                for (int j = 0; j < 2; j++) {
                    wmma::load_matrix_sync(bh[j], sBh[s] + (g * 64 + wn * 32 + j * 16) * 40 + kc, 40);
                    wmma::load_matrix_sync(bl[j], sBl[s] + (g * 64 + wn * 32 + j * 16) * 40 + kc, 40);
                }
#pragma unroll
                for (int i = 0; i < 2; i++)
#pragma unroll
                    for (int j = 0; j < 2; j++) {
                        wmma::mma_sync(acc[g][i][j], ah[i], bh[j], acc[g][i][j]);
                        wmma::mma_sync(acc[g][i][j], ah[i], bl[j], acc[g][i][j]);
                        wmma::mma_sync(acc[g][i][j], al[i], bh[j], acc[g][i][j]);
                    }
            }
        }
        __syncthreads();
        if (kt + 2 < KT) { load_tile(kt & 1, kt + 2); cp_commit(); }
    }

    // ---------------- epilogue ----------------
    // smem reuse (mainloop data dead): wbuf | sX | sW
    float* wbuf = (float*)smem_raw;                       // 8 warps x NSEG x 320 floats
    float* sX = wbuf + 8 * NSEG * 320;                    // 128 x (8|4)
    constexpr int XW = (MODE == 1) ? 4 : 8;
    float* sW = sX + 128 * XW;                            // 192 x 8 (MODE 0/1)

    if (MODE != 2) {
        // cooperative loads of x rows and packed gate weights
#pragma unroll
        for (int r = 0; r < (128 * XW) / 256; r++) {
            int c = tid + r * 256;
            sX[c] = xw[(size_t)(m0 + (c / XW)) * XW + (c % XW)];
        }
#pragma unroll
        for (int r = 0; r < 6; r++) {
            int c = tid + r * 256;       // 1536 = 192*8
            int srow = c >> 3, k = c & 7;
            int seg = srow >> 6, nloc = srow & 63;
            sW[c] = swg[(size_t)(seg * 256 + n0 + nloc) * 8 + k];
        }
    }
    __syncthreads();

    float* wb = wbuf + wid * NSEG * 320;
    const int r_ = lane >> 1;
    const int c0_ = (lane & 1) * 8;

#pragma unroll
    for (int i = 0; i < 2; i++) {
#pragma unroll
        for (int j = 0; j < 2; j++) {
#pragma unroll
            for (int g = 0; g < NSEG; g++)
                wmma::store_matrix_sync(wb + g * 320, acc[g][i][j], 20, wmma::mem_row_major);
            __syncwarp();

            const int mloc = wm * 32 + i * 16 + r_;
            const int m = m0 + mloc;
            const int nl0 = wn * 32 + j * 16 + c0_;   // 0..63 local col
            const int nabs = n0 + nl0;

            __nv_bfloat16 oh8[8], ol8[8];

            if (MODE == 2) {
                float4 b0 = *(const float4*)&xw[nabs];
                float4 b1 = *(const float4*)&xw[nabs + 4];
                float bia[8] = {b0.x,b0.y,b0.z,b0.w,b1.x,b1.y,b1.z,b1.w};
                float ov[8];
#pragma unroll
                for (int cc = 0; cc < 8; cc++) {
                    float v = eluf_(wb[r_ * 20 + c0_ + cc] + bia[cc]);
                    ov[cc] = v;
                    split_bf16(v, oh8[cc], ol8[cc]);
                }
                if (Ofp) {
                    *(float4*)&Ofp[(size_t)m * 256 + nabs] = make_float4(ov[0],ov[1],ov[2],ov[3]);
                    *(float4*)&Ofp[(size_t)m * 256 + nabs + 4] = make_float4(ov[4],ov[5],ov[6],ov[7]);
                }
                if (Ohi) {
                    *(float4*)&Ohi[(size_t)m * ldo + nabs] = *(float4*)oh8;
                    *(float4*)&Olo[(size_t)m * ldo + nabs] = *(float4*)ol8;
                }
            } else {
                // old state (8 contiguous bf16 each)
                float4 hv4 = *(const float4*)&oldHi[(size_t)m * oldLd + nabs];
                float4 lv4 = *(const float4*)&oldLo[(size_t)m * oldLd + nabs];
                const __nv_bfloat16* hvp = (const __nv_bfloat16*)&hv4;
                const __nv_bfloat16* lvp = (const __nv_bfloat16*)&lv4;
                float xr[XW];
#pragma unroll
                for (int k = 0; k < XW; k++) xr[k] = sX[mloc * XW + k];
#pragma unroll
                for (int cc = 0; cc < 8; cc++) {
                    int nl = nl0 + cc;
                    const float* w0 = sW + (0 * 64 + nl) * 8;
                    const float* w1 = sW + (1 * 64 + nl) * 8;
                    const float* w2 = sW + (2 * 64 + nl) * 8;
                    float a0 = wb[0 * 320 + r_ * 20 + c0_ + cc];
                    float a1 = wb[1 * 320 + r_ * 20 + c0_ + cc];
                    float a2 = wb[2 * 320 + r_ * 20 + c0_ + cc];
                    float gi_r, gi_z, gi_n, rr, zz, nn;
                    if (MODE == 0) {
                        gi_r = w0[5]; gi_z = w1[5]; gi_n = w2[5];
#pragma unroll
                        for (int k = 0; k < 5; k++) {
                            gi_r += xr[k] * w0[k];
                            gi_z += xr[k] * w1[k];
                            gi_n += xr[k] * w2[k];
                        }
                        rr = sigmoidf_(gi_r + a0 + w0[6]);
                        zz = sigmoidf_(gi_z + a1 + w1[6]);
                        nn = tanhf(gi_n + rr * (a2 + w2[6]));
                    } else {
                        float a3 = wb[3 * 320 + r_ * 20 + c0_ + cc];
                        gi_r = w0[3]; gi_z = w1[3]; gi_n = w2[3];
#pragma unroll
                        for (int k = 0; k < 3; k++) {
                            gi_r += xr[k] * w0[k];
                            gi_z += xr[k] * w1[k];
                            gi_n += xr[k] * w2[k];
                        }
                        rr = sigmoidf_(gi_r + a0 + w0[4]);
                        zz = sigmoidf_(gi_z + a1 + w1[4]);
                        nn = tanhf(gi_n + a2 + rr * (a3 + w2[4]));
                    }
                    float hold = __bfloat162float(hvp[cc]) + __bfloat162float(lvp[cc]);
                    float hnew = (1.0f - zz) * nn + zz * hold;
                    split_bf16(hnew, oh8[cc], ol8[cc]);
                }
                *(float4*)&Ohi[(size_t)m * ldo + nabs] = *(float4*)oh8;
                *(float4*)&Olo[(size_t)m * ldo + nabs] = *(float4*)ol8;
            }
            __syncwarp();
        }
    }
}

// ---------------- entity max-pool (bf16 hi/lo in/out) ----------------
__global__ void pool_kernel(const __nv_bfloat16* __restrict__ phi,
                            const __nv_bfloat16* __restrict__ plo,
                            __nv_bfloat16* __restrict__ xcat_hi,
                            __nv_bfloat16* __restrict__ xcat_lo)
{
    int idx = blockIdx.x * blockDim.x + threadIdx.x;   // MA_ROWS*32
    if (idx >= MA_ROWS * 32) return;
    int m = idx >> 5, c8 = (idx & 31) * 8;
    float v[8];
#pragma unroll
    for (int k = 0; k < 8; k++) v[k] = -1e30f;
#pragma unroll
    for (int e = 0; e < EE; e++) {
        size_t off = (size_t)(m * EE + e) * HH + c8;
        float4 h4 = *(const float4*)&phi[off];
        float4 l4 = *(const float4*)&plo[off];
        const __nv_bfloat16* hp = (const __nv_bfloat16*)&h4;
        const __nv_bfloat16* lp = (const __nv_bfloat16*)&l4;
#pragma unroll
        for (int k = 0; k < 8; k++)
            v[k] = fmaxf(v[k], __bfloat162float(hp[k]) + __bfloat162float(lp[k]));
    }
    __nv_bfloat16 h8[8], l8[8];
#pragma unroll
    for (int k = 0; k < 8; k++) split_bf16(v[k], h8[k], l8[k]);
    size_t xo = (size_t)m * 512 + c8;
    *(float4*)&xcat_hi[xo] = *(float4*)h8;
    *(float4*)&xcat_lo[xo] = *(float4*)l8;
}

// ---------------- head ----------------
__global__ void head_kernel(const float* __restrict__ t2,
                            const float* __restrict__ Wm2, const float* __restrict__ bm2,
                            float* __restrict__ out, int tstep)
{
    int warp = (blockIdx.x * blockDim.x + threadIdx.x) >> 5;
    int lane = threadIdx.x & 31;
    if (warp >= MA_ROWS) return;
    float s0 = 0.0f, s1 = 0.0f;
    for (int k = lane; k < HH; k += 32) {
        float x = t2[warp * HH + k];
        s0 += x * Wm2[k];
        s1 += x * Wm2[HH + k];
    }
#pragma unroll
    for (int off = 16; off; off >>= 1) {
        s0 += __shfl_xor_sync(0xffffffffu, s0, off);
        s1 += __shfl_xor_sync(0xffffffffu, s1, off);
    }
    if (lane == 0) {
        out[((size_t)tstep * MA_ROWS + warp) * 2 + 0] = tanhf(s0 + bm2[0]) * 0.05f;
        out[((size_t)tstep * MA_ROWS + warp) * 2 + 1] = tanhf(s1 + bm2[1]) * 0.05f;
    }
}

// ---------------- host launcher ----------------
extern "C" void kernel_launch(void* const* d_in, const int* in_sizes, int n_in,
                              void* d_out, int out_size)
{
    const float* obs    = (const float*)d_in[0];
    const float* phys   = (const float*)d_in[1];
    const float* goals  = (const float*)d_in[2];
    const float* mem_p  = (const float*)d_in[3];
    const float* mem_a  = (const float*)d_in[4];
    const float* Wih_p  = (const float*)d_in[5];
    const float* Whh_p  = (const float*)d_in[6];
    const float* bih_p  = (const float*)d_in[7];
    const float* bhh_p  = (const float*)d_in[8];
    const float* Wfc_p  = (const float*)d_in[9];
    const float* bfc_p  = (const float*)d_in[10];
    const float* Wih_a  = (const float*)d_in[11];
    const float* Whh_a  = (const float*)d_in[12];
    const float* bih_a  = (const float*)d_in[13];
    const float* bhh_a  = (const float*)d_in[14];
    const float* Wfc_a  = (const float*)d_in[15];
    const float* bfc_a  = (const float*)d_in[16];
    const float* Wm1    = (const float*)d_in[17];
    const float* bm1    = (const float*)d_in[18];
    const float* Wm2    = (const float*)d_in[19];
    const float* bm2    = (const float*)d_in[20];
    float* out = (float*)d_out;

    void* p;
    __nv_bfloat16 *h_hi[2], *h_lo[2], *xc_hi[2], *xc_lo[2];
    cudaGetSymbolAddress(&p, g_h_hi);    h_hi[0] = (__nv_bfloat16*)p; h_hi[1] = h_hi[0] + (size_t)MP_ROWS*HH;
    cudaGetSymbolAddress(&p, g_h_lo);    h_lo[0] = (__nv_bfloat16*)p; h_lo[1] = h_lo[0] + (size_t)MP_ROWS*HH;
    cudaGetSymbolAddress(&p, g_xcat_hi); xc_hi[0] = (__nv_bfloat16*)p; xc_hi[1] = xc_hi[0] + (size_t)MA_ROWS*512;
    cudaGetSymbolAddress(&p, g_xcat_lo); xc_lo[0] = (__nv_bfloat16*)p; xc_lo[1] = xc_lo[0] + (size_t)MA_ROWS*512;
    cudaGetSymbolAddress(&p, g_proc_hi); __nv_bfloat16* proc_hi = (__nv_bfloat16*)p;
    cudaGetSymbolAddress(&p, g_proc_lo); __nv_bfloat16* proc_lo = (__nv_bfloat16*)p;
    cudaGetSymbolAddress(&p, g_t1_hi);   __nv_bfloat16* t1_hi = (__nv_bfloat16*)p;
    cudaGetSymbolAddress(&p, g_t1_lo);   __nv_bfloat16* t1_lo = (__nv_bfloat16*)p;
    cudaGetSymbolAddress(&p, g_t2);      float* t2 = (float*)p;
    cudaGetSymbolAddress(&p, g_xp8);     float* xp8 = (float*)p;
    cudaGetSymbolAddress(&p, g_xa4);     float* xa4 = (float*)p;
    cudaGetSymbolAddress(&p, g_Wp8);     float* Wp8 = (float*)p;
    cudaGetSymbolAddress(&p, g_Wa8);     float* Wa8 = (float*)p;
    cudaGetSymbolAddress(&p, g_Whhp_hi); __nv_bfloat16* Whhp_hi = (__nv_bfloat16*)p;
    cudaGetSymbolAddress(&p, g_Whhp_lo); __nv_bfloat16* Whhp_lo = (__nv_bfloat16*)p;
    cudaGetSymbolAddress(&p, g_Wfcp_hi); __nv_bfloat16* Wfcp_hi = (__nv_bfloat16*)p;
    cudaGetSymbolAddress(&p, g_Wfcp_lo); __nv_bfloat16* Wfcp_lo = (__nv_bfloat16*)p;
    cudaGetSymbolAddress(&p, g_Wcat_hi); __nv_bfloat16* Wcat_hi = (__nv_bfloat16*)p;
    cudaGetSymbolAddress(&p, g_Wcat_lo); __nv_bfloat16* Wcat_lo = (__nv_bfloat16*)p;
    cudaGetSymbolAddress(&p, g_Wfca_hi); __nv_bfloat16* Wfca_hi = (__nv_bfloat16*)p;
    cudaGetSymbolAddress(&p, g_Wfca_lo); __nv_bfloat16* Wfca_lo = (__nv_bfloat16*)p;
    cudaGetSymbolAddress(&p, g_Wm1_hi);  __nv_bfloat16* Wm1_hi = (__nv_bfloat16*)p;
    cudaGetSymbolAddress(&p, g_Wm1_lo);  __nv_bfloat16* Wm1_lo = (__nv_bfloat16*)p;

    const int SM0 = 40960 + 4 * 3 * 5120;  // 102400
    const int SM1 = 40960 + 4 * 4 * 5120;  // 122880
    const int SM2 = 40960 + 4 * 1 * 5120;  // 61440
    cudaFuncSetAttribute(fused_kernel<0>, cudaFuncAttributeMaxDynamicSharedMemorySize, SM0);
    cudaFuncSetAttribute(fused_kernel<1>, cudaFuncAttributeMaxDynamicSharedMemorySize, SM1);
    cudaFuncSetAttribute(fused_kernel<2>, cudaFuncAttributeMaxDynamicSharedMemorySize, SM2);

    cudaStream_t s = 0;

    // ---- prep ----
    split_kernel<<<(MP_ROWS*HH + 255)/256, 256, 0, s>>>(mem_p, h_hi[0], h_lo[0], MP_ROWS*HH);
    split_strided_kernel<<<(MA_ROWS*HH + 255)/256, 256, 0, s>>>(mem_a, xc_hi[0] + 256, xc_lo[0] + 256, MA_ROWS, HH, 512);
    split_kernel<<<(G3H*HH + 255)/256, 256, 0, s>>>(Whh_p, Whhp_hi, Whhp_lo, G3H*HH);
    split_kernel<<<(HH*HH + 255)/256, 256, 0, s>>>(Wfc_p, Wfcp_hi, Wfcp_lo, HH*HH);
    split_kernel<<<(HH*HH + 255)/256, 256, 0, s>>>(Wfc_a, Wfca_hi, Wfca_lo, HH*HH);
    split_kernel<<<(HH*HH + 255)/256, 256, 0, s>>>(Wm1, Wm1_hi, Wm1_lo, HH*HH);
    build_wcat_kernel<<<(1024*512 + 255)/256, 256, 0, s>>>(Wih_a, Whh_a, Wcat_hi, Wcat_lo);
    prep_xp_kernel<<<(MP_ROWS + 255)/256, 256, 0, s>>>(obs, phys, xp8);
    prep_wp8_kernel<<<(G3H + 255)/256, 256, 0, s>>>(Wih_p, bih_p, bhh_p, Wp8);
    prep_xa_kernel<<<(MA_ROWS + 255)/256, 256, 0, s>>>(goals, xa4);
    prep_wa8_kernel<<<(G3H + 255)/256, 256, 0, s>>>(Wih_a, bih_a, bhh_a, Wa8);

    // ---- recurrence ----
    int cur = 0;
    for (int t = 0; t < TT; t++) {
        int nxt = cur ^ 1;
        // physical GRU fused: h_nxt = GRU(h_cur)
        fused_kernel<0><<<dim3(MP_ROWS/128, 4), 256, SM0, s>>>(
            h_hi[cur], h_lo[cur], HH, Whhp_hi, Whhp_lo, xp8, Wp8,
            h_hi[cur], h_lo[cur], HH,
            h_hi[nxt], h_lo[nxt], HH, nullptr);
        // fc_p + ELU -> proc (hi/lo)
        fused_kernel<2><<<dim3(MP_ROWS/128, 4), 256, SM2, s>>>(
            h_hi[nxt], h_lo[nxt], HH, Wfcp_hi, Wfcp_lo, bfc_p, nullptr,
            nullptr, nullptr, 0,
            proc_hi, proc_lo, HH, nullptr);
        // pool -> feat into xcat[cur][0:256)
        pool_kernel<<<(MA_ROWS*32 + 255)/256, 256, 0, s>>>(proc_hi, proc_lo, xc_hi[cur], xc_lo[cur]);
        // action GRU fused: ma_nxt (into xcat[nxt] cols 256..511)
        fused_kernel<1><<<dim3(MA_ROWS/128, 4), 256, SM1, s>>>(
            xc_hi[cur], xc_lo[cur], 512, Wcat_hi, Wcat_lo, xa4, Wa8,
            xc_hi[cur] + 256, xc_lo[cur] + 256, 512,
            xc_hi[nxt] + 256, xc_lo[nxt] + 256, 512, nullptr);
        // fc_a + ELU -> t1
        fused_kernel<2><<<dim3(MA_ROWS/128, 4), 256, SM2, s>>>(
            xc_hi[nxt] + 256, xc_lo[nxt] + 256, 512, Wfca_hi, Wfca_lo, bfc_a, nullptr,
            nullptr, nullptr, 0,
            t1_hi, t1_lo, HH, nullptr);
        // m1 + ELU -> t2 (fp32)
        fused_kernel<2><<<dim3(MA_ROWS/128, 4), 256, SM2, s>>>(
            t1_hi, t1_lo, HH, Wm1_hi, Wm1_lo, bm1, nullptr,
            nullptr, nullptr, 0,
            nullptr, nullptr, 0, t2);
        head_kernel<<<(MA_ROWS*32 + 255)/256, 256, 0, s>>>(t2, Wm2, bm2, out, t);
        cur = nxt;
    }
}

// round 5
// speedup vs baseline: 3.3534x; 1.4147x over previous
#include <cuda_runtime.h>
#include <cuda_fp16.h>
#include <mma.h>
#include <math.h>
#include <stdint.h>

using namespace nvcuda;

#define BB 512
#define AA 4
#define EE 10
#define HH 256
#define TT 10
#define MP_ROWS (BB*AA*EE)   // 20480
#define MA_ROWS (BB*AA)      // 2048
#define G3H (3*HH)           // 768

// ---------------- scratch ----------------
__device__ __half g_h_hi[2][MP_ROWS * HH];
__device__ __half g_h_lo[2][MP_ROWS * HH];
__device__ __half g_xcat_hi[2][MA_ROWS * 512];   // [feat | ma]
__device__ __half g_xcat_lo[2][MA_ROWS * 512];
__device__ __half g_proc_hi[MP_ROWS * HH];
__device__ __half g_proc_lo[MP_ROWS * HH];
__device__ __half g_t1_hi[MA_ROWS * HH];
__device__ __half g_t1_lo[MA_ROWS * HH];
__device__ float g_t2[MA_ROWS * HH];
__device__ float g_xp8[MP_ROWS * 8];     // [ob0,ob1,ph0,ph1,ph2,0,0,0]
__device__ float g_xa4[MA_ROWS * 4];     // [g0,g1,g2,0]
__device__ float g_Wp8[G3H * 8];         // [w0..w4, bih, bhh, 0]
__device__ float g_Wa8[G3H * 8];         // [wg0..2, bih, bhh, 0,0,0]
__device__ __half g_Whhp[G3H * HH];
__device__ __half g_Wfcp[HH * HH];
__device__ __half g_Wcat[1024 * 512];
__device__ __half g_Wfca[HH * HH];
__device__ __half g_Wm1[HH * HH];

// ---------------- helpers ----------------
__device__ __forceinline__ float sigmoidf_(float x) { return 1.0f / (1.0f + __expf(-x)); }
__device__ __forceinline__ float eluf_(float x) { return x > 0.0f ? x : expm1f(x); }
__device__ __forceinline__ void split_fp16(float x, __half& hi, __half& lo) {
    hi = __float2half_rn(x);
    lo = __float2half_rn(x - __half2float(hi));
}
__device__ __forceinline__ void cp16(void* dst, const void* src) {
    unsigned d = (unsigned)__cvta_generic_to_shared(dst);
    asm volatile("cp.async.cg.shared.global [%0], [%1], 16;\n" :: "r"(d), "l"(src));
}
__device__ __forceinline__ void cp_commit() { asm volatile("cp.async.commit_group;\n" ::); }
template<int N> __device__ __forceinline__ void cp_wait() { asm volatile("cp.async.wait_group %0;\n" :: "n"(N)); }

// ---------------- prep kernels ----------------
__global__ void prep_xp_kernel(const float* __restrict__ obs, const float* __restrict__ phys,
                               float* __restrict__ xp8)
{
    int r = blockIdx.x * blockDim.x + threadIdx.x;
    if (r >= MP_ROWS) return;
    int b = r / (AA*EE);
    int e = r % EE;
    float* o = xp8 + r * 8;
    o[0] = obs[r*2+0]; o[1] = obs[r*2+1];
    const float* ph = phys + (b * EE + e) * 3;
    o[2] = ph[0]; o[3] = ph[1]; o[4] = ph[2];
    o[5] = 0.f; o[6] = 0.f; o[7] = 0.f;
}
__global__ void prep_wp8_kernel(const float* __restrict__ Wih, const float* __restrict__ bih,
                                const float* __restrict__ bhh, float* __restrict__ Wp8)
{
    int r = blockIdx.x * blockDim.x + threadIdx.x;
    if (r >= G3H) return;
    float* o = Wp8 + r * 8;
#pragma unroll
    for (int k = 0; k < 5; k++) o[k] = Wih[r*5+k];
    o[5] = bih[r]; o[6] = bhh[r]; o[7] = 0.f;
}
__global__ void prep_xa_kernel(const float* __restrict__ goals, float* __restrict__ xa4)
{
    int m = blockIdx.x * blockDim.x + threadIdx.x;
    if (m >= MA_ROWS) return;
    float* o = xa4 + m * 4;
    o[0] = goals[m*3+0]; o[1] = goals[m*3+1]; o[2] = goals[m*3+2]; o[3] = 0.f;
}
__global__ void prep_wa8_kernel(const float* __restrict__ Wih, const float* __restrict__ bih,
                                const float* __restrict__ bhh, float* __restrict__ Wa8)
{
    int r = blockIdx.x * blockDim.x + threadIdx.x;
    if (r >= G3H) return;
    float* o = Wa8 + r * 8;
    o[0] = Wih[r*259+256]; o[1] = Wih[r*259+257]; o[2] = Wih[r*259+258];
    o[3] = bih[r]; o[4] = bhh[r]; o[5] = 0.f; o[6] = 0.f; o[7] = 0.f;
}
__global__ void split_kernel(const float* __restrict__ src,
                             __half* __restrict__ hi, __half* __restrict__ lo, int n)
{
    int i = blockIdx.x * blockDim.x + threadIdx.x;
    if (i >= n) return;
    split_fp16(src[i], hi[i], lo[i]);
}
__global__ void split_strided_kernel(const float* __restrict__ src,
                                     __half* __restrict__ hi, __half* __restrict__ lo,
                                     int rows, int cols, int ldo)
{
    int i = blockIdx.x * blockDim.x + threadIdx.x;
    if (i >= rows * cols) return;
    int r = i / cols, c = i - r * cols;
    split_fp16(src[i], hi[r * ldo + c], lo[r * ldo + c]);
}
__global__ void conv_kernel(const float* __restrict__ src, __half* __restrict__ dst, int n)
{
    int i = blockIdx.x * blockDim.x + threadIdx.x;
    if (i >= n) return;
    dst[i] = __float2half_rn(src[i]);
}
// Wcat [1024, 512]: rows g*256+n. g=0:[Wih_r|Whh_r] g=1:[Wih_z|Whh_z] g=2:[Wih_n|0] g=3:[0|Whh_n]
__global__ void build_wcat_kernel(const float* __restrict__ Wih,  // [768,259]
                                  const float* __restrict__ Whh,  // [768,256]
                                  __half* __restrict__ Wcat)
{
    int idx = blockIdx.x * blockDim.x + threadIdx.x;
    if (idx >= 1024 * 512) return;
    int row = idx >> 9, col = idx & 511;
    int g = row >> 8, n = row & 255;
    float v = 0.0f;
    if (g < 2) {
        v = (col < 256) ? Wih[(g * 256 + n) * 259 + col] : Whh[(g * 256 + n) * 256 + (col - 256)];
    } else if (g == 2) {
        if (col < 256) v = Wih[(512 + n) * 259 + col];
    } else {
        if (col >= 256) v = Whh[(512 + n) * 256 + (col - 256)];
    }
    Wcat[idx] = __float2half_rn(v);
}

// ---------------- fused fp16 2-pass GEMM kernel ----------------
// MODE 0: physical GRU  (NSEG=3, K=256), MODE 1: action GRU (NSEG=4, K=512),
// MODE 2: ELU layer     (NSEG=1, K=256).
// A given as fp16 hi/lo pair (2 MMA passes vs single-fp16 B). Block: BM x 64 per seg,
// 256 threads (8 warps). BM=128: warp tile 32x32 (2x2 frags); BM=64: 16x32 (1x2).
template<int MODE, int BM>
__global__ __launch_bounds__(256) void fused_kernel(
    const __half* __restrict__ Ahi, const __half* __restrict__ Alo, int lda,
    const __half* __restrict__ B,
    const float* __restrict__ xw,     // xp8 / xa4 / bias
    const float* __restrict__ swg,    // Wp8 / Wa8 / unused
    const __half* __restrict__ oldHi, const __half* __restrict__ oldLo, int oldLd,
    __half* __restrict__ Ohi, __half* __restrict__ Olo, int ldo,
    float* __restrict__ Ofp)
{
    constexpr int NSEG = (MODE == 0) ? 3 : ((MODE == 1) ? 4 : 1);
    constexpr int K = (MODE == 1) ? 512 : 256;
    constexpr int KT = K / 32;
    constexpr int MI = BM / 64;            // fragments along M per warp
    constexpr int AITER = BM / 32;         // A cp16 chunks per thread
    constexpr int AHS = BM * 40;           // halfs per A matrix per stage
    constexpr int BHS = NSEG * 64 * 40;

    extern __shared__ __align__(16) char smem_raw[];
    __half* sm = (__half*)smem_raw;
    __half* sAh[2] = { sm,           sm + AHS };
    __half* sAl[2] = { sm + 2*AHS,   sm + 3*AHS };
    __half* sB[2]  = { sm + 4*AHS,   sm + 4*AHS + BHS };

    const int m0 = blockIdx.x * BM;
    const int n0 = blockIdx.y * 64;
    const int tid = threadIdx.x;
    const int wid = tid >> 5;
    const int lane = tid & 31;
    const int wm = wid >> 1, wn = wid & 1;

    auto load_tile = [&](int s, int kt) {
        const int k0 = kt * 32;
#pragma unroll
        for (int r = 0; r < AITER; r++) {
            int c = tid + r * 256;
            int half_ = (c >= BM * 4) ? 1 : 0;
            int c2 = c - half_ * BM * 4;
            int row = c2 >> 2, kk = (c2 & 3) * 8;
            const __half* src = (half_ ? Alo : Ahi) + (size_t)(m0 + row) * lda + k0 + kk;
            cp16((half_ ? sAl : sAh)[s] + row * 40 + kk, src);
        }
#pragma unroll
        for (int r = 0; r < NSEG; r++) {
            int c = tid + r * 256;
            int srow = c >> 2, kk = (c & 3) * 8;
            int srcrow = (MODE == 2) ? (n0 + srow) : ((srow >> 6) * 256 + n0 + (srow & 63));
            cp16(sB[s] + srow * 40 + kk, B + (size_t)srcrow * K + k0 + kk);
        }
    };

    wmma::fragment<wmma::accumulator, 16, 16, 16, float> acc[NSEG][MI][2];
#pragma unroll
    for (int g = 0; g < NSEG; g++)
#pragma unroll
        for (int i = 0; i < MI; i++)
#pragma unroll
            for (int j = 0; j < 2; j++) wmma::fill_fragment(acc[g][i][j], 0.0f);

    load_tile(0, 0); cp_commit();
    load_tile(1, 1); cp_commit();

    for (int kt = 0; kt < KT; kt++) {
        if (kt == KT - 1) cp_wait<0>(); else cp_wait<1>();
        __syncthreads();
        const int s = kt & 1;
#pragma unroll
        for (int kc = 0; kc < 32; kc += 16) {
            wmma::fragment<wmma::matrix_a, 16, 16, 16, __half, wmma::row_major> ah[MI], al[MI];
#pragma unroll
            for (int i = 0; i < MI; i++) {
                wmma::load_matrix_sync(ah[i], sAh[s] + (wm * 16 * MI + i * 16) * 40 + kc, 40);
                wmma::load_matrix_sync(al[i], sAl[s] + (wm * 16 * MI + i * 16) * 40 + kc, 40);
            }
#pragma unroll
            for (int g = 0; g < NSEG; g++) {
                wmma::fragment<wmma::matrix_b, 16, 16, 16, __half, wmma::col_major> b[2];
#pragma unroll
                for (int j = 0; j < 2; j++)
                    wmma::load_matrix_sync(b[j], sB[s] + (g * 64 + wn * 32 + j * 16) * 40 + kc, 40);
#pragma unroll
                for (int i = 0; i < MI; i++)
#pragma unroll
                    for (int j = 0; j < 2; j++) {
                        wmma::mma_sync(acc[g][i][j], ah[i], b[j], acc[g][i][j]);
                        wmma::mma_sync(acc[g][i][j], al[i], b[j], acc[g][i][j]);
                    }
            }
        }
        __syncthreads();
        if (kt + 2 < KT) { load_tile(kt & 1, kt + 2); cp_commit(); }
    }

    // ---------------- epilogue (smem reuse; mainloop data dead after final sync) ----------------
    float* wbuf = (float*)smem_raw;                 // 8 warps x NSEG x 320 floats
    float* sX = wbuf + 8 * NSEG * 320;
    constexpr int XW = (MODE == 1) ? 4 : 8;
    float* sW = sX + BM * XW;                       // 192 x 8

    if (MODE != 2) {
#pragma unroll
        for (int r = 0; r < (BM * XW + 255) / 256; r++) {
            int c = tid + r * 256;
            if (c < BM * XW) sX[c] = xw[(size_t)(m0 + (c / XW)) * XW + (c % XW)];
        }
#pragma unroll
        for (int r = 0; r < 6; r++) {
            int c = tid + r * 256;       // 1536 = 192*8
            int srow = c >> 3, k = c & 7;
            sW[c] = swg[(size_t)((srow >> 6) * 256 + n0 + (srow & 63)) * 8 + k];
        }
    }
    __syncthreads();

    float* wb = wbuf + wid * NSEG * 320;
    const int r_ = lane >> 1;
    const int c0_ = (lane & 1) * 8;

#pragma unroll
    for (int i = 0; i < MI; i++) {
#pragma unroll
        for (int j = 0; j < 2; j++) {
#pragma unroll
            for (int g = 0; g < NSEG; g++)
                wmma::store_matrix_sync(wb + g * 320, acc[g][i][j], 20, wmma::mem_row_major);
            __syncwarp();

            const int mloc = wm * 16 * MI + i * 16 + r_;
            const int m = m0 + mloc;
            const int nl0 = wn * 32 + j * 16 + c0_;   // local col in [0,64)
            const int nabs = n0 + nl0;

            __half oh8[8], ol8[8];

            if (MODE == 2) {
                float4 b0 = *(const float4*)&xw[nabs];
                float4 b1 = *(const float4*)&xw[nabs + 4];
                float bia[8] = {b0.x,b0.y,b0.z,b0.w,b1.x,b1.y,b1.z,b1.w};
                float ov[8];
#pragma unroll
                for (int cc = 0; cc < 8; cc++) {
                    float v = eluf_(wb[r_ * 20 + c0_ + cc] + bia[cc]);
                    ov[cc] = v;
                    split_fp16(v, oh8[cc], ol8[cc]);
                }
                if (Ofp) {
                    *(float4*)&Ofp[(size_t)m * 256 + nabs] = make_float4(ov[0],ov[1],ov[2],ov[3]);
                    *(float4*)&Ofp[(size_t)m * 256 + nabs + 4] = make_float4(ov[4],ov[5],ov[6],ov[7]);
                }
                if (Ohi) {
                    *(uint4*)&Ohi[(size_t)m * ldo + nabs] = *(uint4*)oh8;
                    *(uint4*)&Olo[(size_t)m * ldo + nabs] = *(uint4*)ol8;
                }
            } else {
                uint4 hv4 = *(const uint4*)&oldHi[(size_t)m * oldLd + nabs];
                uint4 lv4 = *(const uint4*)&oldLo[(size_t)m * oldLd + nabs];
                const __half* hvp = (const __half*)&hv4;
                const __half* lvp = (const __half*)&lv4;
                float xr[XW];
#pragma unroll
                for (int k = 0; k < XW; k++) xr[k] = sX[mloc * XW + k];
#pragma unroll
                for (int cc = 0; cc < 8; cc++) {
                    int nl = nl0 + cc;
                    const float* w0 = sW + (0 * 64 + nl) * 8;
                    const float* w1 = sW + (1 * 64 + nl) * 8;
                    const float* w2 = sW + (2 * 64 + nl) * 8;
                    float a0 = wb[0 * 320 + r_ * 20 + c0_ + cc];
                    float a1 = wb[1 * 320 + r_ * 20 + c0_ + cc];
                    float a2 = wb[2 * 320 + r_ * 20 + c0_ + cc];
                    float gi_r, gi_z, gi_n, rr, zz, nn;
                    if (MODE == 0) {
                        gi_r = w0[5]; gi_z = w1[5]; gi_n = w2[5];
#pragma unroll
                        for (int k = 0; k < 5; k++) {
                            gi_r += xr[k] * w0[k];
                            gi_z += xr[k] * w1[k];
                            gi_n += xr[k] * w2[k];
                        }
                        rr = sigmoidf_(gi_r + a0 + w0[6]);
                        zz = sigmoidf_(gi_z + a1 + w1[6]);
                        nn = tanhf(gi_n + rr * (a2 + w2[6]));
                    } else {
                        float a3 = wb[3 * 320 + r_ * 20 + c0_ + cc];
                        gi_r = w0[3]; gi_z = w1[3]; gi_n = w2[3];
#pragma unroll
                        for (int k = 0; k < 3; k++) {
                            gi_r += xr[k] * w0[k];
                            gi_z += xr[k] * w1[k];
                            gi_n += xr[k] * w2[k];
                        }
                        rr = sigmoidf_(gi_r + a0 + w0[4]);
                        zz = sigmoidf_(gi_z + a1 + w1[4]);
                        nn = tanhf(gi_n + a2 + rr * (a3 + w2[4]));
                    }
                    float hold = __half2float(hvp[cc]) + __half2float(lvp[cc]);
                    float hnew = (1.0f - zz) * nn + zz * hold;
                    split_fp16(hnew, oh8[cc], ol8[cc]);
                }
                *(uint4*)&Ohi[(size_t)m * ldo + nabs] = *(uint4*)oh8;
                *(uint4*)&Olo[(size_t)m * ldo + nabs] = *(uint4*)ol8;
            }
            __syncwarp();
        }
    }
}

// ---------------- entity max-pool ----------------
__global__ void pool_kernel(const __half* __restrict__ phi,
                            const __half* __restrict__ plo,
                            __half* __restrict__ xcat_hi,
                            __half* __restrict__ xcat_lo)
{
    int idx = blockIdx.x * blockDim.x + threadIdx.x;
    if (idx >= MA_ROWS * 32) return;
    int m = idx >> 5, c8 = (idx & 31) * 8;
    float v[8];
#pragma unroll
    for (int k = 0; k < 8; k++) v[k] = -1e30f;
#pragma unroll
    for (int e = 0; e < EE; e++) {
        size_t off = (size_t)(m * EE + e) * HH + c8;
        uint4 h4 = *(const uint4*)&phi[off];
        uint4 l4 = *(const uint4*)&plo[off];
        const __half* hp = (const __half*)&h4;
        const __half* lp = (const __half*)&l4;
#pragma unroll
        for (int k = 0; k < 8; k++)
            v[k] = fmaxf(v[k], __half2float(hp[k]) + __half2float(lp[k]));
    }
    __half h8[8], l8[8];
#pragma unroll
    for (int k = 0; k < 8; k++) split_fp16(v[k], h8[k], l8[k]);
    size_t xo = (size_t)m * 512 + c8;
    *(uint4*)&xcat_hi[xo] = *(uint4*)h8;
    *(uint4*)&xcat_lo[xo] = *(uint4*)l8;
}

// ---------------- head ----------------
__global__ void head_kernel(const float* __restrict__ t2,
                            const float* __restrict__ Wm2, const float* __restrict__ bm2,
                            float* __restrict__ out, int tstep)
{
    int warp = (blockIdx.x * blockDim.x + threadIdx.x) >> 5;
    int lane = threadIdx.x & 31;
    if (warp >= MA_ROWS) return;
    float s0 = 0.0f, s1 = 0.0f;
    for (int k = lane; k < HH; k += 32) {
        float x = t2[warp * HH + k];
        s0 += x * Wm2[k];
        s1 += x * Wm2[HH + k];
    }
#pragma unroll
    for (int off = 16; off; off >>= 1) {
        s0 += __shfl_xor_sync(0xffffffffu, s0, off);
        s1 += __shfl_xor_sync(0xffffffffu, s1, off);
    }
    if (lane == 0) {
        out[((size_t)tstep * MA_ROWS + warp) * 2 + 0] = tanhf(s0 + bm2[0]) * 0.05f;
        out[((size_t)tstep * MA_ROWS + warp) * 2 + 1] = tanhf(s1 + bm2[1]) * 0.05f;
    }
}

// ---------------- host launcher ----------------
extern "C" void kernel_launch(void* const* d_in, const int* in_sizes, int n_in,
                              void* d_out, int out_size)
{
    const float* obs    = (const float*)d_in[0];
    const float* phys   = (const float*)d_in[1];
    const float* goals  = (const float*)d_in[2];
    const float* mem_p  = (const float*)d_in[3];
    const float* mem_a  = (const float*)d_in[4];
    const float* Wih_p  = (const float*)d_in[5];
    const float* Whh_p  = (const float*)d_in[6];
    const float* bih_p  = (const float*)d_in[7];
    const float* bhh_p  = (const float*)d_in[8];
    const float* Wfc_p  = (const float*)d_in[9];
    const float* bfc_p  = (const float*)d_in[10];
    const float* Wih_a  = (const float*)d_in[11];
    const float* Whh_a  = (const float*)d_in[12];
    const float* bih_a  = (const float*)d_in[13];
    const float* bhh_a  = (const float*)d_in[14];
    const float* Wfc_a  = (const float*)d_in[15];
    const float* bfc_a  = (const float*)d_in[16];
    const float* Wm1    = (const float*)d_in[17];
    const float* bm1    = (const float*)d_in[18];
    const float* Wm2    = (const float*)d_in[19];
    const float* bm2    = (const float*)d_in[20];
    float* out = (float*)d_out;

    void* p;
    __half *h_hi[2], *h_lo[2], *xc_hi[2], *xc_lo[2];
    cudaGetSymbolAddress(&p, g_h_hi);    h_hi[0] = (__half*)p; h_hi[1] = h_hi[0] + (size_t)MP_ROWS*HH;
    cudaGetSymbolAddress(&p, g_h_lo);    h_lo[0] = (__half*)p; h_lo[1] = h_lo[0] + (size_t)MP_ROWS*HH;
    cudaGetSymbolAddress(&p, g_xcat_hi); xc_hi[0] = (__half*)p; xc_hi[1] = xc_hi[0] + (size_t)MA_ROWS*512;
    cudaGetSymbolAddress(&p, g_xcat_lo); xc_lo[0] = (__half*)p; xc_lo[1] = xc_lo[0] + (size_t)MA_ROWS*512;
    cudaGetSymbolAddress(&p, g_proc_hi); __half* proc_hi = (__half*)p;
    cudaGetSymbolAddress(&p, g_proc_lo); __half* proc_lo = (__half*)p;
    cudaGetSymbolAddress(&p, g_t1_hi);   __half* t1_hi = (__half*)p;
    cudaGetSymbolAddress(&p, g_t1_lo);   __half* t1_lo = (__half*)p;
    cudaGetSymbolAddress(&p, g_t2);      float* t2 = (float*)p;
    cudaGetSymbolAddress(&p, g_xp8);     float* xp8 = (float*)p;
    cudaGetSymbolAddress(&p, g_xa4);     float* xa4 = (float*)p;
    cudaGetSymbolAddress(&p, g_Wp8);     float* Wp8 = (float*)p;
    cudaGetSymbolAddress(&p, g_Wa8);     float* Wa8 = (float*)p;
    cudaGetSymbolAddress(&p, g_Whhp);    __half* Whhp = (__half*)p;
    cudaGetSymbolAddress(&p, g_Wfcp);    __half* Wfcp = (__half*)p;
    cudaGetSymbolAddress(&p, g_Wcat);    __half* Wcat = (__half*)p;
    cudaGetSymbolAddress(&p, g_Wfca);    __half* Wfca = (__half*)p;
    cudaGetSymbolAddress(&p, g_Wm1);     __half* Wm1h = (__half*)p;

    // dynamic smem: mainloop = (4*BM*40 + 2*NSEG*64*40)*2 bytes
    const int SM_0_128 = (4*128*40 + 2*3*64*40) * 2;   // 71680
    const int SM_1_64  = (4*64*40  + 2*4*64*40) * 2;   // 61440
    const int SM_2_128 = (4*128*40 + 2*1*64*40) * 2;   // 51200
    const int SM_2_64  = (4*64*40  + 2*1*64*40) * 2;   // 30720
    cudaFuncSetAttribute((const void*)fused_kernel<0,128>, cudaFuncAttributeMaxDynamicSharedMemorySize, SM_0_128);
    cudaFuncSetAttribute((const void*)fused_kernel<1,64>,  cudaFuncAttributeMaxDynamicSharedMemorySize, SM_1_64);
    cudaFuncSetAttribute((const void*)fused_kernel<2,128>, cudaFuncAttributeMaxDynamicSharedMemorySize, SM_2_128);
    cudaFuncSetAttribute((const void*)fused_kernel<2,64>,  cudaFuncAttributeMaxDynamicSharedMemorySize, SM_2_64);

    cudaStream_t s = 0;

    // ---- prep ----
    split_kernel<<<(MP_ROWS*HH + 255)/256, 256, 0, s>>>(mem_p, h_hi[0], h_lo[0], MP_ROWS*HH);
    split_strided_kernel<<<(MA_ROWS*HH + 255)/256, 256, 0, s>>>(mem_a, xc_hi[0] + 256, xc_lo[0] + 256, MA_ROWS, HH, 512);
    conv_kernel<<<(G3H*HH + 255)/256, 256, 0, s>>>(Whh_p, Whhp, G3H*HH);
    conv_kernel<<<(HH*HH + 255)/256, 256, 0, s>>>(Wfc_p, Wfcp, HH*HH);
    conv_kernel<<<(HH*HH + 255)/256, 256, 0, s>>>(Wfc_a, Wfca, HH*HH);
    conv_kernel<<<(HH*HH + 255)/256, 256, 0, s>>>(Wm1, Wm1h, HH*HH);
    build_wcat_kernel<<<(1024*512 + 255)/256, 256, 0, s>>>(Wih_a, Whh_a, Wcat);
    prep_xp_kernel<<<(MP_ROWS + 255)/256, 256, 0, s>>>(obs, phys, xp8);
    prep_wp8_kernel<<<(G3H + 255)/256, 256, 0, s>>>(Wih_p, bih_p, bhh_p, Wp8);
    prep_xa_kernel<<<(MA_ROWS + 255)/256, 256, 0, s>>>(goals, xa4);
    prep_wa8_kernel<<<(G3H + 255)/256, 256, 0, s>>>(Wih_a, bih_a, bhh_a, Wa8);

    // ---- recurrence ----
    int cur = 0;
    for (int t = 0; t < TT; t++) {
        int nxt = cur ^ 1;
        // physical GRU fused
        fused_kernel<0,128><<<dim3(MP_ROWS/128, 4), 256, SM_0_128, s>>>(
            h_hi[cur], h_lo[cur], HH, Whhp, xp8, Wp8,
            h_hi[cur], h_lo[cur], HH,
            h_hi[nxt], h_lo[nxt], HH, nullptr);
        // fc_p + ELU -> proc
        fused_kernel<2,128><<<dim3(MP_ROWS/128, 4), 256, SM_2_128, s>>>(
            h_hi[nxt], h_lo[nxt], HH, Wfcp, bfc_p, nullptr,
            nullptr, nullptr, 0,
            proc_hi, proc_lo, HH, nullptr);
        // pool -> feat into xcat[cur][0:256)
        pool_kernel<<<(MA_ROWS*32 + 255)/256, 256, 0, s>>>(proc_hi, proc_lo, xc_hi[cur], xc_lo[cur]);
        // action GRU fused
        fused_kernel<1,64><<<dim3(MA_ROWS/64, 4), 256, SM_1_64, s>>>(
            xc_hi[cur], xc_lo[cur], 512, Wcat, xa4, Wa8,
            xc_hi[cur] + 256, xc_lo[cur] + 256, 512,
            xc_hi[nxt] + 256, xc_lo[nxt] + 256, 512, nullptr);
        // fc_a + ELU -> t1
        fused_kernel<2,64><<<dim3(MA_ROWS/64, 4), 256, SM_2_64, s>>>(
            xc_hi[nxt] + 256, xc_lo[nxt] + 256, 512, Wfca, bfc_a, nullptr,
            nullptr, nullptr, 0,
            t1_hi, t1_lo, HH, nullptr);
        // m1 + ELU -> t2 (fp32)
        fused_kernel<2,64><<<dim3(MA_ROWS/64, 4), 256, SM_2_64, s>>>(
            t1_hi, t1_lo, HH, Wm1h, bm1, nullptr,
            nullptr, nullptr, 0,
            nullptr, nullptr, 0, t2);
        head_kernel<<<(MA_ROWS*32 + 255)/256, 256, 0, s>>>(t2, Wm2, bm2, out, t);
        cur = nxt;
    }
}

// round 6
// speedup vs baseline: 3.6858x; 1.0991x over previous
#include <cuda_runtime.h>
#include <cuda_fp16.h>
#include <mma.h>
#include <math.h>
#include <stdint.h>

using namespace nvcuda;

#define BB 512
#define AA 4
#define EE 10
#define HH 256
#define TT 10
#define MP_ROWS (BB*AA*EE)   // 20480
#define MA_ROWS (BB*AA)      // 2048
#define G3H (3*HH)           // 768

// ---------------- scratch ----------------
__device__ __half g_h_hi[2][MP_ROWS * HH];
__device__ __half g_h_lo[2][MP_ROWS * HH];
__device__ __half g_xcat_hi[2][MA_ROWS * 512];   // [feat | ma]
__device__ __half g_xcat_lo[2][MA_ROWS * 512];
__device__ __half g_proc_hi[MP_ROWS * HH];
__device__ __half g_proc_lo[MP_ROWS * HH];
__device__ __half g_t1_hi[MA_ROWS * HH];
__device__ __half g_t1_lo[MA_ROWS * HH];
__device__ float g_t2[MA_ROWS * HH];
__device__ float g_xp8[MP_ROWS * 8];     // [ob0,ob1,ph0,ph1,ph2,0,0,0]
__device__ float g_xa4[MA_ROWS * 4];     // [g0,g1,g2,0]
__device__ float g_Wp8[G3H * 8];         // [w0..w4, bih, bhh, 0]
__device__ float g_Wa8[G3H * 8];         // [wg0..2, bih, bhh, 0,0,0]
__device__ __half g_Whhp[G3H * HH];
__device__ __half g_Wfcp[HH * HH];
__device__ __half g_Wcat[1024 * 512];
__device__ __half g_Wfca[HH * HH];
__device__ __half g_Wm1[HH * HH];

// ---------------- helpers ----------------
__device__ __forceinline__ float sigmoidf_(float x) { return 1.0f / (1.0f + __expf(-x)); }
__device__ __forceinline__ float eluf_(float x) { return x > 0.0f ? x : expm1f(x); }
__device__ __forceinline__ void split_fp16(float x, __half& hi, __half& lo) {
    hi = __float2half_rn(x);
    lo = __float2half_rn(x - __half2float(hi));
}
__device__ __forceinline__ void cp16(void* dst, const void* src) {
    unsigned d = (unsigned)__cvta_generic_to_shared(dst);
    asm volatile("cp.async.cg.shared.global [%0], [%1], 16;\n" :: "r"(d), "l"(src));
}
__device__ __forceinline__ void cp_commit() { asm volatile("cp.async.commit_group;\n" ::); }
template<int N> __device__ __forceinline__ void cp_wait() { asm volatile("cp.async.wait_group %0;\n" :: "n"(N)); }

// ---------------- prep kernels ----------------
__global__ void prep_xp_kernel(const float* __restrict__ obs, const float* __restrict__ phys,
                               float* __restrict__ xp8)
{
    int r = blockIdx.x * blockDim.x + threadIdx.x;
    if (r >= MP_ROWS) return;
    int b = r / (AA*EE);
    int e = r % EE;
    float* o = xp8 + r * 8;
    o[0] = obs[r*2+0]; o[1] = obs[r*2+1];
    const float* ph = phys + (b * EE + e) * 3;
    o[2] = ph[0]; o[3] = ph[1]; o[4] = ph[2];
    o[5] = 0.f; o[6] = 0.f; o[7] = 0.f;
}
__global__ void prep_wp8_kernel(const float* __restrict__ Wih, const float* __restrict__ bih,
                                const float* __restrict__ bhh, float* __restrict__ Wp8)
{
    int r = blockIdx.x * blockDim.x + threadIdx.x;
    if (r >= G3H) return;
    float* o = Wp8 + r * 8;
#pragma unroll
    for (int k = 0; k < 5; k++) o[k] = Wih[r*5+k];
    o[5] = bih[r]; o[6] = bhh[r]; o[7] = 0.f;
}
__global__ void prep_xa_kernel(const float* __restrict__ goals, float* __restrict__ xa4)
{
    int m = blockIdx.x * blockDim.x + threadIdx.x;
    if (m >= MA_ROWS) return;
    float* o = xa4 + m * 4;
    o[0] = goals[m*3+0]; o[1] = goals[m*3+1]; o[2] = goals[m*3+2]; o[3] = 0.f;
}
__global__ void prep_wa8_kernel(const float* __restrict__ Wih, const float* __restrict__ bih,
                                const float* __restrict__ bhh, float* __restrict__ Wa8)
{
    int r = blockIdx.x * blockDim.x + threadIdx.x;
    if (r >= G3H) return;
    float* o = Wa8 + r * 8;
    o[0] = Wih[r*259+256]; o[1] = Wih[r*259+257]; o[2] = Wih[r*259+258];
    o[3] = bih[r]; o[4] = bhh[r]; o[5] = 0.f; o[6] = 0.f; o[7] = 0.f;
}
__global__ void split_kernel(const float* __restrict__ src,
                             __half* __restrict__ hi, __half* __restrict__ lo, int n)
{
    int i = blockIdx.x * blockDim.x + threadIdx.x;
    if (i >= n) return;
    split_fp16(src[i], hi[i], lo[i]);
}
__global__ void split_strided_kernel(const float* __restrict__ src,
                                     __half* __restrict__ hi, __half* __restrict__ lo,
                                     int rows, int cols, int ldo)
{
    int i = blockIdx.x * blockDim.x + threadIdx.x;
    if (i >= rows * cols) return;
    int r = i / cols, c = i - r * cols;
    split_fp16(src[i], hi[r * ldo + c], lo[r * ldo + c]);
}
__global__ void conv_kernel(const float* __restrict__ src, __half* __restrict__ dst, int n)
{
    int i = blockIdx.x * blockDim.x + threadIdx.x;
    if (i >= n) return;
    dst[i] = __float2half_rn(src[i]);
}
// Wcat [1024, 512]: rows g*256+n. g=0:[Wih_r|Whh_r] g=1:[Wih_z|Whh_z] g=2:[Wih_n|0] g=3:[0|Whh_n]
__global__ void build_wcat_kernel(const float* __restrict__ Wih,  // [768,259]
                                  const float* __restrict__ Whh,  // [768,256]
                                  __half* __restrict__ Wcat)
{
    int idx = blockIdx.x * blockDim.x + threadIdx.x;
    if (idx >= 1024 * 512) return;
    int row = idx >> 9, col = idx & 511;
    int g = row >> 8, n = row & 255;
    float v = 0.0f;
    if (g < 2) {
        v = (col < 256) ? Wih[(g * 256 + n) * 259 + col] : Whh[(g * 256 + n) * 256 + (col - 256)];
    } else if (g == 2) {
        if (col < 256) v = Wih[(512 + n) * 259 + col];
    } else {
        if (col >= 256) v = Whh[(512 + n) * 256 + (col - 256)];
    }
    Wcat[idx] = __float2half_rn(v);
}

// ---------------- fused fp16 2-pass GEMM kernel ----------------
// MODE 0: physical GRU  (NSEG=3, K=256), MODE 1: action GRU (NSEG=4, K=512),
// MODE 2: ELU layer     (NSEG=1, K=256).
template<int MODE, int BM>
__global__ __launch_bounds__(256) void fused_kernel(
    const __half* __restrict__ Ahi, const __half* __restrict__ Alo, int lda,
    const __half* __restrict__ B,
    const float* __restrict__ xw,     // xp8 / xa4 / bias
    const float* __restrict__ swg,    // Wp8 / Wa8 / unused
    const __half* __restrict__ oldHi, const __half* __restrict__ oldLo, int oldLd,
    __half* __restrict__ Ohi, __half* __restrict__ Olo, int ldo,
    float* __restrict__ Ofp)
{
    constexpr int NSEG = (MODE == 0) ? 3 : ((MODE == 1) ? 4 : 1);
    constexpr int K = (MODE == 1) ? 512 : 256;
    constexpr int KT = K / 32;
    constexpr int MI = BM / 64;
    constexpr int AITER = BM / 32;
    constexpr int AHS = BM * 40;
    constexpr int BHS = NSEG * 64 * 40;

    extern __shared__ __align__(16) char smem_raw[];
    __half* sm = (__half*)smem_raw;
    __half* sAh[2] = { sm,           sm + AHS };
    __half* sAl[2] = { sm + 2*AHS,   sm + 3*AHS };
    __half* sB[2]  = { sm + 4*AHS,   sm + 4*AHS + BHS };

    const int m0 = blockIdx.x * BM;
    const int n0 = blockIdx.y * 64;
    const int tid = threadIdx.x;
    const int wid = tid >> 5;
    const int lane = tid & 31;
    const int wm = wid >> 1, wn = wid & 1;

    auto load_tile = [&](int s, int kt) {
        const int k0 = kt * 32;
#pragma unroll
        for (int r = 0; r < AITER; r++) {
            int c = tid + r * 256;
            int half_ = (c >= BM * 4) ? 1 : 0;
            int c2 = c - half_ * BM * 4;
            int row = c2 >> 2, kk = (c2 & 3) * 8;
            const __half* src = (half_ ? Alo : Ahi) + (size_t)(m0 + row) * lda + k0 + kk;
            cp16((half_ ? sAl : sAh)[s] + row * 40 + kk, src);
        }
#pragma unroll
        for (int r = 0; r < NSEG; r++) {
            int c = tid + r * 256;
            int srow = c >> 2, kk = (c & 3) * 8;
            int srcrow = (MODE == 2) ? (n0 + srow) : ((srow >> 6) * 256 + n0 + (srow & 63));
            cp16(sB[s] + srow * 40 + kk, B + (size_t)srcrow * K + k0 + kk);
        }
    };

    wmma::fragment<wmma::accumulator, 16, 16, 16, float> acc[NSEG][MI][2];
#pragma unroll
    for (int g = 0; g < NSEG; g++)
#pragma unroll
        for (int i = 0; i < MI; i++)
#pragma unroll
            for (int j = 0; j < 2; j++) wmma::fill_fragment(acc[g][i][j], 0.0f);

    load_tile(0, 0); cp_commit();
    load_tile(1, 1); cp_commit();

    for (int kt = 0; kt < KT; kt++) {
        if (kt == KT - 1) cp_wait<0>(); else cp_wait<1>();
        __syncthreads();
        const int s = kt & 1;
#pragma unroll
        for (int kc = 0; kc < 32; kc += 16) {
            wmma::fragment<wmma::matrix_a, 16, 16, 16, __half, wmma::row_major> ah[MI], al[MI];
#pragma unroll
            for (int i = 0; i < MI; i++) {
                wmma::load_matrix_sync(ah[i], sAh[s] + (wm * 16 * MI + i * 16) * 40 + kc, 40);
                wmma::load_matrix_sync(al[i], sAl[s] + (wm * 16 * MI + i * 16) * 40 + kc, 40);
            }
#pragma unroll
            for (int g = 0; g < NSEG; g++) {
                wmma::fragment<wmma::matrix_b, 16, 16, 16, __half, wmma::col_major> b[2];
#pragma unroll
                for (int j = 0; j < 2; j++)
                    wmma::load_matrix_sync(b[j], sB[s] + (g * 64 + wn * 32 + j * 16) * 40 + kc, 40);
#pragma unroll
                for (int i = 0; i < MI; i++)
#pragma unroll
                    for (int j = 0; j < 2; j++) {
                        wmma::mma_sync(acc[g][i][j], ah[i], b[j], acc[g][i][j]);
                        wmma::mma_sync(acc[g][i][j], al[i], b[j], acc[g][i][j]);
                    }
            }
        }
        __syncthreads();
        if (kt + 2 < KT) { load_tile(kt & 1, kt + 2); cp_commit(); }
    }

    // ---------------- epilogue ----------------
    float* wbuf = (float*)smem_raw;
    float* sX = wbuf + 8 * NSEG * 320;
    constexpr int XW = (MODE == 1) ? 4 : 8;
    float* sW = sX + BM * XW;

    if (MODE != 2) {
#pragma unroll
        for (int r = 0; r < (BM * XW + 255) / 256; r++) {
            int c = tid + r * 256;
            if (c < BM * XW) sX[c] = xw[(size_t)(m0 + (c / XW)) * XW + (c % XW)];
        }
#pragma unroll
        for (int r = 0; r < 6; r++) {
            int c = tid + r * 256;
            int srow = c >> 3, k = c & 7;
            sW[c] = swg[(size_t)((srow >> 6) * 256 + n0 + (srow & 63)) * 8 + k];
        }
    }
    __syncthreads();

    float* wb = wbuf + wid * NSEG * 320;
    const int r_ = lane >> 1;
    const int c0_ = (lane & 1) * 8;

#pragma unroll
    for (int i = 0; i < MI; i++) {
#pragma unroll
        for (int j = 0; j < 2; j++) {
#pragma unroll
            for (int g = 0; g < NSEG; g++)
                wmma::store_matrix_sync(wb + g * 320, acc[g][i][j], 20, wmma::mem_row_major);
            __syncwarp();

            const int mloc = wm * 16 * MI + i * 16 + r_;
            const int m = m0 + mloc;
            const int nl0 = wn * 32 + j * 16 + c0_;
            const int nabs = n0 + nl0;

            __half oh8[8], ol8[8];

            if (MODE == 2) {
                float4 b0 = *(const float4*)&xw[nabs];
                float4 b1 = *(const float4*)&xw[nabs + 4];
                float bia[8] = {b0.x,b0.y,b0.z,b0.w,b1.x,b1.y,b1.z,b1.w};
                float ov[8];
#pragma unroll
                for (int cc = 0; cc < 8; cc++) {
                    float v = eluf_(wb[r_ * 20 + c0_ + cc] + bia[cc]);
                    ov[cc] = v;
                    split_fp16(v, oh8[cc], ol8[cc]);
                }
                if (Ofp) {
                    *(float4*)&Ofp[(size_t)m * 256 + nabs] = make_float4(ov[0],ov[1],ov[2],ov[3]);
                    *(float4*)&Ofp[(size_t)m * 256 + nabs + 4] = make_float4(ov[4],ov[5],ov[6],ov[7]);
                }
                if (Ohi) {
                    *(uint4*)&Ohi[(size_t)m * ldo + nabs] = *(uint4*)oh8;
                    *(uint4*)&Olo[(size_t)m * ldo + nabs] = *(uint4*)ol8;
                }
            } else {
                uint4 hv4 = *(const uint4*)&oldHi[(size_t)m * oldLd + nabs];
                uint4 lv4 = *(const uint4*)&oldLo[(size_t)m * oldLd + nabs];
                const __half* hvp = (const __half*)&hv4;
                const __half* lvp = (const __half*)&lv4;
                float xr[XW];
#pragma unroll
                for (int k = 0; k < XW; k++) xr[k] = sX[mloc * XW + k];
#pragma unroll
                for (int cc = 0; cc < 8; cc++) {
                    int nl = nl0 + cc;
                    const float* w0 = sW + (0 * 64 + nl) * 8;
                    const float* w1 = sW + (1 * 64 + nl) * 8;
                    const float* w2 = sW + (2 * 64 + nl) * 8;
                    float a0 = wb[0 * 320 + r_ * 20 + c0_ + cc];
                    float a1 = wb[1 * 320 + r_ * 20 + c0_ + cc];
                    float a2 = wb[2 * 320 + r_ * 20 + c0_ + cc];
                    float gi_r, gi_z, gi_n, rr, zz, nn;
                    if (MODE == 0) {
                        gi_r = w0[5]; gi_z = w1[5]; gi_n = w2[5];
#pragma unroll
                        for (int k = 0; k < 5; k++) {
                            gi_r += xr[k] * w0[k];
                            gi_z += xr[k] * w1[k];
                            gi_n += xr[k] * w2[k];
                        }
                        rr = sigmoidf_(gi_r + a0 + w0[6]);
                        zz = sigmoidf_(gi_z + a1 + w1[6]);
                        nn = tanhf(gi_n + rr * (a2 + w2[6]));
                    } else {
                        float a3 = wb[3 * 320 + r_ * 20 + c0_ + cc];
                        gi_r = w0[3]; gi_z = w1[3]; gi_n = w2[3];
#pragma unroll
                        for (int k = 0; k < 3; k++) {
                            gi_r += xr[k] * w0[k];
                            gi_z += xr[k] * w1[k];
                            gi_n += xr[k] * w2[k];
                        }
                        rr = sigmoidf_(gi_r + a0 + w0[4]);
                        zz = sigmoidf_(gi_z + a1 + w1[4]);
                        nn = tanhf(gi_n + a2 + rr * (a3 + w2[4]));
                    }
                    float hold = __half2float(hvp[cc]) + __half2float(lvp[cc]);
                    float hnew = (1.0f - zz) * nn + zz * hold;
                    split_fp16(hnew, oh8[cc], ol8[cc]);
                }
                *(uint4*)&Ohi[(size_t)m * ldo + nabs] = *(uint4*)oh8;
                *(uint4*)&Olo[(size_t)m * ldo + nabs] = *(uint4*)ol8;
            }
            __syncwarp();
        }
    }
}

// ---------------- entity max-pool ----------------
__global__ void pool_kernel(const __half* __restrict__ phi,
                            const __half* __restrict__ plo,
                            __half* __restrict__ xcat_hi,
                            __half* __restrict__ xcat_lo)
{
    int idx = blockIdx.x * blockDim.x + threadIdx.x;
    if (idx >= MA_ROWS * 32) return;
    int m = idx >> 5, c8 = (idx & 31) * 8;
    float v[8];
#pragma unroll
    for (int k = 0; k < 8; k++) v[k] = -1e30f;
#pragma unroll
    for (int e = 0; e < EE; e++) {
        size_t off = (size_t)(m * EE + e) * HH + c8;
        uint4 h4 = *(const uint4*)&phi[off];
        uint4 l4 = *(const uint4*)&plo[off];
        const __half* hp = (const __half*)&h4;
        const __half* lp = (const __half*)&l4;
#pragma unroll
        for (int k = 0; k < 8; k++)
            v[k] = fmaxf(v[k], __half2float(hp[k]) + __half2float(lp[k]));
    }
    __half h8[8], l8[8];
#pragma unroll
    for (int k = 0; k < 8; k++) split_fp16(v[k], h8[k], l8[k]);
    size_t xo = (size_t)m * 512 + c8;
    *(uint4*)&xcat_hi[xo] = *(uint4*)h8;
    *(uint4*)&xcat_lo[xo] = *(uint4*)l8;
}

// ---------------- head ----------------
__global__ void head_kernel(const float* __restrict__ t2,
                            const float* __restrict__ Wm2, const float* __restrict__ bm2,
                            float* __restrict__ out, int tstep)
{
    int warp = (blockIdx.x * blockDim.x + threadIdx.x) >> 5;
    int lane = threadIdx.x & 31;
    if (warp >= MA_ROWS) return;
    float s0 = 0.0f, s1 = 0.0f;
    for (int k = lane; k < HH; k += 32) {
        float x = t2[warp * HH + k];
        s0 += x * Wm2[k];
        s1 += x * Wm2[HH + k];
    }
#pragma unroll
    for (int off = 16; off; off >>= 1) {
        s0 += __shfl_xor_sync(0xffffffffu, s0, off);
        s1 += __shfl_xor_sync(0xffffffffu, s1, off);
    }
    if (lane == 0) {
        out[((size_t)tstep * MA_ROWS + warp) * 2 + 0] = tanhf(s0 + bm2[0]) * 0.05f;
        out[((size_t)tstep * MA_ROWS + warp) * 2 + 1] = tanhf(s1 + bm2[1]) * 0.05f;
    }
}

// ---------------- host launcher ----------------
extern "C" void kernel_launch(void* const* d_in, const int* in_sizes, int n_in,
                              void* d_out, int out_size)
{
    const float* obs    = (const float*)d_in[0];
    const float* phys   = (const float*)d_in[1];
    const float* goals  = (const float*)d_in[2];
    const float* mem_p  = (const float*)d_in[3];
    const float* mem_a  = (const float*)d_in[4];
    const float* Wih_p  = (const float*)d_in[5];
    const float* Whh_p  = (const float*)d_in[6];
    const float* bih_p  = (const float*)d_in[7];
    const float* bhh_p  = (const float*)d_in[8];
    const float* Wfc_p  = (const float*)d_in[9];
    const float* bfc_p  = (const float*)d_in[10];
    const float* Wih_a  = (const float*)d_in[11];
    const float* Whh_a  = (const float*)d_in[12];
    const float* bih_a  = (const float*)d_in[13];
    const float* bhh_a  = (const float*)d_in[14];
    const float* Wfc_a  = (const float*)d_in[15];
    const float* bfc_a  = (const float*)d_in[16];
    const float* Wm1    = (const float*)d_in[17];
    const float* bm1    = (const float*)d_in[18];
    const float* Wm2    = (const float*)d_in[19];
    const float* bm2    = (const float*)d_in[20];
    float* out = (float*)d_out;

    void* p;
    __half *h_hi[2], *h_lo[2], *xc_hi[2], *xc_lo[2];
    cudaGetSymbolAddress(&p, g_h_hi);    h_hi[0] = (__half*)p; h_hi[1] = h_hi[0] + (size_t)MP_ROWS*HH;
    cudaGetSymbolAddress(&p, g_h_lo);    h_lo[0] = (__half*)p; h_lo[1] = h_lo[0] + (size_t)MP_ROWS*HH;
    cudaGetSymbolAddress(&p, g_xcat_hi); xc_hi[0] = (__half*)p; xc_hi[1] = xc_hi[0] + (size_t)MA_ROWS*512;
    cudaGetSymbolAddress(&p, g_xcat_lo); xc_lo[0] = (__half*)p; xc_lo[1] = xc_lo[0] + (size_t)MA_ROWS*512;
    cudaGetSymbolAddress(&p, g_proc_hi); __half* proc_hi = (__half*)p;
    cudaGetSymbolAddress(&p, g_proc_lo); __half* proc_lo = (__half*)p;
    cudaGetSymbolAddress(&p, g_t1_hi);   __half* t1_hi = (__half*)p;
    cudaGetSymbolAddress(&p, g_t1_lo);   __half* t1_lo = (__half*)p;
    cudaGetSymbolAddress(&p, g_t2);      float* t2 = (float*)p;
    cudaGetSymbolAddress(&p, g_xp8);     float* xp8 = (float*)p;
    cudaGetSymbolAddress(&p, g_xa4);     float* xa4 = (float*)p;
    cudaGetSymbolAddress(&p, g_Wp8);     float* Wp8 = (float*)p;
    cudaGetSymbolAddress(&p, g_Wa8);     float* Wa8 = (float*)p;
    cudaGetSymbolAddress(&p, g_Whhp);    __half* Whhp = (__half*)p;
    cudaGetSymbolAddress(&p, g_Wfcp);    __half* Wfcp = (__half*)p;
    cudaGetSymbolAddress(&p, g_Wcat);    __half* Wcat = (__half*)p;
    cudaGetSymbolAddress(&p, g_Wfca);    __half* Wfca = (__half*)p;
    cudaGetSymbolAddress(&p, g_Wm1);     __half* Wm1h = (__half*)p;

    const int SM_0_128 = (4*128*40 + 2*3*64*40) * 2;   // 71680
    const int SM_1_64  = (4*64*40  + 2*4*64*40) * 2;   // 61440
    const int SM_2_128 = (4*128*40 + 2*1*64*40) * 2;   // 51200
    const int SM_2_64  = (4*64*40  + 2*1*64*40) * 2;   // 30720
    cudaFuncSetAttribute((const void*)fused_kernel<0,128>, cudaFuncAttributeMaxDynamicSharedMemorySize, SM_0_128);
    cudaFuncSetAttribute((const void*)fused_kernel<1,64>,  cudaFuncAttributeMaxDynamicSharedMemorySize, SM_1_64);
    cudaFuncSetAttribute((const void*)fused_kernel<2,128>, cudaFuncAttributeMaxDynamicSharedMemorySize, SM_2_128);
    cudaFuncSetAttribute((const void*)fused_kernel<2,64>,  cudaFuncAttributeMaxDynamicSharedMemorySize, SM_2_64);

    // ---- one-time stream/event setup (resources reused; identical work every call) ----
    static cudaStream_t sA = nullptr;
    static cudaEvent_t evFork = nullptr, evJoin = nullptr;
    static cudaEvent_t evP[TT], evA[TT];
    if (sA == nullptr) {
        cudaStreamCreateWithFlags(&sA, cudaStreamNonBlocking);
        cudaEventCreateWithFlags(&evFork, cudaEventDisableTiming);
        cudaEventCreateWithFlags(&evJoin, cudaEventDisableTiming);
        for (int i = 0; i < TT; i++) {
            cudaEventCreateWithFlags(&evP[i], cudaEventDisableTiming);
            cudaEventCreateWithFlags(&evA[i], cudaEventDisableTiming);
        }
    }

    cudaStream_t s0 = 0;

    // ---- prep (stream 0) ----
    split_kernel<<<(MP_ROWS*HH + 255)/256, 256, 0, s0>>>(mem_p, h_hi[0], h_lo[0], MP_ROWS*HH);
    split_strided_kernel<<<(MA_ROWS*HH + 255)/256, 256, 0, s0>>>(mem_a, xc_hi[0] + 256, xc_lo[0] + 256, MA_ROWS, HH, 512);
    conv_kernel<<<(G3H*HH + 255)/256, 256, 0, s0>>>(Whh_p, Whhp, G3H*HH);
    conv_kernel<<<(HH*HH + 255)/256, 256, 0, s0>>>(Wfc_p, Wfcp, HH*HH);
    conv_kernel<<<(HH*HH + 255)/256, 256, 0, s0>>>(Wfc_a, Wfca, HH*HH);
    conv_kernel<<<(HH*HH + 255)/256, 256, 0, s0>>>(Wm1, Wm1h, HH*HH);
    build_wcat_kernel<<<(1024*512 + 255)/256, 256, 0, s0>>>(Wih_a, Whh_a, Wcat);
    prep_xp_kernel<<<(MP_ROWS + 255)/256, 256, 0, s0>>>(obs, phys, xp8);
    prep_wp8_kernel<<<(G3H + 255)/256, 256, 0, s0>>>(Wih_p, bih_p, bhh_p, Wp8);
    prep_xa_kernel<<<(MA_ROWS + 255)/256, 256, 0, s0>>>(goals, xa4);
    prep_wa8_kernel<<<(G3H + 255)/256, 256, 0, s0>>>(Wih_a, bih_a, bhh_a, Wa8);

    // fork the action stream off stream 0 (after prep)
    cudaEventRecord(evFork, s0);
    cudaStreamWaitEvent(sA, evFork, 0);

    // ---- recurrence ----
    // Stream 0 (physical chain): gru_p(t) -> fc_p(t) -> pool(t), runs ahead.
    // Stream A (action chain):   waits pool(t), then gru_a -> fc_a -> m1 -> head.
    // WAR: pool(t) overwrites xcat[t%2] feat cols read by gru_a(t-2) -> wait evA[t-2].
    int cur = 0;
    for (int t = 0; t < TT; t++) {
        int nxt = cur ^ 1;
        // physical GRU fused
        fused_kernel<0,128><<<dim3(MP_ROWS/128, 4), 256, SM_0_128, s0>>>(
            h_hi[cur], h_lo[cur], HH, Whhp, xp8, Wp8,
            h_hi[cur], h_lo[cur], HH,
            h_hi[nxt], h_lo[nxt], HH, nullptr);
        // fc_p + ELU -> proc
        fused_kernel<2,128><<<dim3(MP_ROWS/128, 4), 256, SM_2_128, s0>>>(
            h_hi[nxt], h_lo[nxt], HH, Wfcp, bfc_p, nullptr,
            nullptr, nullptr, 0,
            proc_hi, proc_lo, HH, nullptr);
        // pool -> feat into xcat[cur][0:256)  (guard WAR vs gru_a(t-2))
        if (t >= 2) cudaStreamWaitEvent(s0, evA[t - 2], 0);
        pool_kernel<<<(MA_ROWS*32 + 255)/256, 256, 0, s0>>>(proc_hi, proc_lo, xc_hi[cur], xc_lo[cur]);
        cudaEventRecord(evP[t], s0);

        // ---- action chain on stream A ----
        cudaStreamWaitEvent(sA, evP[t], 0);
        fused_kernel<1,64><<<dim3(MA_ROWS/64, 4), 256, SM_1_64, sA>>>(
            xc_hi[cur], xc_lo[cur], 512, Wcat, xa4, Wa8,
            xc_hi[cur] + 256, xc_lo[cur] + 256, 512,
            xc_hi[nxt] + 256, xc_lo[nxt] + 256, 512, nullptr);
        cudaEventRecord(evA[t], sA);
        fused_kernel<2,64><<<dim3(MA_ROWS/64, 4), 256, SM_2_64, sA>>>(
            xc_hi[nxt] + 256, xc_lo[nxt] + 256, 512, Wfca, bfc_a, nullptr,
            nullptr, nullptr, 0,
            t1_hi, t1_lo, HH, nullptr);
        fused_kernel<2,64><<<dim3(MA_ROWS/64, 4), 256, SM_2_64, sA>>>(
            t1_hi, t1_lo, HH, Wm1h, bm1, nullptr,
            nullptr, nullptr, 0,
            nullptr, nullptr, 0, t2);
        head_kernel<<<(MA_ROWS*32 + 255)/256, 256, 0, sA>>>(t2, Wm2, bm2, out, t);
        cur = nxt;
    }

    // join action stream back into stream 0
    cudaEventRecord(evJoin, sA);
    cudaStreamWaitEvent(s0, evJoin, 0);
}

// round 7
// speedup vs baseline: 4.5282x; 1.2285x over previous
#include <cuda_runtime.h>
#include <cuda_fp16.h>
#include <mma.h>
#include <math.h>
#include <stdint.h>

using namespace nvcuda;

#define BB 512
#define AA 4
#define EE 10
#define HH 256
#define TT 10
#define MP_ROWS (BB*AA*EE)   // 20480
#define MA_ROWS (BB*AA)      // 2048
#define G3H (3*HH)           // 768

// ---------------- scratch ----------------
__device__ __half g_h_hi[2][MP_ROWS * HH];
__device__ __half g_h_lo[2][MP_ROWS * HH];
__device__ __half g_xcat_hi[2][MA_ROWS * 512];   // [feat | ma]
__device__ __half g_xcat_lo[2][MA_ROWS * 512];
__device__ __half g_proc_hi[MP_ROWS * HH];
__device__ __half g_proc_lo[MP_ROWS * HH];
__device__ __half g_t1_hi[MA_ROWS * HH];
__device__ __half g_t1_lo[MA_ROWS * HH];
__device__ float g_t2[MA_ROWS * HH];
__device__ float g_xp8[MP_ROWS * 8];     // [ob0,ob1,ph0,ph1,ph2,0,0,0]
__device__ float g_xa4[MA_ROWS * 4];     // [g0,g1,g2,0]
__device__ float g_Wp8[G3H * 8];         // [w0..w4, bih, bhh, 0]
__device__ float g_Wa8[G3H * 8];         // [wg0..2, bih, bhh, 0,0,0]
__device__ __half g_Whhp[G3H * HH];
__device__ __half g_Wfcp[HH * HH];
__device__ __half g_Wcat[1024 * 512];
__device__ __half g_Wfca[HH * HH];
__device__ __half g_Wm1[HH * HH];

// ---------------- helpers ----------------
__device__ __forceinline__ float sigmoidf_(float x) { return 1.0f / (1.0f + __expf(-x)); }
__device__ __forceinline__ float eluf_(float x) { return x > 0.0f ? x : expm1f(x); }
__device__ __forceinline__ void split_fp16(float x, __half& hi, __half& lo) {
    hi = __float2half_rn(x);
    lo = __float2half_rn(x - __half2float(hi));
}
__device__ __forceinline__ void cp16(void* dst, const void* src) {
    unsigned d = (unsigned)__cvta_generic_to_shared(dst);
    asm volatile("cp.async.cg.shared.global [%0], [%1], 16;\n" :: "r"(d), "l"(src));
}
__device__ __forceinline__ void cp_commit() { asm volatile("cp.async.commit_group;\n" ::); }
template<int N> __device__ __forceinline__ void cp_wait() { asm volatile("cp.async.wait_group %0;\n" :: "n"(N)); }

// ---------------- prep kernels ----------------
__global__ void prep_xp_kernel(const float* __restrict__ obs, const float* __restrict__ phys,
                               float* __restrict__ xp8)
{
    int r = blockIdx.x * blockDim.x + threadIdx.x;
    if (r >= MP_ROWS) return;
    int b = r / (AA*EE);
    int e = r % EE;
    float* o = xp8 + r * 8;
    o[0] = obs[r*2+0]; o[1] = obs[r*2+1];
    const float* ph = phys + (b * EE + e) * 3;
    o[2] = ph[0]; o[3] = ph[1]; o[4] = ph[2];
    o[5] = 0.f; o[6] = 0.f; o[7] = 0.f;
}
__global__ void prep_wp8_kernel(const float* __restrict__ Wih, const float* __restrict__ bih,
                                const float* __restrict__ bhh, float* __restrict__ Wp8)
{
    int r = blockIdx.x * blockDim.x + threadIdx.x;
    if (r >= G3H) return;
    float* o = Wp8 + r * 8;
#pragma unroll
    for (int k = 0; k < 5; k++) o[k] = Wih[r*5+k];
    o[5] = bih[r]; o[6] = bhh[r]; o[7] = 0.f;
}
__global__ void prep_xa_kernel(const float* __restrict__ goals, float* __restrict__ xa4)
{
    int m = blockIdx.x * blockDim.x + threadIdx.x;
    if (m >= MA_ROWS) return;
    float* o = xa4 + m * 4;
    o[0] = goals[m*3+0]; o[1] = goals[m*3+1]; o[2] = goals[m*3+2]; o[3] = 0.f;
}
__global__ void prep_wa8_kernel(const float* __restrict__ Wih, const float* __restrict__ bih,
                                const float* __restrict__ bhh, float* __restrict__ Wa8)
{
    int r = blockIdx.x * blockDim.x + threadIdx.x;
    if (r >= G3H) return;
    float* o = Wa8 + r * 8;
    o[0] = Wih[r*259+256]; o[1] = Wih[r*259+257]; o[2] = Wih[r*259+258];
    o[3] = bih[r]; o[4] = bhh[r]; o[5] = 0.f; o[6] = 0.f; o[7] = 0.f;
}
__global__ void split_kernel(const float* __restrict__ src,
                             __half* __restrict__ hi, __half* __restrict__ lo, int n)
{
    int i = blockIdx.x * blockDim.x + threadIdx.x;
    if (i >= n) return;
    split_fp16(src[i], hi[i], lo[i]);
}
__global__ void split_strided_kernel(const float* __restrict__ src,
                                     __half* __restrict__ hi, __half* __restrict__ lo,
                                     int rows, int cols, int ldo)
{
    int i = blockIdx.x * blockDim.x + threadIdx.x;
    if (i >= rows * cols) return;
    int r = i / cols, c = i - r * cols;
    split_fp16(src[i], hi[r * ldo + c], lo[r * ldo + c]);
}
__global__ void conv_kernel(const float* __restrict__ src, __half* __restrict__ dst, int n)
{
    int i = blockIdx.x * blockDim.x + threadIdx.x;
    if (i >= n) return;
    dst[i] = __float2half_rn(src[i]);
}
// Wcat [1024, 512]: rows g*256+n. g=0:[Wih_r|Whh_r] g=1:[Wih_z|Whh_z] g=2:[Wih_n|0] g=3:[0|Whh_n]
__global__ void build_wcat_kernel(const float* __restrict__ Wih,  // [768,259]
                                  const float* __restrict__ Whh,  // [768,256]
                                  __half* __restrict__ Wcat)
{
    int idx = blockIdx.x * blockDim.x + threadIdx.x;
    if (idx >= 1024 * 512) return;
    int row = idx >> 9, col = idx & 511;
    int g = row >> 8, n = row & 255;
    float v = 0.0f;
    if (g < 2) {
        v = (col < 256) ? Wih[(g * 256 + n) * 259 + col] : Whh[(g * 256 + n) * 256 + (col - 256)];
    } else if (g == 2) {
        if (col < 256) v = Wih[(512 + n) * 259 + col];
    } else {
        if (col >= 256) v = Whh[(512 + n) * 256 + (col - 256)];
    }
    Wcat[idx] = __float2half_rn(v);
}

// ---------------- fused fp16 single-pass GEMM kernel ----------------
// MODE 0: physical GRU  (NSEG=3, K=256), MODE 1: action GRU (NSEG=4, K=512),
// MODE 2: ELU layer     (NSEG=1, K=256).
// A operand: fp16 hi only (state precision preserved via hi/lo storage + exact epilogue).
template<int MODE, int BM>
__global__ __launch_bounds__(256) void fused_kernel(
    const __half* __restrict__ Ahi, int lda,
    const __half* __restrict__ B,
    const float* __restrict__ xw,     // xp8 / xa4 / bias
    const float* __restrict__ swg,    // Wp8 / Wa8 / unused
    const __half* __restrict__ oldHi, const __half* __restrict__ oldLo, int oldLd,
    __half* __restrict__ Ohi, __half* __restrict__ Olo, int ldo,
    float* __restrict__ Ofp)
{
    constexpr int NSEG = (MODE == 0) ? 3 : ((MODE == 1) ? 4 : 1);
    constexpr int K = (MODE == 1) ? 512 : 256;
    constexpr int KT = K / 32;
    constexpr int MI = BM / 64;
    constexpr int AITER = BM / 64;          // A 16B chunks per thread (hi only)
    constexpr int AHS = BM * 40;
    constexpr int BHS = NSEG * 64 * 40;

    extern __shared__ __align__(16) char smem_raw[];
    __half* sm = (__half*)smem_raw;
    __half* sAh[2] = { sm,           sm + AHS };
    __half* sB[2]  = { sm + 2*AHS,   sm + 2*AHS + BHS };

    const int m0 = blockIdx.x * BM;
    const int n0 = blockIdx.y * 64;
    const int tid = threadIdx.x;
    const int wid = tid >> 5;
    const int lane = tid & 31;
    const int wm = wid >> 1, wn = wid & 1;

    auto load_tile = [&](int s, int kt) {
        const int k0 = kt * 32;
#pragma unroll
        for (int r = 0; r < AITER; r++) {
            int c = tid + r * 256;
            int row = c >> 2, kk = (c & 3) * 8;
            cp16(sAh[s] + row * 40 + kk, Ahi + (size_t)(m0 + row) * lda + k0 + kk);
        }
#pragma unroll
        for (int r = 0; r < NSEG; r++) {
            int c = tid + r * 256;
            int srow = c >> 2, kk = (c & 3) * 8;
            int srcrow = (MODE == 2) ? (n0 + srow) : ((srow >> 6) * 256 + n0 + (srow & 63));
            cp16(sB[s] + srow * 40 + kk, B + (size_t)srcrow * K + k0 + kk);
        }
    };

    wmma::fragment<wmma::accumulator, 16, 16, 16, float> acc[NSEG][MI][2];
#pragma unroll
    for (int g = 0; g < NSEG; g++)
#pragma unroll
        for (int i = 0; i < MI; i++)
#pragma unroll
            for (int j = 0; j < 2; j++) wmma::fill_fragment(acc[g][i][j], 0.0f);

    load_tile(0, 0); cp_commit();
    load_tile(1, 1); cp_commit();

    for (int kt = 0; kt < KT; kt++) {
        if (kt == KT - 1) cp_wait<0>(); else cp_wait<1>();
        __syncthreads();
        const int s = kt & 1;
#pragma unroll
        for (int kc = 0; kc < 32; kc += 16) {
            wmma::fragment<wmma::matrix_a, 16, 16, 16, __half, wmma::row_major> ah[MI];
#pragma unroll
            for (int i = 0; i < MI; i++)
                wmma::load_matrix_sync(ah[i], sAh[s] + (wm * 16 * MI + i * 16) * 40 + kc, 40);
#pragma unroll
            for (int g = 0; g < NSEG; g++) {
                wmma::fragment<wmma::matrix_b, 16, 16, 16, __half, wmma::col_major> b[2];
#pragma unroll
                for (int j = 0; j < 2; j++)
                    wmma::load_matrix_sync(b[j], sB[s] + (g * 64 + wn * 32 + j * 16) * 40 + kc, 40);
#pragma unroll
                for (int i = 0; i < MI; i++)
#pragma unroll
                    for (int j = 0; j < 2; j++)
                        wmma::mma_sync(acc[g][i][j], ah[i], b[j], acc[g][i][j]);
            }
        }
        __syncthreads();
        if (kt + 2 < KT) { load_tile(kt & 1, kt + 2); cp_commit(); }
    }

    // ---------------- epilogue ----------------
    float* wbuf = (float*)smem_raw;
    float* sX = wbuf + 8 * NSEG * 320;
    constexpr int XW = (MODE == 1) ? 4 : 8;
    float* sW = sX + BM * XW;

    if (MODE != 2) {
#pragma unroll
        for (int r = 0; r < (BM * XW + 255) / 256; r++) {
            int c = tid + r * 256;
            if (c < BM * XW) sX[c] = xw[(size_t)(m0 + (c / XW)) * XW + (c % XW)];
        }
#pragma unroll
        for (int r = 0; r < 6; r++) {
            int c = tid + r * 256;
            int srow = c >> 3, k = c & 7;
            sW[c] = swg[(size_t)((srow >> 6) * 256 + n0 + (srow & 63)) * 8 + k];
        }
    }
    __syncthreads();

    float* wb = wbuf + wid * NSEG * 320;
    const int r_ = lane >> 1;
    const int c0_ = (lane & 1) * 8;

#pragma unroll
    for (int i = 0; i < MI; i++) {
#pragma unroll
        for (int j = 0; j < 2; j++) {
#pragma unroll
            for (int g = 0; g < NSEG; g++)
                wmma::store_matrix_sync(wb + g * 320, acc[g][i][j], 20, wmma::mem_row_major);
            __syncwarp();

            const int mloc = wm * 16 * MI + i * 16 + r_;
            const int m = m0 + mloc;
            const int nl0 = wn * 32 + j * 16 + c0_;
            const int nabs = n0 + nl0;

            __half oh8[8], ol8[8];

            if (MODE == 2) {
                float4 b0 = *(const float4*)&xw[nabs];
                float4 b1 = *(const float4*)&xw[nabs + 4];
                float bia[8] = {b0.x,b0.y,b0.z,b0.w,b1.x,b1.y,b1.z,b1.w};
                float ov[8];
#pragma unroll
                for (int cc = 0; cc < 8; cc++) {
                    float v = eluf_(wb[r_ * 20 + c0_ + cc] + bia[cc]);
                    ov[cc] = v;
                    split_fp16(v, oh8[cc], ol8[cc]);
                }
                if (Ofp) {
                    *(float4*)&Ofp[(size_t)m * 256 + nabs] = make_float4(ov[0],ov[1],ov[2],ov[3]);
                    *(float4*)&Ofp[(size_t)m * 256 + nabs + 4] = make_float4(ov[4],ov[5],ov[6],ov[7]);
                }
                if (Ohi) {
                    *(uint4*)&Ohi[(size_t)m * ldo + nabs] = *(uint4*)oh8;
                    *(uint4*)&Olo[(size_t)m * ldo + nabs] = *(uint4*)ol8;
                }
            } else {
                uint4 hv4 = *(const uint4*)&oldHi[(size_t)m * oldLd + nabs];
                uint4 lv4 = *(const uint4*)&oldLo[(size_t)m * oldLd + nabs];
                const __half* hvp = (const __half*)&hv4;
                const __half* lvp = (const __half*)&lv4;
                float xr[XW];
#pragma unroll
                for (int k = 0; k < XW; k++) xr[k] = sX[mloc * XW + k];
#pragma unroll
                for (int cc = 0; cc < 8; cc++) {
                    int nl = nl0 + cc;
                    const float* w0 = sW + (0 * 64 + nl) * 8;
                    const float* w1 = sW + (1 * 64 + nl) * 8;
                    const float* w2 = sW + (2 * 64 + nl) * 8;
                    float a0 = wb[0 * 320 + r_ * 20 + c0_ + cc];
                    float a1 = wb[1 * 320 + r_ * 20 + c0_ + cc];
                    float a2 = wb[2 * 320 + r_ * 20 + c0_ + cc];
                    float gi_r, gi_z, gi_n, rr, zz, nn;
                    if (MODE == 0) {
                        gi_r = w0[5]; gi_z = w1[5]; gi_n = w2[5];
#pragma unroll
                        for (int k = 0; k < 5; k++) {
                            gi_r += xr[k] * w0[k];
                            gi_z += xr[k] * w1[k];
                            gi_n += xr[k] * w2[k];
                        }
                        rr = sigmoidf_(gi_r + a0 + w0[6]);
                        zz = sigmoidf_(gi_z + a1 + w1[6]);
                        nn = tanhf(gi_n + rr * (a2 + w2[6]));
                    } else {
                        float a3 = wb[3 * 320 + r_ * 20 + c0_ + cc];
                        gi_r = w0[3]; gi_z = w1[3]; gi_n = w2[3];
#pragma unroll
                        for (int k = 0; k < 3; k++) {
                            gi_r += xr[k] * w0[k];
                            gi_z += xr[k] * w1[k];
                            gi_n += xr[k] * w2[k];
                        }
                        rr = sigmoidf_(gi_r + a0 + w0[4]);
                        zz = sigmoidf_(gi_z + a1 + w1[4]);
                        nn = tanhf(gi_n + a2 + rr * (a3 + w2[4]));
                    }
                    float hold = __half2float(hvp[cc]) + __half2float(lvp[cc]);
                    float hnew = (1.0f - zz) * nn + zz * hold;
                    split_fp16(hnew, oh8[cc], ol8[cc]);
                }
                *(uint4*)&Ohi[(size_t)m * ldo + nabs] = *(uint4*)oh8;
                *(uint4*)&Olo[(size_t)m * ldo + nabs] = *(uint4*)ol8;
            }
            __syncwarp();
        }
    }
}

// ---------------- entity max-pool ----------------
__global__ void pool_kernel(const __half* __restrict__ phi,
                            const __half* __restrict__ plo,
                            __half* __restrict__ xcat_hi,
                            __half* __restrict__ xcat_lo)
{
    int idx = blockIdx.x * blockDim.x + threadIdx.x;
    if (idx >= MA_ROWS * 32) return;
    int m = idx >> 5, c8 = (idx & 31) * 8;
    float v[8];
#pragma unroll
    for (int k = 0; k < 8; k++) v[k] = -1e30f;
#pragma unroll
    for (int e = 0; e < EE; e++) {
        size_t off = (size_t)(m * EE + e) * HH + c8;
        uint4 h4 = *(const uint4*)&phi[off];
        uint4 l4 = *(const uint4*)&plo[off];
        const __half* hp = (const __half*)&h4;
        const __half* lp = (const __half*)&l4;
#pragma unroll
        for (int k = 0; k < 8; k++)
            v[k] = fmaxf(v[k], __half2float(hp[k]) + __half2float(lp[k]));
    }
    __half h8[8], l8[8];
#pragma unroll
    for (int k = 0; k < 8; k++) split_fp16(v[k], h8[k], l8[k]);
    size_t xo = (size_t)m * 512 + c8;
    *(uint4*)&xcat_hi[xo] = *(uint4*)h8;
    *(uint4*)&xcat_lo[xo] = *(uint4*)l8;
}

// ---------------- head ----------------
__global__ void head_kernel(const float* __restrict__ t2,
                            const float* __restrict__ Wm2, const float* __restrict__ bm2,
                            float* __restrict__ out, int tstep)
{
    int warp = (blockIdx.x * blockDim.x + threadIdx.x) >> 5;
    int lane = threadIdx.x & 31;
    if (warp >= MA_ROWS) return;
    float s0 = 0.0f, s1 = 0.0f;
    for (int k = lane; k < HH; k += 32) {
        float x = t2[warp * HH + k];
        s0 += x * Wm2[k];
        s1 += x * Wm2[HH + k];
    }
#pragma unroll
    for (int off = 16; off; off >>= 1) {
        s0 += __shfl_xor_sync(0xffffffffu, s0, off);
        s1 += __shfl_xor_sync(0xffffffffu, s1, off);
    }
    if (lane == 0) {
        out[((size_t)tstep * MA_ROWS + warp) * 2 + 0] = tanhf(s0 + bm2[0]) * 0.05f;
        out[((size_t)tstep * MA_ROWS + warp) * 2 + 1] = tanhf(s1 + bm2[1]) * 0.05f;
    }
}

// ---------------- host launcher ----------------
extern "C" void kernel_launch(void* const* d_in, const int* in_sizes, int n_in,
                              void* d_out, int out_size)
{
    const float* obs    = (const float*)d_in[0];
    const float* phys   = (const float*)d_in[1];
    const float* goals  = (const float*)d_in[2];
    const float* mem_p  = (const float*)d_in[3];
    const float* mem_a  = (const float*)d_in[4];
    const float* Wih_p  = (const float*)d_in[5];
    const float* Whh_p  = (const float*)d_in[6];
    const float* bih_p  = (const float*)d_in[7];
    const float* bhh_p  = (const float*)d_in[8];
    const float* Wfc_p  = (const float*)d_in[9];
    const float* bfc_p  = (const float*)d_in[10];
    const float* Wih_a  = (const float*)d_in[11];
    const float* Whh_a  = (const float*)d_in[12];
    const float* bih_a  = (const float*)d_in[13];
    const float* bhh_a  = (const float*)d_in[14];
    const float* Wfc_a  = (const float*)d_in[15];
    const float* bfc_a  = (const float*)d_in[16];
    const float* Wm1    = (const float*)d_in[17];
    const float* bm1    = (const float*)d_in[18];
    const float* Wm2    = (const float*)d_in[19];
    const float* bm2    = (const float*)d_in[20];
    float* out = (float*)d_out;

    void* p;
    __half *h_hi[2], *h_lo[2], *xc_hi[2], *xc_lo[2];
    cudaGetSymbolAddress(&p, g_h_hi);    h_hi[0] = (__half*)p; h_hi[1] = h_hi[0] + (size_t)MP_ROWS*HH;
    cudaGetSymbolAddress(&p, g_h_lo);    h_lo[0] = (__half*)p; h_lo[1] = h_lo[0] + (size_t)MP_ROWS*HH;
    cudaGetSymbolAddress(&p, g_xcat_hi); xc_hi[0] = (__half*)p; xc_hi[1] = xc_hi[0] + (size_t)MA_ROWS*512;
    cudaGetSymbolAddress(&p, g_xcat_lo); xc_lo[0] = (__half*)p; xc_lo[1] = xc_lo[0] + (size_t)MA_ROWS*512;
    cudaGetSymbolAddress(&p, g_proc_hi); __half* proc_hi = (__half*)p;
    cudaGetSymbolAddress(&p, g_proc_lo); __half* proc_lo = (__half*)p;
    cudaGetSymbolAddress(&p, g_t1_hi);   __half* t1_hi = (__half*)p;
    cudaGetSymbolAddress(&p, g_t1_lo);   __half* t1_lo = (__half*)p;
    cudaGetSymbolAddress(&p, g_t2);      float* t2 = (float*)p;
    cudaGetSymbolAddress(&p, g_xp8);     float* xp8 = (float*)p;
    cudaGetSymbolAddress(&p, g_xa4);     float* xa4 = (float*)p;
    cudaGetSymbolAddress(&p, g_Wp8);     float* Wp8 = (float*)p;
    cudaGetSymbolAddress(&p, g_Wa8);     float* Wa8 = (float*)p;
    cudaGetSymbolAddress(&p, g_Whhp);    __half* Whhp = (__half*)p;
    cudaGetSymbolAddress(&p, g_Wfcp);    __half* Wfcp = (__half*)p;
    cudaGetSymbolAddress(&p, g_Wcat);    __half* Wcat = (__half*)p;
    cudaGetSymbolAddress(&p, g_Wfca);    __half* Wfca = (__half*)p;
    cudaGetSymbolAddress(&p, g_Wm1);     __half* Wm1h = (__half*)p;

    // smem: (2*BM*40 + 2*NSEG*64*40) * 2 bytes
    const int SM_0_128 = (2*128*40 + 2*3*64*40) * 2;   // 51200
    const int SM_1_64  = (2*64*40  + 2*4*64*40) * 2;   // 51200
    const int SM_2_128 = (2*128*40 + 2*1*64*40) * 2;   // 30720
    const int SM_2_64  = (2*64*40  + 2*1*64*40) * 2;   // 20480
    cudaFuncSetAttribute((const void*)fused_kernel<0,128>, cudaFuncAttributeMaxDynamicSharedMemorySize, SM_0_128);
    cudaFuncSetAttribute((const void*)fused_kernel<1,64>,  cudaFuncAttributeMaxDynamicSharedMemorySize, SM_1_64);
    cudaFuncSetAttribute((const void*)fused_kernel<2,128>, cudaFuncAttributeMaxDynamicSharedMemorySize, SM_2_128);
    cudaFuncSetAttribute((const void*)fused_kernel<2,64>,  cudaFuncAttributeMaxDynamicSharedMemorySize, SM_2_64);

    // ---- one-time stream/event setup ----
    static cudaStream_t sA = nullptr;
    static cudaEvent_t evFork = nullptr, evJoin = nullptr;
    static cudaEvent_t evP[TT], evA[TT];
    if (sA == nullptr) {
        cudaStreamCreateWithFlags(&sA, cudaStreamNonBlocking);
        cudaEventCreateWithFlags(&evFork, cudaEventDisableTiming);
        cudaEventCreateWithFlags(&evJoin, cudaEventDisableTiming);
        for (int i = 0; i < TT; i++) {
            cudaEventCreateWithFlags(&evP[i], cudaEventDisableTiming);
            cudaEventCreateWithFlags(&evA[i], cudaEventDisableTiming);
        }
    }

    cudaStream_t s0 = 0;

    // ---- prep (stream 0) ----
    split_kernel<<<(MP_ROWS*HH + 255)/256, 256, 0, s0>>>(mem_p, h_hi[0], h_lo[0], MP_ROWS*HH);
    split_strided_kernel<<<(MA_ROWS*HH + 255)/256, 256, 0, s0>>>(mem_a, xc_hi[0] + 256, xc_lo[0] + 256, MA_ROWS, HH, 512);
    conv_kernel<<<(G3H*HH + 255)/256, 256, 0, s0>>>(Whh_p, Whhp, G3H*HH);
    conv_kernel<<<(HH*HH + 255)/256, 256, 0, s0>>>(Wfc_p, Wfcp, HH*HH);
    conv_kernel<<<(HH*HH + 255)/256, 256, 0, s0>>>(Wfc_a, Wfca, HH*HH);
    conv_kernel<<<(HH*HH + 255)/256, 256, 0, s0>>>(Wm1, Wm1h, HH*HH);
    build_wcat_kernel<<<(1024*512 + 255)/256, 256, 0, s0>>>(Wih_a, Whh_a, Wcat);
    prep_xp_kernel<<<(MP_ROWS + 255)/256, 256, 0, s0>>>(obs, phys, xp8);
    prep_wp8_kernel<<<(G3H + 255)/256, 256, 0, s0>>>(Wih_p, bih_p, bhh_p, Wp8);
    prep_xa_kernel<<<(MA_ROWS + 255)/256, 256, 0, s0>>>(goals, xa4);
    prep_wa8_kernel<<<(G3H + 255)/256, 256, 0, s0>>>(Wih_a, bih_a, bhh_a, Wa8);

    // fork the action stream off stream 0 (after prep)
    cudaEventRecord(evFork, s0);
    cudaStreamWaitEvent(sA, evFork, 0);

    // ---- recurrence ----
    int cur = 0;
    for (int t = 0; t < TT; t++) {
        int nxt = cur ^ 1;
        // physical GRU fused
        fused_kernel<0,128><<<dim3(MP_ROWS/128, 4), 256, SM_0_128, s0>>>(
            h_hi[cur], HH, Whhp, xp8, Wp8,
            h_hi[cur], h_lo[cur], HH,
            h_hi[nxt], h_lo[nxt], HH, nullptr);
        // fc_p + ELU -> proc
        fused_kernel<2,128><<<dim3(MP_ROWS/128, 4), 256, SM_2_128, s0>>>(
            h_hi[nxt], HH, Wfcp, bfc_p, nullptr,
            nullptr, nullptr, 0,
            proc_hi, proc_lo, HH, nullptr);
        // pool -> feat into xcat[cur][0:256)  (guard WAR vs gru_a(t-2))
        if (t >= 2) cudaStreamWaitEvent(s0, evA[t - 2], 0);
        pool_kernel<<<(MA_ROWS*32 + 255)/256, 256, 0, s0>>>(proc_hi, proc_lo, xc_hi[cur], xc_lo[cur]);
        cudaEventRecord(evP[t], s0);

        // ---- action chain on stream A ----
        cudaStreamWaitEvent(sA, evP[t], 0);
        fused_kernel<1,64><<<dim3(MA_ROWS/64, 4), 256, SM_1_64, sA>>>(
            xc_hi[cur], 512, Wcat, xa4, Wa8,
            xc_hi[cur] + 256, xc_lo[cur] + 256, 512,
            xc_hi[nxt] + 256, xc_lo[nxt] + 256, 512, nullptr);
        cudaEventRecord(evA[t], sA);
        fused_kernel<2,64><<<dim3(MA_ROWS/64, 4), 256, SM_2_64, sA>>>(
            xc_hi[nxt] + 256, 512, Wfca, bfc_a, nullptr,
            nullptr, nullptr, 0,
            t1_hi, t1_lo, HH, nullptr);
        fused_kernel<2,64><<<dim3(MA_ROWS/64, 4), 256, SM_2_64, sA>>>(
            t1_hi, HH, Wm1h, bm1, nullptr,
            nullptr, nullptr, 0,
            nullptr, nullptr, 0, t2);
        head_kernel<<<(MA_ROWS*32 + 255)/256, 256, 0, sA>>>(t2, Wm2, bm2, out, t);
        cur = nxt;
    }

    // join action stream back into stream 0
    cudaEventRecord(evJoin, sA);
    cudaStreamWaitEvent(s0, evJoin, 0);
}

// round 8
// speedup vs baseline: 4.6984x; 1.0376x over previous
#include <cuda_runtime.h>
#include <cuda_fp16.h>
#include <mma.h>
#include <math.h>
#include <stdint.h>

using namespace nvcuda;

#define BB 512
#define AA 4
#define EE 10
#define HH 256
#define TT 10
#define MP_ROWS (BB*AA*EE)   // 20480
#define MA_ROWS (BB*AA)      // 2048
#define G3H (3*HH)           // 768

// ---------------- scratch ----------------
__device__ __half g_h_hi[2][MP_ROWS * HH];
__device__ __half g_h_lo[2][MP_ROWS * HH];
__device__ __half g_xcat_hi[2][MA_ROWS * 512];   // [feat | ma]
__device__ __half g_xcat_lo[2][MA_ROWS * 512];
__device__ __half g_proc_hi[MP_ROWS * HH];
__device__ __half g_proc_lo[MP_ROWS * HH];
__device__ __half g_t1_hi[MA_ROWS * HH];
__device__ __half g_t1_lo[MA_ROWS * HH];
__device__ float g_t2[MA_ROWS * HH];
__device__ float g_xp8[MP_ROWS * 8];     // [ob0,ob1,ph0,ph1,ph2,0,0,0]
__device__ float g_xa4[MA_ROWS * 4];     // [g0,g1,g2,0]
__device__ float g_Wp8[G3H * 8];         // [w0..w4, bih, bhh, 0]
__device__ float g_Wa8[G3H * 8];         // [wg0..2, bih, bhh, 0,0,0]
__device__ __half g_Whhp[G3H * HH];
__device__ __half g_Wfcp[HH * HH];
__device__ __half g_Wcat[1024 * 512];
__device__ __half g_Wfca[HH * HH];
__device__ __half g_Wm1[HH * HH];

// ---------------- helpers ----------------
__device__ __forceinline__ float sigmoidf_(float x) { return 1.0f / (1.0f + __expf(-x)); }
__device__ __forceinline__ float eluf_(float x) { return x > 0.0f ? x : expm1f(x); }
__device__ __forceinline__ void split_fp16(float x, __half& hi, __half& lo) {
    hi = __float2half_rn(x);
    lo = __float2half_rn(x - __half2float(hi));
}
__device__ __forceinline__ void cp16(void* dst, const void* src) {
    unsigned d = (unsigned)__cvta_generic_to_shared(dst);
    asm volatile("cp.async.cg.shared.global [%0], [%1], 16;\n" :: "r"(d), "l"(src));
}
__device__ __forceinline__ void cp_commit() { asm volatile("cp.async.commit_group;\n" ::); }
template<int N> __device__ __forceinline__ void cp_wait() { asm volatile("cp.async.wait_group %0;\n" :: "n"(N)); }

// ---------------- prep kernels ----------------
__global__ void prep_xp_kernel(const float* __restrict__ obs, const float* __restrict__ phys,
                               float* __restrict__ xp8)
{
    int r = blockIdx.x * blockDim.x + threadIdx.x;
    if (r >= MP_ROWS) return;
    int b = r / (AA*EE);
    int e = r % EE;
    float* o = xp8 + r * 8;
    o[0] = obs[r*2+0]; o[1] = obs[r*2+1];
    const float* ph = phys + (b * EE + e) * 3;
    o[2] = ph[0]; o[3] = ph[1]; o[4] = ph[2];
    o[5] = 0.f; o[6] = 0.f; o[7] = 0.f;
}
__global__ void prep_wp8_kernel(const float* __restrict__ Wih, const float* __restrict__ bih,
                                const float* __restrict__ bhh, float* __restrict__ Wp8)
{
    int r = blockIdx.x * blockDim.x + threadIdx.x;
    if (r >= G3H) return;
    float* o = Wp8 + r * 8;
#pragma unroll
    for (int k = 0; k < 5; k++) o[k] = Wih[r*5+k];
    o[5] = bih[r]; o[6] = bhh[r]; o[7] = 0.f;
}
__global__ void prep_xa_kernel(const float* __restrict__ goals, float* __restrict__ xa4)
{
    int m = blockIdx.x * blockDim.x + threadIdx.x;
    if (m >= MA_ROWS) return;
    float* o = xa4 + m * 4;
    o[0] = goals[m*3+0]; o[1] = goals[m*3+1]; o[2] = goals[m*3+2]; o[3] = 0.f;
}
__global__ void prep_wa8_kernel(const float* __restrict__ Wih, const float* __restrict__ bih,
                                const float* __restrict__ bhh, float* __restrict__ Wa8)
{
    int r = blockIdx.x * blockDim.x + threadIdx.x;
    if (r >= G3H) return;
    float* o = Wa8 + r * 8;
    o[0] = Wih[r*259+256]; o[1] = Wih[r*259+257]; o[2] = Wih[r*259+258];
    o[3] = bih[r]; o[4] = bhh[r]; o[5] = 0.f; o[6] = 0.f; o[7] = 0.f;
}
__global__ void split_kernel(const float* __restrict__ src,
                             __half* __restrict__ hi, __half* __restrict__ lo, int n)
{
    int i = blockIdx.x * blockDim.x + threadIdx.x;
    if (i >= n) return;
    split_fp16(src[i], hi[i], lo[i]);
}
__global__ void split_strided_kernel(const float* __restrict__ src,
                                     __half* __restrict__ hi, __half* __restrict__ lo,
                                     int rows, int cols, int ldo)
{
    int i = blockIdx.x * blockDim.x + threadIdx.x;
    if (i >= rows * cols) return;
    int r = i / cols, c = i - r * cols;
    split_fp16(src[i], hi[r * ldo + c], lo[r * ldo + c]);
}
__global__ void conv_kernel(const float* __restrict__ src, __half* __restrict__ dst, int n)
{
    int i = blockIdx.x * blockDim.x + threadIdx.x;
    if (i >= n) return;
    dst[i] = __float2half_rn(src[i]);
}
// Wcat [1024, 512]: rows g*256+n. g=0:[Wih_r|Whh_r] g=1:[Wih_z|Whh_z] g=2:[Wih_n|0] g=3:[0|Whh_n]
__global__ void build_wcat_kernel(const float* __restrict__ Wih,  // [768,259]
                                  const float* __restrict__ Whh,  // [768,256]
                                  __half* __restrict__ Wcat)
{
    int idx = blockIdx.x * blockDim.x + threadIdx.x;
    if (idx >= 1024 * 512) return;
    int row = idx >> 9, col = idx & 511;
    int g = row >> 8, n = row & 255;
    float v = 0.0f;
    if (g < 2) {
        v = (col < 256) ? Wih[(g * 256 + n) * 259 + col] : Whh[(g * 256 + n) * 256 + (col - 256)];
    } else if (g == 2) {
        if (col < 256) v = Wih[(512 + n) * 259 + col];
    } else {
        if (col >= 256) v = Whh[(512 + n) * 256 + (col - 256)];
    }
    Wcat[idx] = __float2half_rn(v);
}

// ---------------- fused fp16 single-pass GEMM kernel ----------------
// MODE 0: physical GRU  (NSEG=3, K=256), MODE 1: action GRU (NSEG=4, K=512),
// MODE 2: ELU layer     (NSEG=1, K=256).
template<int MODE, int BM>
__global__ __launch_bounds__(256) void fused_kernel(
    const __half* __restrict__ Ahi, int lda,
    const __half* __restrict__ B,
    const float* __restrict__ xw,     // xp8 / xa4 / bias
    const float* __restrict__ swg,    // Wp8 / Wa8 / unused
    const __half* __restrict__ oldHi, const __half* __restrict__ oldLo, int oldLd,
    __half* __restrict__ Ohi, __half* __restrict__ Olo, int ldo,
    float* __restrict__ Ofp)
{
    constexpr int NSEG = (MODE == 0) ? 3 : ((MODE == 1) ? 4 : 1);
    constexpr int K = (MODE == 1) ? 512 : 256;
    constexpr int KT = K / 32;
    constexpr int MI = BM / 64;
    constexpr int AITER = BM / 64;
    constexpr int AHS = BM * 40;
    constexpr int BHS = NSEG * 64 * 40;

    extern __shared__ __align__(16) char smem_raw[];
    __half* sm = (__half*)smem_raw;
    __half* sAh[2] = { sm,           sm + AHS };
    __half* sB[2]  = { sm + 2*AHS,   sm + 2*AHS + BHS };

    const int m0 = blockIdx.x * BM;
    const int n0 = blockIdx.y * 64;
    const int tid = threadIdx.x;
    const int wid = tid >> 5;
    const int lane = tid & 31;
    const int wm = wid >> 1, wn = wid & 1;

    auto load_tile = [&](int s, int kt) {
        const int k0 = kt * 32;
#pragma unroll
        for (int r = 0; r < AITER; r++) {
            int c = tid + r * 256;
            int row = c >> 2, kk = (c & 3) * 8;
            cp16(sAh[s] + row * 40 + kk, Ahi + (size_t)(m0 + row) * lda + k0 + kk);
        }
#pragma unroll
        for (int r = 0; r < NSEG; r++) {
            int c = tid + r * 256;
            int srow = c >> 2, kk = (c & 3) * 8;
            int srcrow = (MODE == 2) ? (n0 + srow) : ((srow >> 6) * 256 + n0 + (srow & 63));
            cp16(sB[s] + srow * 40 + kk, B + (size_t)srcrow * K + k0 + kk);
        }
    };

    wmma::fragment<wmma::accumulator, 16, 16, 16, float> acc[NSEG][MI][2];
#pragma unroll
    for (int g = 0; g < NSEG; g++)
#pragma unroll
        for (int i = 0; i < MI; i++)
#pragma unroll
            for (int j = 0; j < 2; j++) wmma::fill_fragment(acc[g][i][j], 0.0f);

    load_tile(0, 0); cp_commit();
    load_tile(1, 1); cp_commit();

    for (int kt = 0; kt < KT; kt++) {
        if (kt == KT - 1) cp_wait<0>(); else cp_wait<1>();
        __syncthreads();
        const int s = kt & 1;
#pragma unroll
        for (int kc = 0; kc < 32; kc += 16) {
            wmma::fragment<wmma::matrix_a, 16, 16, 16, __half, wmma::row_major> ah[MI];
#pragma unroll
            for (int i = 0; i < MI; i++)
                wmma::load_matrix_sync(ah[i], sAh[s] + (wm * 16 * MI + i * 16) * 40 + kc, 40);
#pragma unroll
            for (int g = 0; g < NSEG; g++) {
                wmma::fragment<wmma::matrix_b, 16, 16, 16, __half, wmma::col_major> b[2];
#pragma unroll
                for (int j = 0; j < 2; j++)
                    wmma::load_matrix_sync(b[j], sB[s] + (g * 64 + wn * 32 + j * 16) * 40 + kc, 40);
#pragma unroll
                for (int i = 0; i < MI; i++)
#pragma unroll
                    for (int j = 0; j < 2; j++)
                        wmma::mma_sync(acc[g][i][j], ah[i], b[j], acc[g][i][j]);
            }
        }
        __syncthreads();
        if (kt + 2 < KT) { load_tile(kt & 1, kt + 2); cp_commit(); }
    }

    // ---------------- epilogue ----------------
    float* wbuf = (float*)smem_raw;
    float* sX = wbuf + 8 * NSEG * 320;
    constexpr int XW = (MODE == 1) ? 4 : 8;
    float* sW = sX + BM * XW;

    if (MODE != 2) {
#pragma unroll
        for (int r = 0; r < (BM * XW + 255) / 256; r++) {
            int c = tid + r * 256;
            if (c < BM * XW) sX[c] = xw[(size_t)(m0 + (c / XW)) * XW + (c % XW)];
        }
#pragma unroll
        for (int r = 0; r < 6; r++) {
            int c = tid + r * 256;
            int srow = c >> 3, k = c & 7;
            sW[c] = swg[(size_t)((srow >> 6) * 256 + n0 + (srow & 63)) * 8 + k];
        }
    }
    __syncthreads();

    float* wb = wbuf + wid * NSEG * 320;
    const int r_ = lane >> 1;
    const int c0_ = (lane & 1) * 8;

#pragma unroll
    for (int i = 0; i < MI; i++) {
#pragma unroll
        for (int j = 0; j < 2; j++) {
#pragma unroll
            for (int g = 0; g < NSEG; g++)
                wmma::store_matrix_sync(wb + g * 320, acc[g][i][j], 20, wmma::mem_row_major);
            __syncwarp();

            const int mloc = wm * 16 * MI + i * 16 + r_;
            const int m = m0 + mloc;
            const int nl0 = wn * 32 + j * 16 + c0_;
            const int nabs = n0 + nl0;

            __half oh8[8], ol8[8];

            if (MODE == 2) {
                float4 b0 = *(const float4*)&xw[nabs];
                float4 b1 = *(const float4*)&xw[nabs + 4];
                float bia[8] = {b0.x,b0.y,b0.z,b0.w,b1.x,b1.y,b1.z,b1.w};
                float ov[8];
#pragma unroll
                for (int cc = 0; cc < 8; cc++) {
                    float v = eluf_(wb[r_ * 20 + c0_ + cc] + bia[cc]);
                    ov[cc] = v;
                    split_fp16(v, oh8[cc], ol8[cc]);
                }
                if (Ofp) {
                    *(float4*)&Ofp[(size_t)m * 256 + nabs] = make_float4(ov[0],ov[1],ov[2],ov[3]);
                    *(float4*)&Ofp[(size_t)m * 256 + nabs + 4] = make_float4(ov[4],ov[5],ov[6],ov[7]);
                }
                if (Ohi) {
                    *(uint4*)&Ohi[(size_t)m * ldo + nabs] = *(uint4*)oh8;
                    *(uint4*)&Olo[(size_t)m * ldo + nabs] = *(uint4*)ol8;
                }
            } else {
                uint4 hv4 = *(const uint4*)&oldHi[(size_t)m * oldLd + nabs];
                uint4 lv4 = *(const uint4*)&oldLo[(size_t)m * oldLd + nabs];
                const __half* hvp = (const __half*)&hv4;
                const __half* lvp = (const __half*)&lv4;
                float xr[XW];
#pragma unroll
                for (int k = 0; k < XW; k++) xr[k] = sX[mloc * XW + k];
#pragma unroll
                for (int cc = 0; cc < 8; cc++) {
                    int nl = nl0 + cc;
                    const float* w0 = sW + (0 * 64 + nl) * 8;
                    const float* w1 = sW + (1 * 64 + nl) * 8;
                    const float* w2 = sW + (2 * 64 + nl) * 8;
                    float a0 = wb[0 * 320 + r_ * 20 + c0_ + cc];
                    float a1 = wb[1 * 320 + r_ * 20 + c0_ + cc];
                    float a2 = wb[2 * 320 + r_ * 20 + c0_ + cc];
                    float gi_r, gi_z, gi_n, rr, zz, nn;
                    if (MODE == 0) {
                        gi_r = w0[5]; gi_z = w1[5]; gi_n = w2[5];
#pragma unroll
                        for (int k = 0; k < 5; k++) {
                            gi_r += xr[k] * w0[k];
                            gi_z += xr[k] * w1[k];
                            gi_n += xr[k] * w2[k];
                        }
                        rr = sigmoidf_(gi_r + a0 + w0[6]);
                        zz = sigmoidf_(gi_z + a1 + w1[6]);
                        nn = tanhf(gi_n + rr * (a2 + w2[6]));
                    } else {
                        float a3 = wb[3 * 320 + r_ * 20 + c0_ + cc];
                        gi_r = w0[3]; gi_z = w1[3]; gi_n = w2[3];
#pragma unroll
                        for (int k = 0; k < 3; k++) {
                            gi_r += xr[k] * w0[k];
                            gi_z += xr[k] * w1[k];
                            gi_n += xr[k] * w2[k];
                        }
                        rr = sigmoidf_(gi_r + a0 + w0[4]);
                        zz = sigmoidf_(gi_z + a1 + w1[4]);
                        nn = tanhf(gi_n + a2 + rr * (a3 + w2[4]));
                    }
                    float hold = __half2float(hvp[cc]) + __half2float(lvp[cc]);
                    float hnew = (1.0f - zz) * nn + zz * hold;
                    split_fp16(hnew, oh8[cc], ol8[cc]);
                }
                *(uint4*)&Ohi[(size_t)m * ldo + nabs] = *(uint4*)oh8;
                *(uint4*)&Olo[(size_t)m * ldo + nabs] = *(uint4*)ol8;
            }
            __syncwarp();
        }
    }
}

// ---------------- entity max-pool ----------------
__global__ void pool_kernel(const __half* __restrict__ phi,
                            const __half* __restrict__ plo,
                            __half* __restrict__ xcat_hi,
                            __half* __restrict__ xcat_lo)
{
    int idx = blockIdx.x * blockDim.x + threadIdx.x;
    if (idx >= MA_ROWS * 32) return;
    int m = idx >> 5, c8 = (idx & 31) * 8;
    float v[8];
#pragma unroll
    for (int k = 0; k < 8; k++) v[k] = -1e30f;
#pragma unroll
    for (int e = 0; e < EE; e++) {
        size_t off = (size_t)(m * EE + e) * HH + c8;
        uint4 h4 = *(const uint4*)&phi[off];
        uint4 l4 = *(const uint4*)&plo[off];
        const __half* hp = (const __half*)&h4;
        const __half* lp = (const __half*)&l4;
#pragma unroll
        for (int k = 0; k < 8; k++)
            v[k] = fmaxf(v[k], __half2float(hp[k]) + __half2float(lp[k]));
    }
    __half h8[8], l8[8];
#pragma unroll
    for (int k = 0; k < 8; k++) split_fp16(v[k], h8[k], l8[k]);
    size_t xo = (size_t)m * 512 + c8;
    *(uint4*)&xcat_hi[xo] = *(uint4*)h8;
    *(uint4*)&xcat_lo[xo] = *(uint4*)l8;
}

// ---------------- head ----------------
__global__ void head_kernel(const float* __restrict__ t2,
                            const float* __restrict__ Wm2, const float* __restrict__ bm2,
                            float* __restrict__ out, int tstep)
{
    int warp = (blockIdx.x * blockDim.x + threadIdx.x) >> 5;
    int lane = threadIdx.x & 31;
    if (warp >= MA_ROWS) return;
    float s0 = 0.0f, s1 = 0.0f;
    for (int k = lane; k < HH; k += 32) {
        float x = t2[warp * HH + k];
        s0 += x * Wm2[k];
        s1 += x * Wm2[HH + k];
    }
#pragma unroll
    for (int off = 16; off; off >>= 1) {
        s0 += __shfl_xor_sync(0xffffffffu, s0, off);
        s1 += __shfl_xor_sync(0xffffffffu, s1, off);
    }
    if (lane == 0) {
        out[((size_t)tstep * MA_ROWS + warp) * 2 + 0] = tanhf(s0 + bm2[0]) * 0.05f;
        out[((size_t)tstep * MA_ROWS + warp) * 2 + 1] = tanhf(s1 + bm2[1]) * 0.05f;
    }
}

// ---------------- host launcher ----------------
extern "C" void kernel_launch(void* const* d_in, const int* in_sizes, int n_in,
                              void* d_out, int out_size)
{
    const float* obs    = (const float*)d_in[0];
    const float* phys   = (const float*)d_in[1];
    const float* goals  = (const float*)d_in[2];
    const float* mem_p  = (const float*)d_in[3];
    const float* mem_a  = (const float*)d_in[4];
    const float* Wih_p  = (const float*)d_in[5];
    const float* Whh_p  = (const float*)d_in[6];
    const float* bih_p  = (const float*)d_in[7];
    const float* bhh_p  = (const float*)d_in[8];
    const float* Wfc_p  = (const float*)d_in[9];
    const float* bfc_p  = (const float*)d_in[10];
    const float* Wih_a  = (const float*)d_in[11];
    const float* Whh_a  = (const float*)d_in[12];
    const float* bih_a  = (const float*)d_in[13];
    const float* bhh_a  = (const float*)d_in[14];
    const float* Wfc_a  = (const float*)d_in[15];
    const float* bfc_a  = (const float*)d_in[16];
    const float* Wm1    = (const float*)d_in[17];
    const float* bm1    = (const float*)d_in[18];
    const float* Wm2    = (const float*)d_in[19];
    const float* bm2    = (const float*)d_in[20];
    float* out = (float*)d_out;

    void* p;
    __half *h_hi[2], *h_lo[2], *xc_hi[2], *xc_lo[2];
    cudaGetSymbolAddress(&p, g_h_hi);    h_hi[0] = (__half*)p; h_hi[1] = h_hi[0] + (size_t)MP_ROWS*HH;
    cudaGetSymbolAddress(&p, g_h_lo);    h_lo[0] = (__half*)p; h_lo[1] = h_lo[0] + (size_t)MP_ROWS*HH;
    cudaGetSymbolAddress(&p, g_xcat_hi); xc_hi[0] = (__half*)p; xc_hi[1] = xc_hi[0] + (size_t)MA_ROWS*512;
    cudaGetSymbolAddress(&p, g_xcat_lo); xc_lo[0] = (__half*)p; xc_lo[1] = xc_lo[0] + (size_t)MA_ROWS*512;
    cudaGetSymbolAddress(&p, g_proc_hi); __half* proc_hi = (__half*)p;
    cudaGetSymbolAddress(&p, g_proc_lo); __half* proc_lo = (__half*)p;
    cudaGetSymbolAddress(&p, g_t1_hi);   __half* t1_hi = (__half*)p;
    cudaGetSymbolAddress(&p, g_t1_lo);   __half* t1_lo = (__half*)p;
    cudaGetSymbolAddress(&p, g_t2);      float* t2 = (float*)p;
    cudaGetSymbolAddress(&p, g_xp8);     float* xp8 = (float*)p;
    cudaGetSymbolAddress(&p, g_xa4);     float* xa4 = (float*)p;
    cudaGetSymbolAddress(&p, g_Wp8);     float* Wp8 = (float*)p;
    cudaGetSymbolAddress(&p, g_Wa8);     float* Wa8 = (float*)p;
    cudaGetSymbolAddress(&p, g_Whhp);    __half* Whhp = (__half*)p;
    cudaGetSymbolAddress(&p, g_Wfcp);    __half* Wfcp = (__half*)p;
    cudaGetSymbolAddress(&p, g_Wcat);    __half* Wcat = (__half*)p;
    cudaGetSymbolAddress(&p, g_Wfca);    __half* Wfca = (__half*)p;
    cudaGetSymbolAddress(&p, g_Wm1);     __half* Wm1h = (__half*)p;

    const int SM_0_128 = (2*128*40 + 2*3*64*40) * 2;   // 51200
    const int SM_1_64  = (2*64*40  + 2*4*64*40) * 2;   // 51200
    const int SM_2_128 = (2*128*40 + 2*1*64*40) * 2;   // 30720
    const int SM_2_64  = (2*64*40  + 2*1*64*40) * 2;   // 20480
    cudaFuncSetAttribute((const void*)fused_kernel<0,128>, cudaFuncAttributeMaxDynamicSharedMemorySize, SM_0_128);
    cudaFuncSetAttribute((const void*)fused_kernel<1,64>,  cudaFuncAttributeMaxDynamicSharedMemorySize, SM_1_64);
    cudaFuncSetAttribute((const void*)fused_kernel<2,128>, cudaFuncAttributeMaxDynamicSharedMemorySize, SM_2_128);
    cudaFuncSetAttribute((const void*)fused_kernel<2,64>,  cudaFuncAttributeMaxDynamicSharedMemorySize, SM_2_64);

    // ---- one-time stream/event setup ----
    static cudaStream_t sA = nullptr, sB = nullptr;
    static cudaEvent_t evFork = nullptr, evJoinA = nullptr, evJoinB = nullptr;
    static cudaEvent_t evG[TT], evF[TT], evP[TT], evA[TT];
    if (sA == nullptr) {
        cudaStreamCreateWithFlags(&sA, cudaStreamNonBlocking);
        cudaStreamCreateWithFlags(&sB, cudaStreamNonBlocking);
        cudaEventCreateWithFlags(&evFork, cudaEventDisableTiming);
        cudaEventCreateWithFlags(&evJoinA, cudaEventDisableTiming);
        cudaEventCreateWithFlags(&evJoinB, cudaEventDisableTiming);
        for (int i = 0; i < TT; i++) {
            cudaEventCreateWithFlags(&evG[i], cudaEventDisableTiming);
            cudaEventCreateWithFlags(&evF[i], cudaEventDisableTiming);
            cudaEventCreateWithFlags(&evP[i], cudaEventDisableTiming);
            cudaEventCreateWithFlags(&evA[i], cudaEventDisableTiming);
        }
    }

    cudaStream_t s0 = 0;

    // ---- prep (stream 0) ----
    split_kernel<<<(MP_ROWS*HH + 255)/256, 256, 0, s0>>>(mem_p, h_hi[0], h_lo[0], MP_ROWS*HH);
    split_strided_kernel<<<(MA_ROWS*HH + 255)/256, 256, 0, s0>>>(mem_a, xc_hi[0] + 256, xc_lo[0] + 256, MA_ROWS, HH, 512);
    conv_kernel<<<(G3H*HH + 255)/256, 256, 0, s0>>>(Whh_p, Whhp, G3H*HH);
    conv_kernel<<<(HH*HH + 255)/256, 256, 0, s0>>>(Wfc_p, Wfcp, HH*HH);
    conv_kernel<<<(HH*HH + 255)/256, 256, 0, s0>>>(Wfc_a, Wfca, HH*HH);
    conv_kernel<<<(HH*HH + 255)/256, 256, 0, s0>>>(Wm1, Wm1h, HH*HH);
    build_wcat_kernel<<<(1024*512 + 255)/256, 256, 0, s0>>>(Wih_a, Whh_a, Wcat);
    prep_xp_kernel<<<(MP_ROWS + 255)/256, 256, 0, s0>>>(obs, phys, xp8);
    prep_wp8_kernel<<<(G3H + 255)/256, 256, 0, s0>>>(Wih_p, bih_p, bhh_p, Wp8);
    prep_xa_kernel<<<(MA_ROWS + 255)/256, 256, 0, s0>>>(goals, xa4);
    prep_wa8_kernel<<<(G3H + 255)/256, 256, 0, s0>>>(Wih_a, bih_a, bhh_a, Wa8);

    // fork both side streams off stream 0 (after prep)
    cudaEventRecord(evFork, s0);
    cudaStreamWaitEvent(sA, evFork, 0);
    cudaStreamWaitEvent(sB, evFork, 0);

    // ---- recurrence ----
    // s0 : gru_p(t) chain (the critical path).
    // sB : fc_p(t) + pool(t)  — concurrent with gru_p(t+1).
    // sA : action chain of step t — concurrent with everything downstream.
    // Hazards: gru_p(t) writes h buf (t+1)%2 which fc_p(t-2) reads -> wait evF[t-2].
    //          pool(t) writes xcat[t%2] feat cols read by gru_a(t-2) -> wait evA[t-2].
    int cur = 0;
    for (int t = 0; t < TT; t++) {
        int nxt = cur ^ 1;
        // ---- physical GRU on s0 ----
        if (t >= 2) cudaStreamWaitEvent(s0, evF[t - 2], 0);
        fused_kernel<0,128><<<dim3(MP_ROWS/128, 4), 256, SM_0_128, s0>>>(
            h_hi[cur], HH, Whhp, xp8, Wp8,
            h_hi[cur], h_lo[cur], HH,
            h_hi[nxt], h_lo[nxt], HH, nullptr);
        cudaEventRecord(evG[t], s0);

        // ---- fc_p + pool on sB ----
        cudaStreamWaitEvent(sB, evG[t], 0);
        fused_kernel<2,128><<<dim3(MP_ROWS/128, 4), 256, SM_2_128, sB>>>(
            h_hi[nxt], HH, Wfcp, bfc_p, nullptr,
            nullptr, nullptr, 0,
            proc_hi, proc_lo, HH, nullptr);
        cudaEventRecord(evF[t], sB);
        if (t >= 2) cudaStreamWaitEvent(sB, evA[t - 2], 0);
        pool_kernel<<<(MA_ROWS*32 + 255)/256, 256, 0, sB>>>(proc_hi, proc_lo, xc_hi[cur], xc_lo[cur]);
        cudaEventRecord(evP[t], sB);

        // ---- action chain on sA ----
        cudaStreamWaitEvent(sA, evP[t], 0);
        fused_kernel<1,64><<<dim3(MA_ROWS/64, 4), 256, SM_1_64, sA>>>(
            xc_hi[cur], 512, Wcat, xa4, Wa8,
            xc_hi[cur] + 256, xc_lo[cur] + 256, 512,
            xc_hi[nxt] + 256, xc_lo[nxt] + 256, 512, nullptr);
        cudaEventRecord(evA[t], sA);
        fused_kernel<2,64><<<dim3(MA_ROWS/64, 4), 256, SM_2_64, sA>>>(
            xc_hi[nxt] + 256, 512, Wfca, bfc_a, nullptr,
            nullptr, nullptr, 0,
            t1_hi, t1_lo, HH, nullptr);
        fused_kernel<2,64><<<dim3(MA_ROWS/64, 4), 256, SM_2_64, sA>>>(
            t1_hi, HH, Wm1h, bm1, nullptr,
            nullptr, nullptr, 0,
            nullptr, nullptr, 0, t2);
        head_kernel<<<(MA_ROWS*32 + 255)/256, 256, 0, sA>>>(t2, Wm2, bm2, out, t);
        cur = nxt;
    }

    // join side streams back into stream 0
    cudaEventRecord(evJoinA, sA);
    cudaStreamWaitEvent(s0, evJoinA, 0);
    cudaEventRecord(evJoinB, sB);
    cudaStreamWaitEvent(s0, evJoinB, 0);
}

// round 9
// speedup vs baseline: 5.4729x; 1.1649x over previous
#include <cuda_runtime.h>
#include <cuda_fp16.h>
#include <mma.h>
#include <math.h>
#include <stdint.h>

using namespace nvcuda;

#define BB 512
#define AA 4
#define EE 10
#define HH 256
#define TT 10
#define MP_ROWS (BB*AA*EE)   // 20480
#define MA_ROWS (BB*AA)      // 2048
#define G3H (3*HH)           // 768

// ---------------- scratch ----------------
__device__ __half g_h_hi[2][MP_ROWS * HH];
__device__ __half g_h_lo[2][MP_ROWS * HH];
__device__ __half g_xcat_hi[2][MA_ROWS * 512];   // [feat | ma]
__device__ __half g_xcat_lo[2][MA_ROWS * 512];
__device__ __half g_proc_hi[MP_ROWS * HH];
__device__ __half g_proc_lo[MP_ROWS * HH];
__device__ __half g_t1_hi[MA_ROWS * HH];
__device__ __half g_t1_lo[MA_ROWS * HH];
__device__ float g_t2[MA_ROWS * HH];
__device__ float g_xp8[MP_ROWS * 8];     // [ob0,ob1,ph0,ph1,ph2,0,0,0]
__device__ float g_xa4[MA_ROWS * 4];     // [g0,g1,g2,0]
__device__ float g_Wp8[G3H * 8];         // [w0..w4, bih, bhh, 0]
__device__ float g_Wa8[G3H * 8];         // [wg0..2, bih, bhh, 0,0,0]
__device__ __half g_Whhp[G3H * HH];
__device__ __half g_Wfcp[HH * HH];
__device__ __half g_Wcat[1024 * 512];
__device__ __half g_Wfca[HH * HH];
__device__ __half g_Wm1[HH * HH];

// ---------------- helpers ----------------
__device__ __forceinline__ float sigmoidf_(float x) { return 1.0f / (1.0f + __expf(-x)); }
__device__ __forceinline__ float eluf_(float x) { return x > 0.0f ? x : expm1f(x); }
__device__ __forceinline__ void split_fp16(float x, __half& hi, __half& lo) {
    hi = __float2half_rn(x);
    lo = __float2half_rn(x - __half2float(hi));
}
__device__ __forceinline__ void cp16(void* dst, const void* src) {
    unsigned d = (unsigned)__cvta_generic_to_shared(dst);
    asm volatile("cp.async.cg.shared.global [%0], [%1], 16;\n" :: "r"(d), "l"(src));
}
__device__ __forceinline__ void cp_commit() { asm volatile("cp.async.commit_group;\n" ::); }
template<int N> __device__ __forceinline__ void cp_wait() { asm volatile("cp.async.wait_group %0;\n" :: "n"(N)); }

// ---------------- prep kernels ----------------
__global__ void prep_xp_kernel(const float* __restrict__ obs, const float* __restrict__ phys,
                               float* __restrict__ xp8)
{
    int r = blockIdx.x * blockDim.x + threadIdx.x;
    if (r >= MP_ROWS) return;
    int b = r / (AA*EE);
    int e = r % EE;
    float* o = xp8 + r * 8;
    o[0] = obs[r*2+0]; o[1] = obs[r*2+1];
    const float* ph = phys + (b * EE + e) * 3;
    o[2] = ph[0]; o[3] = ph[1]; o[4] = ph[2];
    o[5] = 0.f; o[6] = 0.f; o[7] = 0.f;
}
__global__ void prep_wp8_kernel(const float* __restrict__ Wih, const float* __restrict__ bih,
                                const float* __restrict__ bhh, float* __restrict__ Wp8)
{
    int r = blockIdx.x * blockDim.x + threadIdx.x;
    if (r >= G3H) return;
    float* o = Wp8 + r * 8;
#pragma unroll
    for (int k = 0; k < 5; k++) o[k] = Wih[r*5+k];
    o[5] = bih[r]; o[6] = bhh[r]; o[7] = 0.f;
}
__global__ void prep_xa_kernel(const float* __restrict__ goals, float* __restrict__ xa4)
{
    int m = blockIdx.x * blockDim.x + threadIdx.x;
    if (m >= MA_ROWS) return;
    float* o = xa4 + m * 4;
    o[0] = goals[m*3+0]; o[1] = goals[m*3+1]; o[2] = goals[m*3+2]; o[3] = 0.f;
}
__global__ void prep_wa8_kernel(const float* __restrict__ Wih, const float* __restrict__ bih,
                                const float* __restrict__ bhh, float* __restrict__ Wa8)
{
    int r = blockIdx.x * blockDim.x + threadIdx.x;
    if (r >= G3H) return;
    float* o = Wa8 + r * 8;
    o[0] = Wih[r*259+256]; o[1] = Wih[r*259+257]; o[2] = Wih[r*259+258];
    o[3] = bih[r]; o[4] = bhh[r]; o[5] = 0.f; o[6] = 0.f; o[7] = 0.f;
}
__global__ void split_kernel(const float* __restrict__ src,
                             __half* __restrict__ hi, __half* __restrict__ lo, int n)
{
    int i = blockIdx.x * blockDim.x + threadIdx.x;
    if (i >= n) return;
    split_fp16(src[i], hi[i], lo[i]);
}
__global__ void split_strided_kernel(const float* __restrict__ src,
                                     __half* __restrict__ hi, __half* __restrict__ lo,
                                     int rows, int cols, int ldo)
{
    int i = blockIdx.x * blockDim.x + threadIdx.x;
    if (i >= rows * cols) return;
    int r = i / cols, c = i - r * cols;
    split_fp16(src[i], hi[r * ldo + c], lo[r * ldo + c]);
}
__global__ void conv_kernel(const float* __restrict__ src, __half* __restrict__ dst, int n)
{
    int i = blockIdx.x * blockDim.x + threadIdx.x;
    if (i >= n) return;
    dst[i] = __float2half_rn(src[i]);
}
// Wcat [1024, 512]: rows g*256+n. g=0:[Wih_r|Whh_r] g=1:[Wih_z|Whh_z] g=2:[Wih_n|0] g=3:[0|Whh_n]
__global__ void build_wcat_kernel(const float* __restrict__ Wih,  // [768,259]
                                  const float* __restrict__ Whh,  // [768,256]
                                  __half* __restrict__ Wcat)
{
    int idx = blockIdx.x * blockDim.x + threadIdx.x;
    if (idx >= 1024 * 512) return;
    int row = idx >> 9, col = idx & 511;
    int g = row >> 8, n = row & 255;
    float v = 0.0f;
    if (g < 2) {
        v = (col < 256) ? Wih[(g * 256 + n) * 259 + col] : Whh[(g * 256 + n) * 256 + (col - 256)];
    } else if (g == 2) {
        if (col < 256) v = Wih[(512 + n) * 259 + col];
    } else {
        if (col >= 256) v = Whh[(512 + n) * 256 + (col - 256)];
    }
    Wcat[idx] = __float2half_rn(v);
}

// ---------------- fused fp16 single-pass GEMM kernel (BK=64) ----------------
// MODE 0: physical GRU  (NSEG=3, K=256), MODE 1: action GRU (NSEG=4, K=512),
// MODE 2: ELU layer     (NSEG=1, K=256).
template<int MODE, int BM>
__global__ __launch_bounds__(256) void fused_kernel(
    const __half* __restrict__ Ahi, int lda,
    const __half* __restrict__ B,
    const float* __restrict__ xw,     // xp8 / xa4 / bias
    const float* __restrict__ swg,    // Wp8 / Wa8 / unused
    const __half* __restrict__ oldHi, const __half* __restrict__ oldLo, int oldLd,
    __half* __restrict__ Ohi, __half* __restrict__ Olo, int ldo,
    float* __restrict__ Ofp)
{
    constexpr int NSEG = (MODE == 0) ? 3 : ((MODE == 1) ? 4 : 1);
    constexpr int K = (MODE == 1) ? 512 : 256;
    constexpr int KT = K / 64;              // 64-wide k-chunks
    constexpr int MI = BM / 64;
    constexpr int STR = 72;                 // smem row stride in halfs (144B, 16B-aligned)
    constexpr int AITER = BM / 32;          // A 16B chunks per thread (BM*8/256)
    constexpr int AHS = BM * STR;
    constexpr int BHS = NSEG * 64 * STR;

    extern __shared__ __align__(16) char smem_raw[];
    __half* sm = (__half*)smem_raw;
    __half* sAh[2] = { sm,           sm + AHS };
    __half* sB[2]  = { sm + 2*AHS,   sm + 2*AHS + BHS };

    const int m0 = blockIdx.x * BM;
    const int n0 = blockIdx.y * 64;
    const int tid = threadIdx.x;
    const int wid = tid >> 5;
    const int lane = tid & 31;
    const int wm = wid >> 1, wn = wid & 1;

    auto load_tile = [&](int s, int kt) {
        const int k0 = kt * 64;
#pragma unroll
        for (int r = 0; r < AITER; r++) {
            int c = tid + r * 256;
            int row = c >> 3, kk = (c & 7) * 8;
            cp16(sAh[s] + row * STR + kk, Ahi + (size_t)(m0 + row) * lda + k0 + kk);
        }
#pragma unroll
        for (int r = 0; r < NSEG * 2; r++) {
            int c = tid + r * 256;
            int srow = c >> 3, kk = (c & 7) * 8;
            int srcrow = (MODE == 2) ? (n0 + srow) : ((srow >> 6) * 256 + n0 + (srow & 63));
            cp16(sB[s] + srow * STR + kk, B + (size_t)srcrow * K + k0 + kk);
        }
    };

    wmma::fragment<wmma::accumulator, 16, 16, 16, float> acc[NSEG][MI][2];
#pragma unroll
    for (int g = 0; g < NSEG; g++)
#pragma unroll
        for (int i = 0; i < MI; i++)
#pragma unroll
            for (int j = 0; j < 2; j++) wmma::fill_fragment(acc[g][i][j], 0.0f);

    load_tile(0, 0); cp_commit();
    if (KT > 1) { load_tile(1, 1); cp_commit(); }

    for (int kt = 0; kt < KT; kt++) {
        if (kt == KT - 1) cp_wait<0>(); else cp_wait<1>();
        __syncthreads();
        const int s = kt & 1;
#pragma unroll
        for (int kc = 0; kc < 64; kc += 16) {
            wmma::fragment<wmma::matrix_a, 16, 16, 16, __half, wmma::row_major> ah[MI];
#pragma unroll
            for (int i = 0; i < MI; i++)
                wmma::load_matrix_sync(ah[i], sAh[s] + (wm * 16 * MI + i * 16) * STR + kc, STR);
#pragma unroll
            for (int g = 0; g < NSEG; g++) {
                wmma::fragment<wmma::matrix_b, 16, 16, 16, __half, wmma::col_major> b[2];
#pragma unroll
                for (int j = 0; j < 2; j++)
                    wmma::load_matrix_sync(b[j], sB[s] + (g * 64 + wn * 32 + j * 16) * STR + kc, STR);
#pragma unroll
                for (int i = 0; i < MI; i++)
#pragma unroll
                    for (int j = 0; j < 2; j++)
                        wmma::mma_sync(acc[g][i][j], ah[i], b[j], acc[g][i][j]);
            }
        }
        __syncthreads();
        if (kt + 2 < KT) { load_tile(kt & 1, kt + 2); cp_commit(); }
    }

    // ---------------- epilogue ----------------
    float* wbuf = (float*)smem_raw;
    float* sX = wbuf + 8 * NSEG * 320;
    constexpr int XW = (MODE == 1) ? 4 : 8;
    float* sW = sX + BM * XW;

    if (MODE != 2) {
#pragma unroll
        for (int r = 0; r < (BM * XW + 255) / 256; r++) {
            int c = tid + r * 256;
            if (c < BM * XW) sX[c] = xw[(size_t)(m0 + (c / XW)) * XW + (c % XW)];
        }
#pragma unroll
        for (int r = 0; r < 6; r++) {
            int c = tid + r * 256;
            int srow = c >> 3, k = c & 7;
            sW[c] = swg[(size_t)((srow >> 6) * 256 + n0 + (srow & 63)) * 8 + k];
        }
    }
    __syncthreads();

    float* wb = wbuf + wid * NSEG * 320;
    const int r_ = lane >> 1;
    const int c0_ = (lane & 1) * 8;

#pragma unroll
    for (int i = 0; i < MI; i++) {
#pragma unroll
        for (int j = 0; j < 2; j++) {
#pragma unroll
            for (int g = 0; g < NSEG; g++)
                wmma::store_matrix_sync(wb + g * 320, acc[g][i][j], 20, wmma::mem_row_major);
            __syncwarp();

            const int mloc = wm * 16 * MI + i * 16 + r_;
            const int m = m0 + mloc;
            const int nl0 = wn * 32 + j * 16 + c0_;
            const int nabs = n0 + nl0;

            __half oh8[8], ol8[8];

            if (MODE == 2) {
                float4 b0 = *(const float4*)&xw[nabs];
                float4 b1 = *(const float4*)&xw[nabs + 4];
                float bia[8] = {b0.x,b0.y,b0.z,b0.w,b1.x,b1.y,b1.z,b1.w};
                float ov[8];
#pragma unroll
                for (int cc = 0; cc < 8; cc++) {
                    float v = eluf_(wb[r_ * 20 + c0_ + cc] + bia[cc]);
                    ov[cc] = v;
                    split_fp16(v, oh8[cc], ol8[cc]);
                }
                if (Ofp) {
                    *(float4*)&Ofp[(size_t)m * 256 + nabs] = make_float4(ov[0],ov[1],ov[2],ov[3]);
                    *(float4*)&Ofp[(size_t)m * 256 + nabs + 4] = make_float4(ov[4],ov[5],ov[6],ov[7]);
                }
                if (Ohi) {
                    *(uint4*)&Ohi[(size_t)m * ldo + nabs] = *(uint4*)oh8;
                    *(uint4*)&Olo[(size_t)m * ldo + nabs] = *(uint4*)ol8;
                }
            } else {
                uint4 hv4 = *(const uint4*)&oldHi[(size_t)m * oldLd + nabs];
                uint4 lv4 = *(const uint4*)&oldLo[(size_t)m * oldLd + nabs];
                const __half* hvp = (const __half*)&hv4;
                const __half* lvp = (const __half*)&lv4;
                float xr[XW];
#pragma unroll
                for (int k = 0; k < XW; k++) xr[k] = sX[mloc * XW + k];
#pragma unroll
                for (int cc = 0; cc < 8; cc++) {
                    int nl = nl0 + cc;
                    const float* w0 = sW + (0 * 64 + nl) * 8;
                    const float* w1 = sW + (1 * 64 + nl) * 8;
                    const float* w2 = sW + (2 * 64 + nl) * 8;
                    float a0 = wb[0 * 320 + r_ * 20 + c0_ + cc];
                    float a1 = wb[1 * 320 + r_ * 20 + c0_ + cc];
                    float a2 = wb[2 * 320 + r_ * 20 + c0_ + cc];
                    float gi_r, gi_z, gi_n, rr, zz, nn;
                    if (MODE == 0) {
                        gi_r = w0[5]; gi_z = w1[5]; gi_n = w2[5];
#pragma unroll
                        for (int k = 0; k < 5; k++) {
                            gi_r += xr[k] * w0[k];
                            gi_z += xr[k] * w1[k];
                            gi_n += xr[k] * w2[k];
                        }
                        rr = sigmoidf_(gi_r + a0 + w0[6]);
                        zz = sigmoidf_(gi_z + a1 + w1[6]);
                        nn = tanhf(gi_n + rr * (a2 + w2[6]));
                    } else {
                        float a3 = wb[3 * 320 + r_ * 20 + c0_ + cc];
                        gi_r = w0[3]; gi_z = w1[3]; gi_n = w2[3];
#pragma unroll
                        for (int k = 0; k < 3; k++) {
                            gi_r += xr[k] * w0[k];
                            gi_z += xr[k] * w1[k];
                            gi_n += xr[k] * w2[k];
                        }
                        rr = sigmoidf_(gi_r + a0 + w0[4]);
                        zz = sigmoidf_(gi_z + a1 + w1[4]);
                        nn = tanhf(gi_n + a2 + rr * (a3 + w2[4]));
                    }
                    float hold = __half2float(hvp[cc]) + __half2float(lvp[cc]);
                    float hnew = (1.0f - zz) * nn + zz * hold;
                    split_fp16(hnew, oh8[cc], ol8[cc]);
                }
                *(uint4*)&Ohi[(size_t)m * ldo + nabs] = *(uint4*)oh8;
                *(uint4*)&Olo[(size_t)m * ldo + nabs] = *(uint4*)ol8;
            }
            __syncwarp();
        }
    }
}

// ---------------- entity max-pool ----------------
__global__ void pool_kernel(const __half* __restrict__ phi,
                            const __half* __restrict__ plo,
                            __half* __restrict__ xcat_hi,
                            __half* __restrict__ xcat_lo)
{
    int idx = blockIdx.x * blockDim.x + threadIdx.x;
    if (idx >= MA_ROWS * 32) return;
    int m = idx >> 5, c8 = (idx & 31) * 8;
    float v[8];
#pragma unroll
    for (int k = 0; k < 8; k++) v[k] = -1e30f;
#pragma unroll
    for (int e = 0; e < EE; e++) {
        size_t off = (size_t)(m * EE + e) * HH + c8;
        uint4 h4 = *(const uint4*)&phi[off];
        uint4 l4 = *(const uint4*)&plo[off];
        const __half* hp = (const __half*)&h4;
        const __half* lp = (const __half*)&l4;
#pragma unroll
        for (int k = 0; k < 8; k++)
            v[k] = fmaxf(v[k], __half2float(hp[k]) + __half2float(lp[k]));
    }
    __half h8[8], l8[8];
#pragma unroll
    for (int k = 0; k < 8; k++) split_fp16(v[k], h8[k], l8[k]);
    size_t xo = (size_t)m * 512 + c8;
    *(uint4*)&xcat_hi[xo] = *(uint4*)h8;
    *(uint4*)&xcat_lo[xo] = *(uint4*)l8;
}

// ---------------- head ----------------
__global__ void head_kernel(const float* __restrict__ t2,
                            const float* __restrict__ Wm2, const float* __restrict__ bm2,
                            float* __restrict__ out, int tstep)
{
    int warp = (blockIdx.x * blockDim.x + threadIdx.x) >> 5;
    int lane = threadIdx.x & 31;
    if (warp >= MA_ROWS) return;
    float s0 = 0.0f, s1 = 0.0f;
    for (int k = lane; k < HH; k += 32) {
        float x = t2[warp * HH + k];
        s0 += x * Wm2[k];
        s1 += x * Wm2[HH + k];
    }
#pragma unroll
    for (int off = 16; off; off >>= 1) {
        s0 += __shfl_xor_sync(0xffffffffu, s0, off);
        s1 += __shfl_xor_sync(0xffffffffu, s1, off);
    }
    if (lane == 0) {
        out[((size_t)tstep * MA_ROWS + warp) * 2 + 0] = tanhf(s0 + bm2[0]) * 0.05f;
        out[((size_t)tstep * MA_ROWS + warp) * 2 + 1] = tanhf(s1 + bm2[1]) * 0.05f;
    }
}

// ---------------- host launcher ----------------
extern "C" void kernel_launch(void* const* d_in, const int* in_sizes, int n_in,
                              void* d_out, int out_size)
{
    const float* obs    = (const float*)d_in[0];
    const float* phys   = (const float*)d_in[1];
    const float* goals  = (const float*)d_in[2];
    const float* mem_p  = (const float*)d_in[3];
    const float* mem_a  = (const float*)d_in[4];
    const float* Wih_p  = (const float*)d_in[5];
    const float* Whh_p  = (const float*)d_in[6];
    const float* bih_p  = (const float*)d_in[7];
    const float* bhh_p  = (const float*)d_in[8];
    const float* Wfc_p  = (const float*)d_in[9];
    const float* bfc_p  = (const float*)d_in[10];
    const float* Wih_a  = (const float*)d_in[11];
    const float* Whh_a  = (const float*)d_in[12];
    const float* bih_a  = (const float*)d_in[13];
    const float* bhh_a  = (const float*)d_in[14];
    const float* Wfc_a  = (const float*)d_in[15];
    const float* bfc_a  = (const float*)d_in[16];
    const float* Wm1    = (const float*)d_in[17];
    const float* bm1    = (const float*)d_in[18];
    const float* Wm2    = (const float*)d_in[19];
    const float* bm2    = (const float*)d_in[20];
    float* out = (float*)d_out;

    void* p;
    __half *h_hi[2], *h_lo[2], *xc_hi[2], *xc_lo[2];
    cudaGetSymbolAddress(&p, g_h_hi);    h_hi[0] = (__half*)p; h_hi[1] = h_hi[0] + (size_t)MP_ROWS*HH;
    cudaGetSymbolAddress(&p, g_h_lo);    h_lo[0] = (__half*)p; h_lo[1] = h_lo[0] + (size_t)MP_ROWS*HH;
    cudaGetSymbolAddress(&p, g_xcat_hi); xc_hi[0] = (__half*)p; xc_hi[1] = xc_hi[0] + (size_t)MA_ROWS*512;
    cudaGetSymbolAddress(&p, g_xcat_lo); xc_lo[0] = (__half*)p; xc_lo[1] = xc_lo[0] + (size_t)MA_ROWS*512;
    cudaGetSymbolAddress(&p, g_proc_hi); __half* proc_hi = (__half*)p;
    cudaGetSymbolAddress(&p, g_proc_lo); __half* proc_lo = (__half*)p;
    cudaGetSymbolAddress(&p, g_t1_hi);   __half* t1_hi = (__half*)p;
    cudaGetSymbolAddress(&p, g_t1_lo);   __half* t1_lo = (__half*)p;
    cudaGetSymbolAddress(&p, g_t2);      float* t2 = (float*)p;
    cudaGetSymbolAddress(&p, g_xp8);     float* xp8 = (float*)p;
    cudaGetSymbolAddress(&p, g_xa4);     float* xa4 = (float*)p;
    cudaGetSymbolAddress(&p, g_Wp8);     float* Wp8 = (float*)p;
    cudaGetSymbolAddress(&p, g_Wa8);     float* Wa8 = (float*)p;
    cudaGetSymbolAddress(&p, g_Whhp);    __half* Whhp = (__half*)p;
    cudaGetSymbolAddress(&p, g_Wfcp);    __half* Wfcp = (__half*)p;
    cudaGetSymbolAddress(&p, g_Wcat);    __half* Wcat = (__half*)p;
    cudaGetSymbolAddress(&p, g_Wfca);    __half* Wfca = (__half*)p;
    cudaGetSymbolAddress(&p, g_Wm1);     __half* Wm1h = (__half*)p;

    // smem: (2*BM*72 + 2*NSEG*64*72) * 2 bytes
    const int SM_0_128 = (2*128*72 + 2*3*64*72) * 2;   // 92160
    const int SM_1_64  = (2*64*72  + 2*4*64*72) * 2;   // 92160
    const int SM_2_128 = (2*128*72 + 2*1*64*72) * 2;   // 55296
    const int SM_2_64  = (2*64*72  + 2*1*64*72) * 2;   // 36864
    cudaFuncSetAttribute((const void*)fused_kernel<0,128>, cudaFuncAttributeMaxDynamicSharedMemorySize, SM_0_128);
    cudaFuncSetAttribute((const void*)fused_kernel<1,64>,  cudaFuncAttributeMaxDynamicSharedMemorySize, SM_1_64);
    cudaFuncSetAttribute((const void*)fused_kernel<2,128>, cudaFuncAttributeMaxDynamicSharedMemorySize, SM_2_128);
    cudaFuncSetAttribute((const void*)fused_kernel<2,64>,  cudaFuncAttributeMaxDynamicSharedMemorySize, SM_2_64);

    // ---- one-time stream/event setup ----
    static cudaStream_t sA = nullptr, sB = nullptr;
    static cudaEvent_t evFork = nullptr, evJoinA = nullptr, evJoinB = nullptr;
    static cudaEvent_t evG[TT], evF[TT], evP[TT], evA[TT];
    if (sA == nullptr) {
        cudaStreamCreateWithFlags(&sA, cudaStreamNonBlocking);
        cudaStreamCreateWithFlags(&sB, cudaStreamNonBlocking);
        cudaEventCreateWithFlags(&evFork, cudaEventDisableTiming);
        cudaEventCreateWithFlags(&evJoinA, cudaEventDisableTiming);
        cudaEventCreateWithFlags(&evJoinB, cudaEventDisableTiming);
        for (int i = 0; i < TT; i++) {
            cudaEventCreateWithFlags(&evG[i], cudaEventDisableTiming);
            cudaEventCreateWithFlags(&evF[i], cudaEventDisableTiming);
            cudaEventCreateWithFlags(&evP[i], cudaEventDisableTiming);
            cudaEventCreateWithFlags(&evA[i], cudaEventDisableTiming);
        }
    }

    cudaStream_t s0 = 0;

    // ---- prep, ordered so the 6th launch is the REAL gru_p(t=0) (ncu -s 5 -c 1 profiles it) ----
    split_kernel<<<(MP_ROWS*HH + 255)/256, 256, 0, s0>>>(mem_p, h_hi[0], h_lo[0], MP_ROWS*HH);   // 1
    conv_kernel<<<(G3H*HH + 255)/256, 256, 0, s0>>>(Whh_p, Whhp, G3H*HH);                         // 2
    prep_xp_kernel<<<(MP_ROWS + 255)/256, 256, 0, s0>>>(obs, phys, xp8);                          // 3
    prep_wp8_kernel<<<(G3H + 255)/256, 256, 0, s0>>>(Wih_p, bih_p, bhh_p, Wp8);                   // 4
    split_strided_kernel<<<(MA_ROWS*HH + 255)/256, 256, 0, s0>>>(mem_a, xc_hi[0] + 256, xc_lo[0] + 256, MA_ROWS, HH, 512); // 5
    // 6: gru_p(t=0): h[1] = GRU(h[0])
    fused_kernel<0,128><<<dim3(MP_ROWS/128, 4), 256, SM_0_128, s0>>>(
        h_hi[0], HH, Whhp, xp8, Wp8,
        h_hi[0], h_lo[0], HH,
        h_hi[1], h_lo[1], HH, nullptr);
    // remaining prep (independent of gru_p)
    conv_kernel<<<(HH*HH + 255)/256, 256, 0, s0>>>(Wfc_p, Wfcp, HH*HH);
    conv_kernel<<<(HH*HH + 255)/256, 256, 0, s0>>>(Wfc_a, Wfca, HH*HH);
    conv_kernel<<<(HH*HH + 255)/256, 256, 0, s0>>>(Wm1, Wm1h, HH*HH);
    build_wcat_kernel<<<(1024*512 + 255)/256, 256, 0, s0>>>(Wih_a, Whh_a, Wcat);
    prep_xa_kernel<<<(MA_ROWS + 255)/256, 256, 0, s0>>>(goals, xa4);
    prep_wa8_kernel<<<(G3H + 255)/256, 256, 0, s0>>>(Wih_a, bih_a, bhh_a, Wa8);

    cudaEventRecord(evFork, s0);
    cudaStreamWaitEvent(sA, evFork, 0);
    cudaStreamWaitEvent(sB, evFork, 0);

    // ---- recurrence (gru_p(0) already issued above) ----
    int cur = 0;
    for (int t = 0; t < TT; t++) {
        int nxt = cur ^ 1;
        // ---- physical GRU on s0 ----
        if (t > 0) {
            if (t >= 2) cudaStreamWaitEvent(s0, evF[t - 2], 0);
            fused_kernel<0,128><<<dim3(MP_ROWS/128, 4), 256, SM_0_128, s0>>>(
                h_hi[cur], HH, Whhp, xp8, Wp8,
                h_hi[cur], h_lo[cur], HH,
                h_hi[nxt], h_lo[nxt], HH, nullptr);
        }
        cudaEventRecord(evG[t], s0);

        // ---- fc_p + pool on sB ----
        cudaStreamWaitEvent(sB, evG[t], 0);
        fused_kernel<2,128><<<dim3(MP_ROWS/128, 4), 256, SM_2_128, sB>>>(
            h_hi[nxt], HH, Wfcp, bfc_p, nullptr,
            nullptr, nullptr, 0,
            proc_hi, proc_lo, HH, nullptr);
        cudaEventRecord(evF[t], sB);
        if (t >= 2) cudaStreamWaitEvent(sB, evA[t - 2], 0);
        pool_kernel<<<(MA_ROWS*32 + 255)/256, 256, 0, sB>>>(proc_hi, proc_lo, xc_hi[cur], xc_lo[cur]);
        cudaEventRecord(evP[t], sB);

        // ---- action chain on sA ----
        cudaStreamWaitEvent(sA, evP[t], 0);
        fused_kernel<1,64><<<dim3(MA_ROWS/64, 4), 256, SM_1_64, sA>>>(
            xc_hi[cur], 512, Wcat, xa4, Wa8,
            xc_hi[cur] + 256, xc_lo[cur] + 256, 512,
            xc_hi[nxt] + 256, xc_lo[nxt] + 256, 512, nullptr);
        cudaEventRecord(evA[t], sA);
        fused_kernel<2,64><<<dim3(MA_ROWS/64, 4), 256, SM_2_64, sA>>>(
            xc_hi[nxt] + 256, 512, Wfca, bfc_a, nullptr,
            nullptr, nullptr, 0,
            t1_hi, t1_lo, HH, nullptr);
        fused_kernel<2,64><<<dim3(MA_ROWS/64, 4), 256, SM_2_64, sA>>>(
            t1_hi, HH, Wm1h, bm1, nullptr,
            nullptr, nullptr, 0,
            nullptr, nullptr, 0, t2);
        head_kernel<<<(MA_ROWS*32 + 255)/256, 256, 0, sA>>>(t2, Wm2, bm2, out, t);
        cur = nxt;
    }

    // join side streams back into stream 0
    cudaEventRecord(evJoinA, sA);
    cudaStreamWaitEvent(s0, evJoinA, 0);
    cudaEventRecord(evJoinB, sB);
    cudaStreamWaitEvent(s0, evJoinB, 0);
}

// round 10
// speedup vs baseline: 5.8447x; 1.0679x over previous
#include <cuda_runtime.h>
#include <cuda_fp16.h>
#include <mma.h>
#include <math.h>
#include <stdint.h>

using namespace nvcuda;

#define BB 512
#define AA 4
#define EE 10
#define HH 256
#define TT 10
#define MP_ROWS (BB*AA*EE)   // 20480
#define MA_ROWS (BB*AA)      // 2048
#define G3H (3*HH)           // 768

// ---------------- scratch ----------------
__device__ __half g_h_hi[2][MP_ROWS * HH];
__device__ __half g_h_lo[2][MP_ROWS * HH];
__device__ __half g_xcat_hi[2][MA_ROWS * 512];   // [feat | ma]
__device__ __half g_xcat_lo[2][MA_ROWS * 512];
__device__ __half g_proc_hi[MP_ROWS * HH];
__device__ __half g_t1_hi[MA_ROWS * HH];
__device__ float g_t2[MA_ROWS * HH];
__device__ float g_xp8[MP_ROWS * 8];     // [ob0,ob1,ph0,ph1,ph2,0,0,0]
__device__ float g_xa4[MA_ROWS * 4];     // [g0,g1,g2,0]
__device__ float g_Wp8[G3H * 8];         // [w0..w4, bih, bhh, 0]
__device__ float g_Wa8[G3H * 8];         // [wg0..2, bih, bhh, 0,0,0]
__device__ __half g_Whhp[G3H * HH];
__device__ __half g_Wfcp[HH * HH];
__device__ __half g_Wcat[1024 * 512];
__device__ __half g_Wfca[HH * HH];
__device__ __half g_Wm1[HH * HH];

// ---------------- helpers ----------------
__device__ __forceinline__ float fsig(float x) {
    float e = __expf(-x);
    return __fdividef(1.0f, 1.0f + e);
}
__device__ __forceinline__ float ftanh_(float x) {
    float xc = fmaxf(fminf(x, 15.0f), -15.0f);
    float e = __expf(-2.0f * xc);
    return __fdividef(1.0f - e, 1.0f + e);
}
__device__ __forceinline__ float eluf_(float x) { return x > 0.0f ? x : expm1f(x); }
__device__ __forceinline__ void split_fp16(float x, __half& hi, __half& lo) {
    hi = __float2half_rn(x);
    lo = __float2half_rn(x - __half2float(hi));
}
__device__ __forceinline__ void cp16(void* dst, const void* src) {
    unsigned d = (unsigned)__cvta_generic_to_shared(dst);
    asm volatile("cp.async.cg.shared.global [%0], [%1], 16;\n" :: "r"(d), "l"(src));
}
__device__ __forceinline__ void cp_commit() { asm volatile("cp.async.commit_group;\n" ::); }
template<int N> __device__ __forceinline__ void cp_wait() { asm volatile("cp.async.wait_group %0;\n" :: "n"(N)); }

// ---------------- prep kernels ----------------
__global__ void prep_xp_kernel(const float* __restrict__ obs, const float* __restrict__ phys,
                               float* __restrict__ xp8)
{
    int r = blockIdx.x * blockDim.x + threadIdx.x;
    if (r >= MP_ROWS) return;
    int b = r / (AA*EE);
    int e = r % EE;
    float* o = xp8 + r * 8;
    o[0] = obs[r*2+0]; o[1] = obs[r*2+1];
    const float* ph = phys + (b * EE + e) * 3;
    o[2] = ph[0]; o[3] = ph[1]; o[4] = ph[2];
    o[5] = 0.f; o[6] = 0.f; o[7] = 0.f;
}
__global__ void prep_wp8_kernel(const float* __restrict__ Wih, const float* __restrict__ bih,
                                const float* __restrict__ bhh, float* __restrict__ Wp8)
{
    int r = blockIdx.x * blockDim.x + threadIdx.x;
    if (r >= G3H) return;
    float* o = Wp8 + r * 8;
#pragma unroll
    for (int k = 0; k < 5; k++) o[k] = Wih[r*5+k];
    o[5] = bih[r]; o[6] = bhh[r]; o[7] = 0.f;
}
__global__ void prep_xa_kernel(const float* __restrict__ goals, float* __restrict__ xa4)
{
    int m = blockIdx.x * blockDim.x + threadIdx.x;
    if (m >= MA_ROWS) return;
    float* o = xa4 + m * 4;
    o[0] = goals[m*3+0]; o[1] = goals[m*3+1]; o[2] = goals[m*3+2]; o[3] = 0.f;
}
__global__ void prep_wa8_kernel(const float* __restrict__ Wih, const float* __restrict__ bih,
                                const float* __restrict__ bhh, float* __restrict__ Wa8)
{
    int r = blockIdx.x * blockDim.x + threadIdx.x;
    if (r >= G3H) return;
    float* o = Wa8 + r * 8;
    o[0] = Wih[r*259+256]; o[1] = Wih[r*259+257]; o[2] = Wih[r*259+258];
    o[3] = bih[r]; o[4] = bhh[r]; o[5] = 0.f; o[6] = 0.f; o[7] = 0.f;
}
__global__ void split_kernel(const float* __restrict__ src,
                             __half* __restrict__ hi, __half* __restrict__ lo, int n)
{
    int i = blockIdx.x * blockDim.x + threadIdx.x;
    if (i >= n) return;
    split_fp16(src[i], hi[i], lo[i]);
}
__global__ void split_strided_kernel(const float* __restrict__ src,
                                     __half* __restrict__ hi, __half* __restrict__ lo,
                                     int rows, int cols, int ldo)
{
    int i = blockIdx.x * blockDim.x + threadIdx.x;
    if (i >= rows * cols) return;
    int r = i / cols, c = i - r * cols;
    split_fp16(src[i], hi[r * ldo + c], lo[r * ldo + c]);
}
__global__ void conv_kernel(const float* __restrict__ src, __half* __restrict__ dst, int n)
{
    int i = blockIdx.x * blockDim.x + threadIdx.x;
    if (i >= n) return;
    dst[i] = __float2half_rn(src[i]);
}
// Wcat [1024, 512]: rows g*256+n. g=0:[Wih_r|Whh_r] g=1:[Wih_z|Whh_z] g=2:[Wih_n|0] g=3:[0|Whh_n]
__global__ void build_wcat_kernel(const float* __restrict__ Wih,  // [768,259]
                                  const float* __restrict__ Whh,  // [768,256]
                                  __half* __restrict__ Wcat)
{
    int idx = blockIdx.x * blockDim.x + threadIdx.x;
    if (idx >= 1024 * 512) return;
    int row = idx >> 9, col = idx & 511;
    int g = row >> 8, n = row & 255;
    float v = 0.0f;
    if (g < 2) {
        v = (col < 256) ? Wih[(g * 256 + n) * 259 + col] : Whh[(g * 256 + n) * 256 + (col - 256)];
    } else if (g == 2) {
        if (col < 256) v = Wih[(512 + n) * 259 + col];
    } else {
        if (col >= 256) v = Whh[(512 + n) * 256 + (col - 256)];
    }
    Wcat[idx] = __float2half_rn(v);
}

// ---------------- fused fp16 single-pass GEMM kernel (BK=64) ----------------
// MODE 0: physical GRU  (NSEG=3, K=256), MODE 1: action GRU (NSEG=4, K=512),
// MODE 2: ELU layer     (NSEG=1, K=256).
template<int MODE, int BM>
__global__ __launch_bounds__(256) void fused_kernel(
    const __half* __restrict__ Ahi, int lda,
    const __half* __restrict__ B,
    const float* __restrict__ xw,     // xp8 / xa4 / bias
    const float* __restrict__ swg,    // Wp8 / Wa8 / unused
    const __half* __restrict__ oldHi, const __half* __restrict__ oldLo, int oldLd,
    __half* __restrict__ Ohi, __half* __restrict__ Olo, int ldo,
    float* __restrict__ Ofp)
{
    constexpr int NSEG = (MODE == 0) ? 3 : ((MODE == 1) ? 4 : 1);
    constexpr int K = (MODE == 1) ? 512 : 256;
    constexpr int KT = K / 64;
    constexpr int MI = BM / 64;
    constexpr int STR = 72;
    constexpr int AITER = BM / 32;
    constexpr int AHS = BM * STR;
    constexpr int BHS = NSEG * 64 * STR;

    extern __shared__ __align__(16) char smem_raw[];
    __half* sm = (__half*)smem_raw;
    __half* sAh[2] = { sm,           sm + AHS };
    __half* sB[2]  = { sm + 2*AHS,   sm + 2*AHS + BHS };

    const int m0 = blockIdx.x * BM;
    const int n0 = blockIdx.y * 64;
    const int tid = threadIdx.x;
    const int wid = tid >> 5;
    const int lane = tid & 31;
    const int wm = wid >> 1, wn = wid & 1;

    auto load_tile = [&](int s, int kt) {
        const int k0 = kt * 64;
#pragma unroll
        for (int r = 0; r < AITER; r++) {
            int c = tid + r * 256;
            int row = c >> 3, kk = (c & 7) * 8;
            cp16(sAh[s] + row * STR + kk, Ahi + (size_t)(m0 + row) * lda + k0 + kk);
        }
#pragma unroll
        for (int r = 0; r < NSEG * 2; r++) {
            int c = tid + r * 256;
            int srow = c >> 3, kk = (c & 7) * 8;
            int srcrow = (MODE == 2) ? (n0 + srow) : ((srow >> 6) * 256 + n0 + (srow & 63));
            cp16(sB[s] + srow * STR + kk, B + (size_t)srcrow * K + k0 + kk);
        }
    };

    wmma::fragment<wmma::accumulator, 16, 16, 16, float> acc[NSEG][MI][2];
#pragma unroll
    for (int g = 0; g < NSEG; g++)
#pragma unroll
        for (int i = 0; i < MI; i++)
#pragma unroll
            for (int j = 0; j < 2; j++) wmma::fill_fragment(acc[g][i][j], 0.0f);

    load_tile(0, 0); cp_commit();
    if (KT > 1) { load_tile(1, 1); cp_commit(); }

    for (int kt = 0; kt < KT; kt++) {
        if (kt == KT - 1) cp_wait<0>(); else cp_wait<1>();
        __syncthreads();
        const int s = kt & 1;
#pragma unroll
        for (int kc = 0; kc < 64; kc += 16) {
            wmma::fragment<wmma::matrix_a, 16, 16, 16, __half, wmma::row_major> ah[MI];
#pragma unroll
            for (int i = 0; i < MI; i++)
                wmma::load_matrix_sync(ah[i], sAh[s] + (wm * 16 * MI + i * 16) * STR + kc, STR);
#pragma unroll
            for (int g = 0; g < NSEG; g++) {
                wmma::fragment<wmma::matrix_b, 16, 16, 16, __half, wmma::col_major> b[2];
#pragma unroll
                for (int j = 0; j < 2; j++)
                    wmma::load_matrix_sync(b[j], sB[s] + (g * 64 + wn * 32 + j * 16) * STR + kc, STR);
#pragma unroll
                for (int i = 0; i < MI; i++)
#pragma unroll
                    for (int j = 0; j < 2; j++)
                        wmma::mma_sync(acc[g][i][j], ah[i], b[j], acc[g][i][j]);
            }
        }
        __syncthreads();
        if (kt + 2 < KT) { load_tile(kt & 1, kt + 2); cp_commit(); }
    }

    // ---------------- epilogue ----------------
    float* wbuf = (float*)smem_raw;
    float* sX = wbuf + 8 * NSEG * 320;
    constexpr int XW = (MODE == 1) ? 4 : 8;
    float* sW = sX + BM * XW;

    if (MODE != 2) {
#pragma unroll
        for (int r = 0; r < (BM * XW + 255) / 256; r++) {
            int c = tid + r * 256;
            if (c < BM * XW) sX[c] = xw[(size_t)(m0 + (c / XW)) * XW + (c % XW)];
        }
#pragma unroll
        for (int r = 0; r < 6; r++) {
            int c = tid + r * 256;
            int srow = c >> 3, k = c & 7;
            sW[c] = swg[(size_t)((srow >> 6) * 256 + n0 + (srow & 63)) * 8 + k];
        }
    }
    __syncthreads();

    float* wb = wbuf + wid * NSEG * 320;
    const int r_ = lane >> 1;
    const int c0_ = (lane & 1) * 8;

#pragma unroll
    for (int i = 0; i < MI; i++) {
#pragma unroll
        for (int j = 0; j < 2; j++) {
#pragma unroll
            for (int g = 0; g < NSEG; g++)
                wmma::store_matrix_sync(wb + g * 320, acc[g][i][j], 20, wmma::mem_row_major);
            __syncwarp();

            const int mloc = wm * 16 * MI + i * 16 + r_;
            const int m = m0 + mloc;
            const int nl0 = wn * 32 + j * 16 + c0_;
            const int nabs = n0 + nl0;

            __half oh8[8], ol8[8];

            if (MODE == 2) {
                float4 b0 = *(const float4*)&xw[nabs];
                float4 b1 = *(const float4*)&xw[nabs + 4];
                float bia[8] = {b0.x,b0.y,b0.z,b0.w,b1.x,b1.y,b1.z,b1.w};
                float ov[8];
#pragma unroll
                for (int cc = 0; cc < 8; cc++) {
                    float v = eluf_(wb[r_ * 20 + c0_ + cc] + bia[cc]);
                    ov[cc] = v;
                    oh8[cc] = __float2half_rn(v);
                }
                if (Ofp) {
                    *(float4*)&Ofp[(size_t)m * 256 + nabs] = make_float4(ov[0],ov[1],ov[2],ov[3]);
                    *(float4*)&Ofp[(size_t)m * 256 + nabs + 4] = make_float4(ov[4],ov[5],ov[6],ov[7]);
                }
                if (Ohi) {
                    *(uint4*)&Ohi[(size_t)m * ldo + nabs] = *(uint4*)oh8;
                    if (Olo) {
#pragma unroll
                        for (int cc = 0; cc < 8; cc++)
                            ol8[cc] = __float2half_rn(ov[cc] - __half2float(oh8[cc]));
                        *(uint4*)&Olo[(size_t)m * ldo + nabs] = *(uint4*)ol8;
                    }
                }
            } else {
                uint4 hv4 = *(const uint4*)&oldHi[(size_t)m * oldLd + nabs];
                uint4 lv4 = *(const uint4*)&oldLo[(size_t)m * oldLd + nabs];
                const __half* hvp = (const __half*)&hv4;
                const __half* lvp = (const __half*)&lv4;
                float xr[XW];
#pragma unroll
                for (int k = 0; k < XW; k++) xr[k] = sX[mloc * XW + k];
#pragma unroll
                for (int cc = 0; cc < 8; cc++) {
                    int nl = nl0 + cc;
                    const float* w0 = sW + (0 * 64 + nl) * 8;
                    const float* w1 = sW + (1 * 64 + nl) * 8;
                    const float* w2 = sW + (2 * 64 + nl) * 8;
                    float a0 = wb[0 * 320 + r_ * 20 + c0_ + cc];
                    float a1 = wb[1 * 320 + r_ * 20 + c0_ + cc];
                    float a2 = wb[2 * 320 + r_ * 20 + c0_ + cc];
                    float gi_r, gi_z, gi_n, rr, zz, nn;
                    if (MODE == 0) {
                        gi_r = w0[5]; gi_z = w1[5]; gi_n = w2[5];
#pragma unroll
                        for (int k = 0; k < 5; k++) {
                            gi_r += xr[k] * w0[k];
                            gi_z += xr[k] * w1[k];
                            gi_n += xr[k] * w2[k];
                        }
                        rr = fsig(gi_r + a0 + w0[6]);
                        zz = fsig(gi_z + a1 + w1[6]);
                        nn = ftanh_(gi_n + rr * (a2 + w2[6]));
                    } else {
                        float a3 = wb[3 * 320 + r_ * 20 + c0_ + cc];
                        gi_r = w0[3]; gi_z = w1[3]; gi_n = w2[3];
#pragma unroll
                        for (int k = 0; k < 3; k++) {
                            gi_r += xr[k] * w0[k];
                            gi_z += xr[k] * w1[k];
                            gi_n += xr[k] * w2[k];
                        }
                        rr = fsig(gi_r + a0 + w0[4]);
                        zz = fsig(gi_z + a1 + w1[4]);
                        nn = ftanh_(gi_n + a2 + rr * (a3 + w2[4]));
                    }
                    float hold = __half2float(hvp[cc]) + __half2float(lvp[cc]);
                    float hnew = (1.0f - zz) * nn + zz * hold;
                    split_fp16(hnew, oh8[cc], ol8[cc]);
                }
                *(uint4*)&Ohi[(size_t)m * ldo + nabs] = *(uint4*)oh8;
                *(uint4*)&Olo[(size_t)m * ldo + nabs] = *(uint4*)ol8;
            }
            __syncwarp();
        }
    }
}

// ---------------- entity max-pool (hi planes only) ----------------
__global__ void pool_kernel(const __half* __restrict__ phi,
                            __half* __restrict__ xcat_hi)
{
    int idx = blockIdx.x * blockDim.x + threadIdx.x;
    if (idx >= MA_ROWS * 32) return;
    int m = idx >> 5, c8 = (idx & 31) * 8;
    float v[8];
#pragma unroll
    for (int k = 0; k < 8; k++) v[k] = -1e30f;
#pragma unroll
    for (int e = 0; e < EE; e++) {
        size_t off = (size_t)(m * EE + e) * HH + c8;
        uint4 h4 = *(const uint4*)&phi[off];
        const __half* hp = (const __half*)&h4;
#pragma unroll
        for (int k = 0; k < 8; k++)
            v[k] = fmaxf(v[k], __half2float(hp[k]));
    }
    __half h8[8];
#pragma unroll
    for (int k = 0; k < 8; k++) h8[k] = __float2half_rn(v[k]);
    *(uint4*)&xcat_hi[(size_t)m * 512 + c8] = *(uint4*)h8;
}

// ---------------- head ----------------
__global__ void head_kernel(const float* __restrict__ t2,
                            const float* __restrict__ Wm2, const float* __restrict__ bm2,
                            float* __restrict__ out, int tstep)
{
    int warp = (blockIdx.x * blockDim.x + threadIdx.x) >> 5;
    int lane = threadIdx.x & 31;
    if (warp >= MA_ROWS) return;
    float s0 = 0.0f, s1 = 0.0f;
    for (int k = lane; k < HH; k += 32) {
        float x = t2[warp * HH + k];
        s0 += x * Wm2[k];
        s1 += x * Wm2[HH + k];
    }
#pragma unroll
    for (int off = 16; off; off >>= 1) {
        s0 += __shfl_xor_sync(0xffffffffu, s0, off);
        s1 += __shfl_xor_sync(0xffffffffu, s1, off);
    }
    if (lane == 0) {
        out[((size_t)tstep * MA_ROWS + warp) * 2 + 0] = ftanh_(s0 + bm2[0]) * 0.05f;
        out[((size_t)tstep * MA_ROWS + warp) * 2 + 1] = ftanh_(s1 + bm2[1]) * 0.05f;
    }
}

// ---------------- host launcher ----------------
extern "C" void kernel_launch(void* const* d_in, const int* in_sizes, int n_in,
                              void* d_out, int out_size)
{
    const float* obs    = (const float*)d_in[0];
    const float* phys   = (const float*)d_in[1];
    const float* goals  = (const float*)d_in[2];
    const float* mem_p  = (const float*)d_in[3];
    const float* mem_a  = (const float*)d_in[4];
    const float* Wih_p  = (const float*)d_in[5];
    const float* Whh_p  = (const float*)d_in[6];
    const float* bih_p  = (const float*)d_in[7];
    const float* bhh_p  = (const float*)d_in[8];
    const float* Wfc_p  = (const float*)d_in[9];
    const float* bfc_p  = (const float*)d_in[10];
    const float* Wih_a  = (const float*)d_in[11];
    const float* Whh_a  = (const float*)d_in[12];
    const float* bih_a  = (const float*)d_in[13];
    const float* bhh_a  = (const float*)d_in[14];
    const float* Wfc_a  = (const float*)d_in[15];
    const float* bfc_a  = (const float*)d_in[16];
    const float* Wm1    = (const float*)d_in[17];
    const float* bm1    = (const float*)d_in[18];
    const float* Wm2    = (const float*)d_in[19];
    const float* bm2    = (const float*)d_in[20];
    float* out = (float*)d_out;

    void* p;
    __half *h_hi[2], *h_lo[2], *xc_hi[2], *xc_lo[2];
    cudaGetSymbolAddress(&p, g_h_hi);    h_hi[0] = (__half*)p; h_hi[1] = h_hi[0] + (size_t)MP_ROWS*HH;
    cudaGetSymbolAddress(&p, g_h_lo);    h_lo[0] = (__half*)p; h_lo[1] = h_lo[0] + (size_t)MP_ROWS*HH;
    cudaGetSymbolAddress(&p, g_xcat_hi); xc_hi[0] = (__half*)p; xc_hi[1] = xc_hi[0] + (size_t)MA_ROWS*512;
    cudaGetSymbolAddress(&p, g_xcat_lo); xc_lo[0] = (__half*)p; xc_lo[1] = xc_lo[0] + (size_t)MA_ROWS*512;
    cudaGetSymbolAddress(&p, g_proc_hi); __half* proc_hi = (__half*)p;
    cudaGetSymbolAddress(&p, g_t1_hi);   __half* t1_hi = (__half*)p;
    cudaGetSymbolAddress(&p, g_t2);      float* t2 = (float*)p;
    cudaGetSymbolAddress(&p, g_xp8);     float* xp8 = (float*)p;
    cudaGetSymbolAddress(&p, g_xa4);     float* xa4 = (float*)p;
    cudaGetSymbolAddress(&p, g_Wp8);     float* Wp8 = (float*)p;
    cudaGetSymbolAddress(&p, g_Wa8);     float* Wa8 = (float*)p;
    cudaGetSymbolAddress(&p, g_Whhp);    __half* Whhp = (__half*)p;
    cudaGetSymbolAddress(&p, g_Wfcp);    __half* Wfcp = (__half*)p;
    cudaGetSymbolAddress(&p, g_Wcat);    __half* Wcat = (__half*)p;
    cudaGetSymbolAddress(&p, g_Wfca);    __half* Wfca = (__half*)p;
    cudaGetSymbolAddress(&p, g_Wm1);     __half* Wm1h = (__half*)p;

    const int SM_0_128 = (2*128*72 + 2*3*64*72) * 2;   // 92160
    const int SM_1_64  = (2*64*72  + 2*4*64*72) * 2;   // 92160
    const int SM_2_128 = (2*128*72 + 2*1*64*72) * 2;   // 55296
    const int SM_2_64  = (2*64*72  + 2*1*64*72) * 2;   // 36864
    cudaFuncSetAttribute((const void*)fused_kernel<0,128>, cudaFuncAttributeMaxDynamicSharedMemorySize, SM_0_128);
    cudaFuncSetAttribute((const void*)fused_kernel<1,64>,  cudaFuncAttributeMaxDynamicSharedMemorySize, SM_1_64);
    cudaFuncSetAttribute((const void*)fused_kernel<2,128>, cudaFuncAttributeMaxDynamicSharedMemorySize, SM_2_128);
    cudaFuncSetAttribute((const void*)fused_kernel<2,64>,  cudaFuncAttributeMaxDynamicSharedMemorySize, SM_2_64);

    // ---- one-time stream/event setup ----
    static cudaStream_t sA = nullptr, sB = nullptr;
    static cudaEvent_t evFork = nullptr, evJoinA = nullptr, evJoinB = nullptr;
    static cudaEvent_t evG[TT], evF[TT], evP[TT], evA[TT];
    if (sA == nullptr) {
        cudaStreamCreateWithFlags(&sA, cudaStreamNonBlocking);
        cudaStreamCreateWithFlags(&sB, cudaStreamNonBlocking);
        cudaEventCreateWithFlags(&evFork, cudaEventDisableTiming);
        cudaEventCreateWithFlags(&evJoinA, cudaEventDisableTiming);
        cudaEventCreateWithFlags(&evJoinB, cudaEventDisableTiming);
        for (int i = 0; i < TT; i++) {
            cudaEventCreateWithFlags(&evG[i], cudaEventDisableTiming);
            cudaEventCreateWithFlags(&evF[i], cudaEventDisableTiming);
            cudaEventCreateWithFlags(&evP[i], cudaEventDisableTiming);
            cudaEventCreateWithFlags(&evA[i], cudaEventDisableTiming);
        }
    }

    cudaStream_t s0 = 0;

    // ---- fork sB immediately so its prep work is rooted in the capture ----
    cudaEventRecord(evFork, s0);
    cudaStreamWaitEvent(sB, evFork, 0);

    // ---- gru_p-critical prep on s0 ----
    split_kernel<<<(MP_ROWS*HH + 255)/256, 256, 0, s0>>>(mem_p, h_hi[0], h_lo[0], MP_ROWS*HH);
    conv_kernel<<<(G3H*HH + 255)/256, 256, 0, s0>>>(Whh_p, Whhp, G3H*HH);
    prep_xp_kernel<<<(MP_ROWS + 255)/256, 256, 0, s0>>>(obs, phys, xp8);
    prep_wp8_kernel<<<(G3H + 255)/256, 256, 0, s0>>>(Wih_p, bih_p, bhh_p, Wp8);

    // ---- everything else on sB (hides under gru_p(0)) ----
    split_strided_kernel<<<(MA_ROWS*HH + 255)/256, 256, 0, sB>>>(mem_a, xc_hi[0] + 256, xc_lo[0] + 256, MA_ROWS, HH, 512);
    conv_kernel<<<(HH*HH + 255)/256, 256, 0, sB>>>(Wfc_p, Wfcp, HH*HH);
    conv_kernel<<<(HH*HH + 255)/256, 256, 0, sB>>>(Wfc_a, Wfca, HH*HH);
    conv_kernel<<<(HH*HH + 255)/256, 256, 0, sB>>>(Wm1, Wm1h, HH*HH);
    build_wcat_kernel<<<(1024*512 + 255)/256, 256, 0, sB>>>(Wih_a, Whh_a, Wcat);
    prep_xa_kernel<<<(MA_ROWS + 255)/256, 256, 0, sB>>>(goals, xa4);
    prep_wa8_kernel<<<(G3H + 255)/256, 256, 0, sB>>>(Wih_a, bih_a, bhh_a, Wa8);

    // ---- recurrence ----
    // s0 : gru_p chain (critical path). sB : fc_p + pool. sA : action chain.
    int cur = 0;
    for (int t = 0; t < TT; t++) {
        int nxt = cur ^ 1;
        // ---- physical GRU on s0 ----
        if (t >= 2) cudaStreamWaitEvent(s0, evF[t - 2], 0);
        fused_kernel<0,128><<<dim3(MP_ROWS/128, 4), 256, SM_0_128, s0>>>(
            h_hi[cur], HH, Whhp, xp8, Wp8,
            h_hi[cur], h_lo[cur], HH,
            h_hi[nxt], h_lo[nxt], HH, nullptr);
        cudaEventRecord(evG[t], s0);

        // ---- fc_p + pool on sB ----
        cudaStreamWaitEvent(sB, evG[t], 0);
        fused_kernel<2,128><<<dim3(MP_ROWS/128, 4), 256, SM_2_128, sB>>>(
            h_hi[nxt], HH, Wfcp, bfc_p, nullptr,
            nullptr, nullptr, 0,
            proc_hi, nullptr, HH, nullptr);
        cudaEventRecord(evF[t], sB);
        if (t >= 2) cudaStreamWaitEvent(sB, evA[t - 2], 0);
        pool_kernel<<<(MA_ROWS*32 + 255)/256, 256, 0, sB>>>(proc_hi, xc_hi[cur]);
        cudaEventRecord(evP[t], sB);

        // ---- action chain on sA ----
        cudaStreamWaitEvent(sA, evP[t], 0);
        fused_kernel<1,64><<<dim3(MA_ROWS/64, 4), 256, SM_1_64, sA>>>(
            xc_hi[cur], 512, Wcat, xa4, Wa8,
            xc_hi[cur] + 256, xc_lo[cur] + 256, 512,
            xc_hi[nxt] + 256, xc_lo[nxt] + 256, 512, nullptr);
        cudaEventRecord(evA[t], sA);
        fused_kernel<2,64><<<dim3(MA_ROWS/64, 4), 256, SM_2_64, sA>>>(
            xc_hi[nxt] + 256, 512, Wfca, bfc_a, nullptr,
            nullptr, nullptr, 0,
            t1_hi, nullptr, HH, nullptr);
        fused_kernel<2,64><<<dim3(MA_ROWS/64, 4), 256, SM_2_64, sA>>>(
            t1_hi, HH, Wm1h, bm1, nullptr,
            nullptr, nullptr, 0,
            nullptr, nullptr, 0, t2);
        head_kernel<<<(MA_ROWS*32 + 255)/256, 256, 0, sA>>>(t2, Wm2, bm2, out, t);
        cur = nxt;
    }

    // join side streams back into stream 0
    cudaEventRecord(evJoinA, sA);
    cudaStreamWaitEvent(s0, evJoinA, 0);
    cudaEventRecord(evJoinB, sB);
    cudaStreamWaitEvent(s0, evJoinB, 0);
}